// round 2
// baseline (speedup 1.0000x reference)
#include <cuda_runtime.h>
#include <math.h>

#define S_LEN 2048
#define BATCH 2
#define HID   4096
#define NH    32
#define NKV   8
#define HD    128
#define WIN   1024
#define QDIM  (NH*HD)     // 4096
#define KVDIM (NKV*HD)    // 1024
#define MROWS (BATCH*S_LEN) // 4096

// Scratch buffers (device globals per harness allocation rules)
__device__ float g_Q[(size_t)MROWS*QDIM];
__device__ float g_K[(size_t)MROWS*KVDIM];
__device__ float g_V[(size_t)MROWS*KVDIM];
__device__ float g_AO[(size_t)MROWS*QDIM];

typedef unsigned long long ull;

__device__ __forceinline__ ull pk(float x, float y) {
    ull r; asm("mov.b64 %0,{%1,%2};" : "=l"(r) : "f"(x), "f"(y)); return r;
}
__device__ __forceinline__ float2 up(ull v) {
    float2 r; asm("mov.b64 {%0,%1},%2;" : "=f"(r.x), "=f"(r.y) : "l"(v)); return r;
}
__device__ __forceinline__ void fma2(ull &acc, ull a, ull b) {
    asm("fma.rn.f32x2 %0,%1,%2,%0;" : "+l"(acc) : "l"(a), "l"(b));
}
__device__ __forceinline__ ull mul2(ull a, ull b) {
    ull r; asm("mul.rn.f32x2 %0,%1,%2;" : "=l"(r) : "l"(a), "l"(b)); return r;
}

// ---------------------------------------------------------------------------
// NT SGEMM: C[m][n] = sum_k A[m*K+k] * B[n*K+k]
// 128x128 tile, BK=16, 256 threads, 8x8 microtile, packed f32x2 FMA.
// M,N multiples of 128; K multiple of 16.
// ---------------------------------------------------------------------------
__global__ void __launch_bounds__(256) sgemm_nt(
    const float* __restrict__ A, const float* __restrict__ B,
    float* __restrict__ C, int M, int N, int K)
{
    __shared__ __align__(16) float As[16][132];
    __shared__ __align__(16) float Bs[16][132];

    const int tid = threadIdx.x;
    const int tm  = tid >> 4;        // 0..15
    const int tn  = tid & 15;        // 0..15
    const int m0  = blockIdx.y * 128;
    const int n0  = blockIdx.x * 128;
    const int lr  = tid >> 2;        // 0..63
    const int lc  = (tid & 3) << 2;  // 0,4,8,12

    ull acc[8][4];
    #pragma unroll
    for (int i = 0; i < 8; ++i)
        #pragma unroll
        for (int j = 0; j < 4; ++j) acc[i][j] = 0ULL;

    for (int kt = 0; kt < K; kt += 16) {
        #pragma unroll
        for (int h = 0; h < 2; ++h) {
            int row = lr + h * 64;
            float4 a4 = *(const float4*)&A[(size_t)(m0 + row) * K + kt + lc];
            As[lc+0][row] = a4.x; As[lc+1][row] = a4.y;
            As[lc+2][row] = a4.z; As[lc+3][row] = a4.w;
            float4 b4 = *(const float4*)&B[(size_t)(n0 + row) * K + kt + lc];
            Bs[lc+0][row] = b4.x; Bs[lc+1][row] = b4.y;
            Bs[lc+2][row] = b4.z; Bs[lc+3][row] = b4.w;
        }
        __syncthreads();

        #pragma unroll
        for (int kk = 0; kk < 16; ++kk) {
            float4 a0 = *(const float4*)&As[kk][tm*8];
            float4 a1 = *(const float4*)&As[kk][tm*8+4];
            ulonglong2 b0 = *(const ulonglong2*)&Bs[kk][tn*8];
            ulonglong2 b1 = *(const ulonglong2*)&Bs[kk][tn*8+4];
            float av[8] = {a0.x,a0.y,a0.z,a0.w,a1.x,a1.y,a1.z,a1.w};
            #pragma unroll
            for (int i = 0; i < 8; ++i) {
                ull ap = pk(av[i], av[i]);
                fma2(acc[i][0], ap, b0.x);
                fma2(acc[i][1], ap, b0.y);
                fma2(acc[i][2], ap, b1.x);
                fma2(acc[i][3], ap, b1.y);
            }
        }
        __syncthreads();
    }

    #pragma unroll
    for (int i = 0; i < 8; ++i) {
        size_t row = (size_t)(m0 + tm*8 + i) * N + n0 + tn*8;
        *(float2*)&C[row + 0] = up(acc[i][0]);
        *(float2*)&C[row + 2] = up(acc[i][1]);
        *(float2*)&C[row + 4] = up(acc[i][2]);
        *(float2*)&C[row + 6] = up(acc[i][3]);
    }
}

// ---------------------------------------------------------------------------
// RoPE: buf layout [MROWS][nheads*128]. One thread per (row, head, pair i).
// ---------------------------------------------------------------------------
__global__ void rope_kernel(float* __restrict__ buf, int nheads)
{
    int idx = blockIdx.x * blockDim.x + threadIdx.x;
    int i   = idx & 63;
    int t   = idx >> 6;
    int h   = t % nheads;
    int row = t / nheads;          // b*S + s
    int s   = row & (S_LEN - 1);

    float inv = powf(10000.0f, -(float)i * (1.0f / 64.0f));
    float ang = (float)s * inv;
    float sn, cs;
    sincosf(ang, &sn, &cs);

    float* p = buf + (size_t)row * (nheads * HD) + h * HD;
    float x1 = p[i], x2 = p[i + 64];
    p[i]      = x1 * cs - x2 * sn;
    p[i + 64] = x2 * cs + x1 * sn;
}

// ---------------------------------------------------------------------------
// Flash attention with sliding window (causal, W=1024), GQA (4 q-heads per kv).
// Block: (q-tile of 64, head, batch). 256 threads, 4x4 score microtile,
// online softmax, 4x8 output microtile. f32x2 packed FMA throughout.
// ---------------------------------------------------------------------------
__global__ void __launch_bounds__(256) attn_kernel(
    const float* __restrict__ Qg, const float* __restrict__ Kg,
    const float* __restrict__ Vg, float* __restrict__ Og)
{
    extern __shared__ float smx[];
    float* Qs = smx;                 // [64][128]
    float* Ks = smx + 64*128;        // [128][66] transposed (d-major)
    float* Vs = Ks + 128*66;         // [64][128]
    float* Ps = Vs + 64*128;         // [64][64]

    const int tid = threadIdx.x;
    const int tm  = tid >> 4;        // 0..15 -> 4 query rows
    const int tn  = tid & 15;        // 0..15
    const int qb  = blockIdx.x;
    const int h   = blockIdx.y;
    const int b   = blockIdx.z;
    const int q0  = qb * 64;
    const int kvh = h >> 2;
    const float SC = 0.08838834764831845f;  // 1/sqrt(128)

    // Load Q tile
    #pragma unroll
    for (int it = 0; it < 8; ++it) {
        int idx = tid + it * 256;
        int r = idx >> 5;
        int d = (idx & 31) << 2;
        *(float4*)&Qs[r*128 + d] =
            *(const float4*)&Qg[(size_t)(b*S_LEN + q0 + r)*QDIM + h*HD + d];
    }

    ull o2[4][4];
    #pragma unroll
    for (int r = 0; r < 4; ++r)
        #pragma unroll
        for (int j = 0; j < 4; ++j) o2[r][j] = 0ULL;
    float mrow[4] = {-1e30f, -1e30f, -1e30f, -1e30f};
    float lrow[4] = {0.f, 0.f, 0.f, 0.f};

    const int lo  = (q0 > (WIN - 1)) ? (q0 - (WIN - 1)) : 0;
    const int kt0 = lo >> 6;

    for (int kt = kt0; kt <= qb; ++kt) {
        const int kbase = kt << 6;

        // Load K (transposed) and V tiles
        #pragma unroll
        for (int it = 0; it < 8; ++it) {
            int idx = tid + it * 256;
            int r = idx >> 5;
            int d = (idx & 31) << 2;
            size_t goff = (size_t)(b*S_LEN + kbase + r)*KVDIM + kvh*HD + d;
            float4 kv = *(const float4*)&Kg[goff];
            Ks[(d+0)*66 + r] = kv.x;
            Ks[(d+1)*66 + r] = kv.y;
            Ks[(d+2)*66 + r] = kv.z;
            Ks[(d+3)*66 + r] = kv.w;
            *(float4*)&Vs[r*128 + d] = *(const float4*)&Vg[goff];
        }
        __syncthreads();

        // S = Q K^T  (4 rows x 4 cols per thread, f32x2 along key dim)
        ull s2[4][2];
        #pragma unroll
        for (int r = 0; r < 4; ++r) { s2[r][0] = 0ULL; s2[r][1] = 0ULL; }

        #pragma unroll 4
        for (int d = 0; d < 128; d += 2) {
            float2 qr0 = *(const float2*)&Qs[(tm*4+0)*128 + d];
            float2 qr1 = *(const float2*)&Qs[(tm*4+1)*128 + d];
            float2 qr2 = *(const float2*)&Qs[(tm*4+2)*128 + d];
            float2 qr3 = *(const float2*)&Qs[(tm*4+3)*128 + d];
            ull k00 = *(const ull*)&Ks[d*66 + tn*4];
            ull k01 = *(const ull*)&Ks[d*66 + tn*4 + 2];
            ull k10 = *(const ull*)&Ks[(d+1)*66 + tn*4];
            ull k11 = *(const ull*)&Ks[(d+1)*66 + tn*4 + 2];
            fma2(s2[0][0], pk(qr0.x,qr0.x), k00); fma2(s2[0][1], pk(qr0.x,qr0.x), k01);
            fma2(s2[0][0], pk(qr0.y,qr0.y), k10); fma2(s2[0][1], pk(qr0.y,qr0.y), k11);
            fma2(s2[1][0], pk(qr1.x,qr1.x), k00); fma2(s2[1][1], pk(qr1.x,qr1.x), k01);
            fma2(s2[1][0], pk(qr1.y,qr1.y), k10); fma2(s2[1][1], pk(qr1.y,qr1.y), k11);
            fma2(s2[2][0], pk(qr2.x,qr2.x), k00); fma2(s2[2][1], pk(qr2.x,qr2.x), k01);
            fma2(s2[2][0], pk(qr2.y,qr2.y), k10); fma2(s2[2][1], pk(qr2.y,qr2.y), k11);
            fma2(s2[3][0], pk(qr3.x,qr3.x), k00); fma2(s2[3][1], pk(qr3.x,qr3.x), k01);
            fma2(s2[3][0], pk(qr3.y,qr3.y), k10); fma2(s2[3][1], pk(qr3.y,qr3.y), k11);
        }

        // Unpack, scale, mask, online softmax
        float sv[4][4];
        #pragma unroll
        for (int r = 0; r < 4; ++r) {
            float2 t0 = up(s2[r][0]);
            float2 t1 = up(s2[r][1]);
            sv[r][0] = t0.x * SC; sv[r][1] = t0.y * SC;
            sv[r][2] = t1.x * SC; sv[r][3] = t1.y * SC;
        }

        #pragma unroll
        for (int r = 0; r < 4; ++r) {
            const int qi = q0 + tm*4 + r;
            bool ok[4];
            float rm = -1e30f;
            #pragma unroll
            for (int c = 0; c < 4; ++c) {
                int kj = kbase + tn*4 + c;
                ok[c] = (kj <= qi) && ((qi - kj) < WIN);
                if (!ok[c]) sv[r][c] = -1e30f;
                rm = fmaxf(rm, sv[r][c]);
            }
            rm = fmaxf(rm, __shfl_xor_sync(0xffffffffu, rm, 1));
            rm = fmaxf(rm, __shfl_xor_sync(0xffffffffu, rm, 2));
            rm = fmaxf(rm, __shfl_xor_sync(0xffffffffu, rm, 4));
            rm = fmaxf(rm, __shfl_xor_sync(0xffffffffu, rm, 8));
            float mn = fmaxf(mrow[r], rm);

            float p[4], rs = 0.f;
            #pragma unroll
            for (int c = 0; c < 4; ++c) {
                p[c] = ok[c] ? __expf(sv[r][c] - mn) : 0.f;
                rs += p[c];
            }
            rs += __shfl_xor_sync(0xffffffffu, rs, 1);
            rs += __shfl_xor_sync(0xffffffffu, rs, 2);
            rs += __shfl_xor_sync(0xffffffffu, rs, 4);
            rs += __shfl_xor_sync(0xffffffffu, rs, 8);

            float scl = __expf(mrow[r] - mn);
            lrow[r] = lrow[r] * scl + rs;
            mrow[r] = mn;

            ull sp = pk(scl, scl);
            #pragma unroll
            for (int j = 0; j < 4; ++j) o2[r][j] = mul2(o2[r][j], sp);

            #pragma unroll
            for (int c = 0; c < 4; ++c)
                Ps[(tm*4+r)*64 + tn*4 + c] = p[c];
        }
        __syncthreads();

        // O += P @ V   (4 rows x 8 cols per thread)
        #pragma unroll 4
        for (int k = 0; k < 64; ++k) {
            ulonglong2 v0 = *(const ulonglong2*)&Vs[k*128 + tn*8];
            ulonglong2 v1 = *(const ulonglong2*)&Vs[k*128 + tn*8 + 4];
            #pragma unroll
            for (int r = 0; r < 4; ++r) {
                float pv = Ps[(tm*4+r)*64 + k];
                ull pp = pk(pv, pv);
                fma2(o2[r][0], pp, v0.x);
                fma2(o2[r][1], pp, v0.y);
                fma2(o2[r][2], pp, v1.x);
                fma2(o2[r][3], pp, v1.y);
            }
        }
        __syncthreads();
    }

    // Epilogue: O /= l, write out
    #pragma unroll
    for (int r = 0; r < 4; ++r) {
        float inv = 1.0f / lrow[r];
        ull ip = pk(inv, inv);
        float* orow = &Og[(size_t)(b*S_LEN + q0 + tm*4 + r)*QDIM + h*HD + tn*8];
        *(float2*)&orow[0] = up(mul2(o2[r][0], ip));
        *(float2*)&orow[2] = up(mul2(o2[r][1], ip));
        *(float2*)&orow[4] = up(mul2(o2[r][2], ip));
        *(float2*)&orow[6] = up(mul2(o2[r][3], ip));
    }
}

// ---------------------------------------------------------------------------
extern "C" void kernel_launch(void* const* d_in, const int* in_sizes, int n_in,
                              void* d_out, int out_size)
{
    const float* X  = (const float*)d_in[0];
    const float* Wq = (const float*)d_in[1];
    const float* Wk = (const float*)d_in[2];
    const float* Wv = (const float*)d_in[3];
    const float* Wo = (const float*)d_in[4];
    float* out = (float*)d_out;

    float *q, *k, *v, *ao;
    cudaGetSymbolAddress((void**)&q,  g_Q);
    cudaGetSymbolAddress((void**)&k,  g_K);
    cudaGetSymbolAddress((void**)&v,  g_V);
    cudaGetSymbolAddress((void**)&ao, g_AO);

    // Projections: x @ W^T  (NT gemms)
    sgemm_nt<<<dim3(QDIM/128,  MROWS/128), 256>>>(X, Wq, q, MROWS, QDIM,  HID);
    sgemm_nt<<<dim3(KVDIM/128, MROWS/128), 256>>>(X, Wk, k, MROWS, KVDIM, HID);
    sgemm_nt<<<dim3(KVDIM/128, MROWS/128), 256>>>(X, Wv, v, MROWS, KVDIM, HID);

    // RoPE on Q and K
    rope_kernel<<<(MROWS*NH*64)/256,  256>>>(q, NH);
    rope_kernel<<<(MROWS*NKV*64)/256, 256>>>(k, NKV);

    // Sliding-window flash attention
    const int smem_bytes = (64*128 + 128*66 + 64*128 + 64*64) * 4;  // 115712
    cudaFuncSetAttribute(attn_kernel,
                         cudaFuncAttributeMaxDynamicSharedMemorySize, smem_bytes);
    attn_kernel<<<dim3(S_LEN/64, NH, BATCH), 256, smem_bytes>>>(q, k, v, ao);

    // Output projection
    sgemm_nt<<<dim3(QDIM/128, MROWS/128), 256>>>(ao, Wo, out, MROWS, QDIM, HID);
}

// round 4
// speedup vs baseline: 1.7765x; 1.7765x over previous
#include <cuda_runtime.h>
#include <cuda_bf16.h>
#include <math.h>
#include <stdint.h>

#define S_LEN 2048
#define HID   4096
#define NH    32
#define NKV   8
#define HD    128
#define WIN   1024
#define QDIM  4096
#define KVLD  2048
#define MROWS 4096

typedef unsigned long long ull;
typedef __nv_bfloat16 bf16;

// fp32 intermediates
__device__ float g_Q  [(size_t)MROWS*QDIM];
__device__ float g_KV [(size_t)MROWS*KVLD];
__device__ float g_AO [(size_t)MROWS*QDIM];
// bf16 split operands
__device__ bf16 g_xh [(size_t)MROWS*HID],  g_xl [(size_t)MROWS*HID];
__device__ bf16 g_wqh[(size_t)QDIM*HID],   g_wql[(size_t)QDIM*HID];
__device__ bf16 g_wkh[(size_t)KVLD*HID],   g_wkl[(size_t)KVLD*HID];
__device__ bf16 g_woh[(size_t)HID*QDIM],   g_wol[(size_t)HID*QDIM];
__device__ bf16 g_aoh[(size_t)MROWS*QDIM], g_aol[(size_t)MROWS*QDIM];

// ---------------- PTX helpers (baseline ISA only) ----------------
__device__ __forceinline__ uint32_t s2u(const void* p){
    uint32_t a;
    asm("{ .reg .u64 t; cvta.to.shared.u64 t,%1; cvt.u32.u64 %0,t; }":"=r"(a):"l"(p));
    return a;
}
#define CPA(dst,src) asm volatile( \
    "cp.async.cg.shared.global [%0],[%1],16;" :: "r"(dst),"l"(src) : "memory")
#define CPA_COMMIT() asm volatile("cp.async.commit_group;" ::: "memory")
#define CPA_WAIT2()  asm volatile("cp.async.wait_group 2;" ::: "memory")

#define LDSM4(r,addr) asm volatile( \
    "ldmatrix.sync.aligned.m8n8.x4.shared.b16 {%0,%1,%2,%3},[%4];" \
    : "=r"((r)[0]),"=r"((r)[1]),"=r"((r)[2]),"=r"((r)[3]) : "r"(addr))

#define MMA_BF16(c,a,b) asm volatile( \
    "mma.sync.aligned.m16n8k16.row.col.f32.bf16.bf16.f32 " \
    "{%0,%1,%2,%3},{%4,%5,%6,%7},{%8,%9},{%0,%1,%2,%3};" \
    : "+f"((c)[0]),"+f"((c)[1]),"+f"((c)[2]),"+f"((c)[3]) \
    : "r"((a)[0]),"r"((a)[1]),"r"((a)[2]),"r"((a)[3]),"r"((b)[0]),"r"((b)[1]))

// ---------------------------------------------------------------------------
// bf16 split HMMA GEMM: C[M,N] = A[M,K]·B[N,K]^T, K=4096.
// CTA 128x128, BK=32, 4-stage cp.async pipeline, 8 warps (4m x 2n), each 32x64.
// C = Ahi·Bhi + Ahi·Blo + Alo·Bhi  (fp32 accumulate)
// ---------------------------------------------------------------------------
#define GK      4096
#define NCH     128            // GK/32
#define ROWB    80             // padded row bytes (32 bf16 = 64B data + 16B pad)
#define ARR_B   10240          // 128 rows * 80B
#define STG_B   40960          // 4 arrays
#define OFF_AL  10240
#define OFF_BH  20480
#define OFF_BL  30720
#define GSMEM   (4*STG_B)      // 163840

static __device__ __forceinline__ void load_stage(
    uint32_t sb, int stage, int kc, int m0, int n0, int tid,
    const bf16* __restrict__ Ah, const bf16* __restrict__ Al,
    const bf16* __restrict__ Bh, const bf16* __restrict__ Bl)
{
    uint32_t st = sb + stage*STG_B;
    #pragma unroll
    for (int it=0; it<2; ++it){
        int idx = tid + it*256;          // 0..511
        int r = idx>>2, ch = idx&3;
        uint32_t so = (uint32_t)(r*ROWB + ch*16);
        size_t gA = (size_t)(m0+r)*GK + kc + ch*8;
        size_t gB = (size_t)(n0+r)*GK + kc + ch*8;
        CPA(st+so,        Ah+gA);
        CPA(st+OFF_AL+so, Al+gA);
        CPA(st+OFF_BH+so, Bh+gB);
        CPA(st+OFF_BL+so, Bl+gB);
    }
    CPA_COMMIT();
}

__global__ void __launch_bounds__(256) gemm_bf16s(
    const bf16* __restrict__ Ah, const bf16* __restrict__ Al,
    const bf16* __restrict__ Bh, const bf16* __restrict__ Bl,
    float* __restrict__ C, int ldC)
{
    extern __shared__ __align__(128) char sm[];
    const uint32_t sb = s2u(sm);
    const int tid = threadIdx.x, wid = tid>>5, lane = tid&31;
    const int wm = wid&3, wn = wid>>2;
    const int g = lane>>2, tg = lane&3;
    const int m0 = blockIdx.y*128, n0 = blockIdx.x*128;

    float acc[2][8][4];
    #pragma unroll
    for (int i=0;i<2;++i)
        #pragma unroll
        for (int j=0;j<8;++j){acc[i][j][0]=0;acc[i][j][1]=0;acc[i][j][2]=0;acc[i][j][3]=0;}

    load_stage(sb,0,0, m0,n0,tid,Ah,Al,Bh,Bl);
    load_stage(sb,1,32,m0,n0,tid,Ah,Al,Bh,Bl);
    load_stage(sb,2,64,m0,n0,tid,Ah,Al,Bh,Bl);

    // fragment address pieces (constant across chunks)
    const uint32_t a_row = (uint32_t)(wm*32 + (lane&15));          // + mt*16
    const uint32_t a_colb = (uint32_t)((lane>>4)*16);              // bytes: (lane/16)*8 halves
    const uint32_t b_row = (uint32_t)(wn*64 + (lane&7) + ((lane>>4)<<3));  // + p*16
    const uint32_t b_colb = (uint32_t)((((lane>>3)&1)*8)*2);

    for (int c=0; c<NCH; ++c){
        CPA_WAIT2();
        __syncthreads();
        if (c+3 < NCH) load_stage(sb,(c+3)&3,(c+3)*32, m0,n0,tid,Ah,Al,Bh,Bl);
        else CPA_COMMIT();   // keep group count uniform

        const uint32_t st = sb + (c&3)*STG_B;
        #pragma unroll
        for (int s=0; s<2; ++s){
            uint32_t ah[2][4], al[2][4];
            #pragma unroll
            for (int mt=0; mt<2; ++mt){
                uint32_t aa = st + (a_row + mt*16)*ROWB + s*32 + a_colb;
                LDSM4(ah[mt], aa);
                LDSM4(al[mt], aa + OFF_AL);
            }
            uint32_t bh[8][2], bl[8][2];
            #pragma unroll
            for (int p=0; p<4; ++p){
                uint32_t ba = st + OFF_BH + (b_row + p*16)*ROWB + s*32 + b_colb;
                uint32_t r[4];
                LDSM4(r, ba);
                bh[2*p][0]=r[0]; bh[2*p][1]=r[1]; bh[2*p+1][0]=r[2]; bh[2*p+1][1]=r[3];
                LDSM4(r, ba + ARR_B);   // Blo is 10240 after Bhi
                bl[2*p][0]=r[0]; bl[2*p][1]=r[1]; bl[2*p+1][0]=r[2]; bl[2*p+1][1]=r[3];
            }
            #pragma unroll
            for (int mt=0; mt<2; ++mt)
                #pragma unroll
                for (int nt=0; nt<8; ++nt){
                    MMA_BF16(acc[mt][nt], ah[mt], bh[nt]);
                    MMA_BF16(acc[mt][nt], ah[mt], bl[nt]);
                    MMA_BF16(acc[mt][nt], al[mt], bh[nt]);
                }
        }
    }

    #pragma unroll
    for (int mt=0; mt<2; ++mt)
        #pragma unroll
        for (int nt=0; nt<8; ++nt){
            int row = m0 + wm*32 + mt*16 + g;
            int col = n0 + wn*64 + nt*8 + tg*2;
            float2 v0 = {acc[mt][nt][0], acc[mt][nt][1]};
            float2 v1 = {acc[mt][nt][2], acc[mt][nt][3]};
            *(float2*)&C[(size_t)row*ldC + col]     = v0;
            *(float2*)&C[(size_t)(row+8)*ldC + col] = v1;
        }
}

// ---------------- fp32 -> bf16 hi/lo split ----------------
__global__ void split_bf(const float* __restrict__ in,
                         bf16* __restrict__ hi, bf16* __restrict__ lo)
{
    size_t i = ((size_t)blockIdx.x*blockDim.x + threadIdx.x)*4;
    float4 v = *(const float4*)(in+i);
    bf16 hx = __float2bfloat16(v.x), hy = __float2bfloat16(v.y);
    bf16 hz = __float2bfloat16(v.z), hw = __float2bfloat16(v.w);
    hi[i]=hx; hi[i+1]=hy; hi[i+2]=hz; hi[i+3]=hw;
    lo[i]  = __float2bfloat16(v.x - __bfloat162float(hx));
    lo[i+1]= __float2bfloat16(v.y - __bfloat162float(hy));
    lo[i+2]= __float2bfloat16(v.z - __bfloat162float(hz));
    lo[i+3]= __float2bfloat16(v.w - __bfloat162float(hw));
}

// ---------------- RoPE ----------------
__global__ void rope_kernel(float* __restrict__ buf, int nheads, int rstride)
{
    int idx = blockIdx.x*blockDim.x + threadIdx.x;
    int i = idx & 63, t = idx >> 6;
    int h = t % nheads, row = t / nheads;
    int s = row & (S_LEN-1);
    float inv = powf(10000.0f, -(float)i*(1.0f/64.0f));
    float sn, cs; sincosf((float)s*inv, &sn, &cs);
    float* p = buf + (size_t)row*rstride + h*HD;
    float x1 = p[i], x2 = p[i+64];
    p[i]    = x1*cs - x2*sn;
    p[i+64] = x2*cs + x1*sn;
}

// ---------------- flash attention (f32x2, sliding window, GQA) ----------------
__device__ __forceinline__ ull pk(float x,float y){ull r;asm("mov.b64 %0,{%1,%2};":"=l"(r):"f"(x),"f"(y));return r;}
__device__ __forceinline__ float2 up(ull v){float2 r;asm("mov.b64 {%0,%1},%2;":"=f"(r.x),"=f"(r.y):"l"(v));return r;}
__device__ __forceinline__ void fma2(ull&a,ull x,ull y){asm("fma.rn.f32x2 %0,%1,%2,%0;":"+l"(a):"l"(x),"l"(y));}
__device__ __forceinline__ ull mul2(ull x,ull y){ull r;asm("mul.rn.f32x2 %0,%1,%2;":"=l"(r):"l"(x),"l"(y));return r;}

__global__ void __launch_bounds__(256) attn_kernel(
    const float* __restrict__ Qg, const float* __restrict__ Kg,
    const float* __restrict__ Vg, float* __restrict__ Og)
{
    extern __shared__ float smx[];
    float* Qs = smx;
    float* Ks = smx + 64*128;
    float* Vs = Ks + 128*66;
    float* Ps = Vs + 64*128;

    const int tid = threadIdx.x;
    const int tm = tid>>4, tn = tid&15;
    const int qb = blockIdx.x, h = blockIdx.y, b = blockIdx.z;
    const int q0 = qb*64, kvh = h>>2;
    const float SC = 0.08838834764831845f;

    #pragma unroll
    for (int it=0; it<8; ++it){
        int idx = tid + it*256;
        int r = idx>>5, d = (idx&31)<<2;
        *(float4*)&Qs[r*128+d] =
            *(const float4*)&Qg[(size_t)(b*S_LEN+q0+r)*QDIM + h*HD + d];
    }

    ull o2[4][4];
    #pragma unroll
    for (int r=0;r<4;++r){o2[r][0]=0;o2[r][1]=0;o2[r][2]=0;o2[r][3]=0;}
    float mrow[4]={-1e30f,-1e30f,-1e30f,-1e30f};
    float lrow[4]={0.f,0.f,0.f,0.f};

    const int lo = (q0 > WIN-1) ? (q0-(WIN-1)) : 0;
    for (int kt = lo>>6; kt <= qb; ++kt){
        const int kbase = kt<<6;
        #pragma unroll
        for (int it=0; it<8; ++it){
            int idx = tid + it*256;
            int r = idx>>5, d = (idx&31)<<2;
            size_t goff = (size_t)(b*S_LEN+kbase+r)*KVLD + kvh*HD + d;
            float4 kv = *(const float4*)&Kg[goff];
            Ks[(d+0)*66+r]=kv.x; Ks[(d+1)*66+r]=kv.y;
            Ks[(d+2)*66+r]=kv.z; Ks[(d+3)*66+r]=kv.w;
            *(float4*)&Vs[r*128+d] = *(const float4*)&Vg[goff];
        }
        __syncthreads();

        ull s2[4][2];
        #pragma unroll
        for (int r=0;r<4;++r){s2[r][0]=0;s2[r][1]=0;}
        #pragma unroll 4
        for (int d=0; d<128; d+=2){
            float2 q0v=*(const float2*)&Qs[(tm*4+0)*128+d];
            float2 q1v=*(const float2*)&Qs[(tm*4+1)*128+d];
            float2 q2v=*(const float2*)&Qs[(tm*4+2)*128+d];
            float2 q3v=*(const float2*)&Qs[(tm*4+3)*128+d];
            ull k00=*(const ull*)&Ks[d*66+tn*4],     k01=*(const ull*)&Ks[d*66+tn*4+2];
            ull k10=*(const ull*)&Ks[(d+1)*66+tn*4], k11=*(const ull*)&Ks[(d+1)*66+tn*4+2];
            fma2(s2[0][0],pk(q0v.x,q0v.x),k00); fma2(s2[0][1],pk(q0v.x,q0v.x),k01);
            fma2(s2[0][0],pk(q0v.y,q0v.y),k10); fma2(s2[0][1],pk(q0v.y,q0v.y),k11);
            fma2(s2[1][0],pk(q1v.x,q1v.x),k00); fma2(s2[1][1],pk(q1v.x,q1v.x),k01);
            fma2(s2[1][0],pk(q1v.y,q1v.y),k10); fma2(s2[1][1],pk(q1v.y,q1v.y),k11);
            fma2(s2[2][0],pk(q2v.x,q2v.x),k00); fma2(s2[2][1],pk(q2v.x,q2v.x),k01);
            fma2(s2[2][0],pk(q2v.y,q2v.y),k10); fma2(s2[2][1],pk(q2v.y,q2v.y),k11);
            fma2(s2[3][0],pk(q3v.x,q3v.x),k00); fma2(s2[3][1],pk(q3v.x,q3v.x),k01);
            fma2(s2[3][0],pk(q3v.y,q3v.y),k10); fma2(s2[3][1],pk(q3v.y,q3v.y),k11);
        }

        float sv[4][4];
        #pragma unroll
        for (int r=0;r<4;++r){
            float2 t0=up(s2[r][0]), t1=up(s2[r][1]);
            sv[r][0]=t0.x*SC; sv[r][1]=t0.y*SC; sv[r][2]=t1.x*SC; sv[r][3]=t1.y*SC;
        }
        #pragma unroll
        for (int r=0;r<4;++r){
            const int qi = q0 + tm*4 + r;
            bool ok[4]; float rm=-1e30f;
            #pragma unroll
            for (int c=0;c<4;++c){
                int kj = kbase + tn*4 + c;
                ok[c] = (kj<=qi) && ((qi-kj)<WIN);
                if(!ok[c]) sv[r][c]=-1e30f;
                rm = fmaxf(rm, sv[r][c]);
            }
            rm=fmaxf(rm,__shfl_xor_sync(~0u,rm,1));
            rm=fmaxf(rm,__shfl_xor_sync(~0u,rm,2));
            rm=fmaxf(rm,__shfl_xor_sync(~0u,rm,4));
            rm=fmaxf(rm,__shfl_xor_sync(~0u,rm,8));
            float mn = fmaxf(mrow[r], rm);
            float p[4], rs=0.f;
            #pragma unroll
            for (int c=0;c<4;++c){ p[c]=ok[c]?__expf(sv[r][c]-mn):0.f; rs+=p[c]; }
            rs+=__shfl_xor_sync(~0u,rs,1);
            rs+=__shfl_xor_sync(~0u,rs,2);
            rs+=__shfl_xor_sync(~0u,rs,4);
            rs+=__shfl_xor_sync(~0u,rs,8);
            float scl=__expf(mrow[r]-mn);
            lrow[r]=lrow[r]*scl+rs; mrow[r]=mn;
            ull sp=pk(scl,scl);
            #pragma unroll
            for (int j=0;j<4;++j) o2[r][j]=mul2(o2[r][j],sp);
            #pragma unroll
            for (int c=0;c<4;++c) Ps[(tm*4+r)*64+tn*4+c]=p[c];
        }
        __syncthreads();

        #pragma unroll 4
        for (int k=0;k<64;++k){
            ulonglong2 v0=*(const ulonglong2*)&Vs[k*128+tn*8];
            ulonglong2 v1=*(const ulonglong2*)&Vs[k*128+tn*8+4];
            #pragma unroll
            for (int r=0;r<4;++r){
                ull pp=pk(Ps[(tm*4+r)*64+k],Ps[(tm*4+r)*64+k]);
                fma2(o2[r][0],pp,v0.x); fma2(o2[r][1],pp,v0.y);
                fma2(o2[r][2],pp,v1.x); fma2(o2[r][3],pp,v1.y);
            }
        }
        __syncthreads();
    }

    #pragma unroll
    for (int r=0;r<4;++r){
        float inv=1.0f/lrow[r];
        ull ip=pk(inv,inv);
        float* orow=&Og[(size_t)(b*S_LEN+q0+tm*4+r)*QDIM + h*HD + tn*8];
        *(float2*)&orow[0]=up(mul2(o2[r][0],ip));
        *(float2*)&orow[2]=up(mul2(o2[r][1],ip));
        *(float2*)&orow[4]=up(mul2(o2[r][2],ip));
        *(float2*)&orow[6]=up(mul2(o2[r][3],ip));
    }
}

// ---------------------------------------------------------------------------
extern "C" void kernel_launch(void* const* d_in, const int* in_sizes, int n_in,
                              void* d_out, int out_size)
{
    const float* X  = (const float*)d_in[0];
    const float* Wq = (const float*)d_in[1];
    const float* Wk = (const float*)d_in[2];
    const float* Wv = (const float*)d_in[3];
    const float* Wo = (const float*)d_in[4];
    float* out = (float*)d_out;

    float *q,*kv,*ao;
    bf16 *xh,*xl,*wqh,*wql,*wkh,*wkl,*woh,*wol,*aoh,*aol;
    cudaGetSymbolAddress((void**)&q,  g_Q);
    cudaGetSymbolAddress((void**)&kv, g_KV);
    cudaGetSymbolAddress((void**)&ao, g_AO);
    cudaGetSymbolAddress((void**)&xh, g_xh);  cudaGetSymbolAddress((void**)&xl, g_xl);
    cudaGetSymbolAddress((void**)&wqh,g_wqh); cudaGetSymbolAddress((void**)&wql,g_wql);
    cudaGetSymbolAddress((void**)&wkh,g_wkh); cudaGetSymbolAddress((void**)&wkl,g_wkl);
    cudaGetSymbolAddress((void**)&woh,g_woh); cudaGetSymbolAddress((void**)&wol,g_wol);
    cudaGetSymbolAddress((void**)&aoh,g_aoh); cudaGetSymbolAddress((void**)&aol,g_aol);

    const size_t KVW = (size_t)1024*HID;

    split_bf<<<(int)(((size_t)MROWS*HID)/1024), 256>>>(X,  xh,  xl);
    split_bf<<<(int)(((size_t)QDIM*HID)/1024),  256>>>(Wq, wqh, wql);
    split_bf<<<(int)(KVW/1024), 256>>>(Wk, wkh,       wkl);
    split_bf<<<(int)(KVW/1024), 256>>>(Wv, wkh + KVW, wkl + KVW);
    split_bf<<<(int)(((size_t)HID*QDIM)/1024),  256>>>(Wo, woh, wol);

    cudaFuncSetAttribute(gemm_bf16s, cudaFuncAttributeMaxDynamicSharedMemorySize, GSMEM);
    gemm_bf16s<<<dim3(QDIM/128, MROWS/128), 256, GSMEM>>>(xh,xl,wqh,wql,q,  QDIM);
    gemm_bf16s<<<dim3(KVLD/128, MROWS/128), 256, GSMEM>>>(xh,xl,wkh,wkl,kv, KVLD);

    rope_kernel<<<(MROWS*NH *64)/256, 256>>>(q,  NH,  QDIM);
    rope_kernel<<<(MROWS*NKV*64)/256, 256>>>(kv, NKV, KVLD);

    const int asmem = (64*128 + 128*66 + 64*128 + 64*64)*4;
    cudaFuncSetAttribute(attn_kernel, cudaFuncAttributeMaxDynamicSharedMemorySize, asmem);
    attn_kernel<<<dim3(S_LEN/64, NH, 2), 256, asmem>>>(q, kv, kv + 1024, ao);

    split_bf<<<(int)(((size_t)MROWS*QDIM)/1024), 256>>>(ao, aoh, aol);
    gemm_bf16s<<<dim3(QDIM/128, MROWS/128), 256, GSMEM>>>(aoh,aol,woh,wol,out,QDIM);
}

// round 5
// speedup vs baseline: 2.4488x; 1.3785x over previous
#include <cuda_runtime.h>
#include <cuda_bf16.h>
#include <math.h>
#include <stdint.h>

#define S_LEN 2048
#define HID   4096
#define NH    32
#define NKV   8
#define HD    128
#define WIN   1024
#define QDIM  4096
#define KVLD  2048
#define KVDIM 1024
#define MROWS 4096

typedef unsigned long long ull;
typedef __nv_bfloat16 bf16;

__device__ float g_Q  [(size_t)MROWS*QDIM];
__device__ float g_KV [(size_t)MROWS*KVLD];
__device__ bf16 g_xh [(size_t)MROWS*HID],  g_xl [(size_t)MROWS*HID];
__device__ bf16 g_wqh[(size_t)QDIM*HID],   g_wql[(size_t)QDIM*HID];
__device__ bf16 g_wkh[(size_t)KVLD*HID],   g_wkl[(size_t)KVLD*HID];
__device__ bf16 g_woh[(size_t)HID*QDIM],   g_wol[(size_t)HID*QDIM];
__device__ bf16 g_qh [(size_t)MROWS*QDIM], g_ql [(size_t)MROWS*QDIM];
__device__ bf16 g_kh [(size_t)MROWS*KVDIM],g_kl [(size_t)MROWS*KVDIM];
__device__ bf16 g_vh [(size_t)MROWS*KVDIM],g_vl [(size_t)MROWS*KVDIM];
__device__ bf16 g_aoh[(size_t)MROWS*QDIM], g_aol[(size_t)MROWS*QDIM];

// ---------------- PTX helpers ----------------
__device__ __forceinline__ uint32_t s2u(const void* p){
    uint32_t a;
    asm("{ .reg .u64 t; cvta.to.shared.u64 t,%1; cvt.u32.u64 %0,t; }":"=r"(a):"l"(p));
    return a;
}
#define CPA(dst,src) asm volatile( \
    "cp.async.cg.shared.global [%0],[%1],16;" :: "r"(dst),"l"(src) : "memory")
#define CPA_COMMIT() asm volatile("cp.async.commit_group;" ::: "memory")
#define CPA_WAIT0()  asm volatile("cp.async.wait_group 0;" ::: "memory")
#define CPA_WAIT1()  asm volatile("cp.async.wait_group 1;" ::: "memory")
#define CPA_WAIT2()  asm volatile("cp.async.wait_group 2;" ::: "memory")

#define LDSM4(r,addr) asm volatile( \
    "ldmatrix.sync.aligned.m8n8.x4.shared.b16 {%0,%1,%2,%3},[%4];" \
    : "=r"((r)[0]),"=r"((r)[1]),"=r"((r)[2]),"=r"((r)[3]) : "r"(addr))
#define LDSM4T(r,addr) asm volatile( \
    "ldmatrix.sync.aligned.m8n8.x4.trans.shared.b16 {%0,%1,%2,%3},[%4];" \
    : "=r"((r)[0]),"=r"((r)[1]),"=r"((r)[2]),"=r"((r)[3]) : "r"(addr))

#define MMA_BF16(c,a,b) asm volatile( \
    "mma.sync.aligned.m16n8k16.row.col.f32.bf16.bf16.f32 " \
    "{%0,%1,%2,%3},{%4,%5,%6,%7},{%8,%9},{%0,%1,%2,%3};" \
    : "+f"((c)[0]),"+f"((c)[1]),"+f"((c)[2]),"+f"((c)[3]) \
    : "r"((a)[0]),"r"((a)[1]),"r"((a)[2]),"r"((a)[3]),"r"((b)[0]),"r"((b)[1]))

// pack two fp32 into bf16x2 reg: low half = lo, high half = hi
__device__ __forceinline__ uint32_t pkbf(float lo, float hi){
    uint32_t r;
    asm("cvt.rn.bf16x2.f32 %0,%1,%2;" : "=r"(r) : "f"(hi), "f"(lo));
    return r;
}
// hi/lo split pack: returns hi-pack, writes residual pack
__device__ __forceinline__ uint32_t splitpk(float a, float b, uint32_t &res){
    uint32_t h = pkbf(a, b);
    float ra = a - __uint_as_float(h << 16);
    float rb = b - __uint_as_float(h & 0xFFFF0000u);
    res = pkbf(ra, rb);
    return h;
}

// ---------------------------------------------------------------------------
// bf16 split HMMA GEMM (unchanged, proven): C = A[M,K]·B[N,K]^T
// ---------------------------------------------------------------------------
#define GK      4096
#define NCHG    128
#define ROWB    80
#define ARR_B   10240
#define STG_B   40960
#define OFF_AL  10240
#define OFF_BH  20480
#define OFF_BL  30720
#define GSMEM   (4*STG_B)

static __device__ __forceinline__ void load_stage(
    uint32_t sb, int stage, int kc, int m0, int n0, int tid,
    const bf16* __restrict__ Ah, const bf16* __restrict__ Al,
    const bf16* __restrict__ Bh, const bf16* __restrict__ Bl)
{
    uint32_t st = sb + stage*STG_B;
    #pragma unroll
    for (int it=0; it<2; ++it){
        int idx = tid + it*256;
        int r = idx>>2, ch = idx&3;
        uint32_t so = (uint32_t)(r*ROWB + ch*16);
        size_t gA = (size_t)(m0+r)*GK + kc + ch*8;
        size_t gB = (size_t)(n0+r)*GK + kc + ch*8;
        CPA(st+so,        Ah+gA);
        CPA(st+OFF_AL+so, Al+gA);
        CPA(st+OFF_BH+so, Bh+gB);
        CPA(st+OFF_BL+so, Bl+gB);
    }
    CPA_COMMIT();
}

__global__ void __launch_bounds__(256) gemm_bf16s(
    const bf16* __restrict__ Ah, const bf16* __restrict__ Al,
    const bf16* __restrict__ Bh, const bf16* __restrict__ Bl,
    float* __restrict__ C, int ldC)
{
    extern __shared__ __align__(128) char sm[];
    const uint32_t sb = s2u(sm);
    const int tid = threadIdx.x, wid = tid>>5, lane = tid&31;
    const int wm = wid&3, wn = wid>>2;
    const int g = lane>>2, tg = lane&3;
    const int m0 = blockIdx.y*128, n0 = blockIdx.x*128;

    float acc[2][8][4];
    #pragma unroll
    for (int i=0;i<2;++i)
        #pragma unroll
        for (int j=0;j<8;++j){acc[i][j][0]=0;acc[i][j][1]=0;acc[i][j][2]=0;acc[i][j][3]=0;}

    load_stage(sb,0,0, m0,n0,tid,Ah,Al,Bh,Bl);
    load_stage(sb,1,32,m0,n0,tid,Ah,Al,Bh,Bl);
    load_stage(sb,2,64,m0,n0,tid,Ah,Al,Bh,Bl);

    const uint32_t a_row  = (uint32_t)(wm*32 + (lane&15));
    const uint32_t a_colb = (uint32_t)((lane>>4)*16);
    const uint32_t b_row  = (uint32_t)(wn*64 + (lane&7) + ((lane>>4)<<3));
    const uint32_t b_colb = (uint32_t)(((lane>>3)&1)*16);

    for (int c=0; c<NCHG; ++c){
        CPA_WAIT2();
        __syncthreads();
        if (c+3 < NCHG) load_stage(sb,(c+3)&3,(c+3)*32, m0,n0,tid,Ah,Al,Bh,Bl);
        else CPA_COMMIT();

        const uint32_t st = sb + (c&3)*STG_B;
        #pragma unroll
        for (int s=0; s<2; ++s){
            uint32_t ah[2][4], al[2][4];
            #pragma unroll
            for (int mt=0; mt<2; ++mt){
                uint32_t aa = st + (a_row + mt*16)*ROWB + s*32 + a_colb;
                LDSM4(ah[mt], aa);
                LDSM4(al[mt], aa + OFF_AL);
            }
            uint32_t bh[8][2], bl[8][2];
            #pragma unroll
            for (int p=0; p<4; ++p){
                uint32_t ba = st + OFF_BH + (b_row + p*16)*ROWB + s*32 + b_colb;
                uint32_t r[4];
                LDSM4(r, ba);
                bh[2*p][0]=r[0]; bh[2*p][1]=r[1]; bh[2*p+1][0]=r[2]; bh[2*p+1][1]=r[3];
                LDSM4(r, ba + ARR_B);
                bl[2*p][0]=r[0]; bl[2*p][1]=r[1]; bl[2*p+1][0]=r[2]; bl[2*p+1][1]=r[3];
            }
            #pragma unroll
            for (int mt=0; mt<2; ++mt)
                #pragma unroll
                for (int nt=0; nt<8; ++nt){
                    MMA_BF16(acc[mt][nt], ah[mt], bh[nt]);
                    MMA_BF16(acc[mt][nt], ah[mt], bl[nt]);
                    MMA_BF16(acc[mt][nt], al[mt], bh[nt]);
                }
        }
    }
    #pragma unroll
    for (int mt=0; mt<2; ++mt)
        #pragma unroll
        for (int nt=0; nt<8; ++nt){
            int row = m0 + wm*32 + mt*16 + g;
            int col = n0 + wn*64 + nt*8 + tg*2;
            float2 v0 = {acc[mt][nt][0], acc[mt][nt][1]};
            float2 v1 = {acc[mt][nt][2], acc[mt][nt][3]};
            *(float2*)&C[(size_t)row*ldC + col]     = v0;
            *(float2*)&C[(size_t)(row+8)*ldC + col] = v1;
        }
}

// ---------------- fp32 -> bf16 hi/lo split ----------------
__global__ void split_bf(const float* __restrict__ in,
                         bf16* __restrict__ hi, bf16* __restrict__ lo)
{
    size_t i = ((size_t)blockIdx.x*blockDim.x + threadIdx.x)*4;
    float4 v = *(const float4*)(in+i);
    bf16 hx=__float2bfloat16(v.x), hy=__float2bfloat16(v.y);
    bf16 hz=__float2bfloat16(v.z), hw=__float2bfloat16(v.w);
    hi[i]=hx; hi[i+1]=hy; hi[i+2]=hz; hi[i+3]=hw;
    lo[i]  =__float2bfloat16(v.x-__bfloat162float(hx));
    lo[i+1]=__float2bfloat16(v.y-__bfloat162float(hy));
    lo[i+2]=__float2bfloat16(v.z-__bfloat162float(hz));
    lo[i+3]=__float2bfloat16(v.w-__bfloat162float(hw));
}

// ---------------- RoPE + split (scale folded into Q) ----------------
__global__ void rope_split(const float* __restrict__ buf, bf16* __restrict__ oh,
                           bf16* __restrict__ ol, int nheads, int rstride, float scale)
{
    int idx = blockIdx.x*blockDim.x + threadIdx.x;
    int i = idx & 63, t = idx >> 6;
    int h = t % nheads, row = t / nheads;
    int s = row & (S_LEN-1);
    float inv = powf(10000.0f, -(float)i*(1.0f/64.0f));
    float sn, cs; sincosf((float)s*inv, &sn, &cs);
    const float* p = buf + (size_t)row*rstride + h*HD;
    float x1 = p[i], x2 = p[i+64];
    float y1 = (x1*cs - x2*sn)*scale;
    float y2 = (x2*cs + x1*sn)*scale;
    size_t o = (size_t)row*(nheads*HD) + h*HD + i;
    bf16 h1=__float2bfloat16(y1), h2=__float2bfloat16(y2);
    oh[o]=h1;     ol[o]=__float2bfloat16(y1-__bfloat162float(h1));
    oh[o+64]=h2;  ol[o+64]=__float2bfloat16(y2-__bfloat162float(h2));
}

// split V half of KV (strided input)
__global__ void split_v(const float* __restrict__ v, bf16* __restrict__ oh,
                        bf16* __restrict__ ol)
{
    size_t idx = (size_t)blockIdx.x*blockDim.x + threadIdx.x;
    size_t r = idx >> 8;
    int c = (int)(idx & 255) * 4;
    float4 x = *(const float4*)&v[r*KVLD + c];
    size_t o = r*KVDIM + c;
    bf16 hx=__float2bfloat16(x.x), hy=__float2bfloat16(x.y);
    bf16 hz=__float2bfloat16(x.z), hw=__float2bfloat16(x.w);
    oh[o]=hx; oh[o+1]=hy; oh[o+2]=hz; oh[o+3]=hw;
    ol[o]  =__float2bfloat16(x.x-__bfloat162float(hx));
    ol[o+1]=__float2bfloat16(x.y-__bfloat162float(hy));
    ol[o+2]=__float2bfloat16(x.z-__bfloat162float(hz));
    ol[o+3]=__float2bfloat16(x.w-__bfloat162float(hw));
}

// ---------------------------------------------------------------------------
// HMMA flash attention: BQ=128, BK=64, 8 warps x 16 q-rows, split bf16.
// ---------------------------------------------------------------------------
#define AROWB 272
#define QSZ   34816      // 128*272
#define KVARR 17408      // 64*272
#define KVSTG 69632      // 4 arrays
#define ASMEM (2*QSZ + 2*KVSTG)   // 208896

static __device__ __forceinline__ void a_load_kv(
    uint32_t st, int kbase, int brow, int tid, int kvh,
    const bf16* __restrict__ kh, const bf16* __restrict__ kl,
    const bf16* __restrict__ vh, const bf16* __restrict__ vl)
{
    #pragma unroll
    for (int it=0; it<4; ++it){
        int idx = tid + it*256;
        int r = idx>>4, ch = idx&15;
        uint32_t so = (uint32_t)(r*AROWB + ch*16);
        size_t gsrc = (size_t)(brow + kbase + r)*KVDIM + kvh*HD + ch*8;
        CPA(st + so,           kh + gsrc);
        CPA(st + KVARR + so,   kl + gsrc);
        CPA(st + 2*KVARR + so, vh + gsrc);
        CPA(st + 3*KVARR + so, vl + gsrc);
    }
    CPA_COMMIT();
}

__global__ void __launch_bounds__(256,1) attn_mma(
    const bf16* __restrict__ qh_, const bf16* __restrict__ ql_,
    const bf16* __restrict__ kh_, const bf16* __restrict__ kl_,
    const bf16* __restrict__ vh_, const bf16* __restrict__ vl_,
    bf16* __restrict__ aoh, bf16* __restrict__ aol)
{
    extern __shared__ __align__(128) char sm[];
    const uint32_t sb = s2u(sm);
    const uint32_t QH = sb, QL = sb + QSZ, ST0 = sb + 2*QSZ;

    const int tid = threadIdx.x, w = tid>>5, lane = tid&31;
    const int qb = blockIdx.x, hh = blockIdx.y, b = blockIdx.z;
    const int q0 = qb*128, kvh = hh>>2;
    const int g = lane>>2, colc = (lane&3)*2;
    const int browg = b*S_LEN;   // global row base

    // Q tile -> smem (group 0)
    #pragma unroll
    for (int it=0; it<8; ++it){
        int idx = tid + it*256;
        int r = idx>>4, ch = idx&15;
        uint32_t so = (uint32_t)(r*AROWB + ch*16);
        size_t gsrc = (size_t)(browg + q0 + r)*QDIM + hh*HD + ch*8;
        CPA(QH + so, qh_ + gsrc);
        CPA(QL + so, ql_ + gsrc);
    }
    CPA_COMMIT();

    int lo = q0 - (WIN-1); if (lo < 0) lo = 0;
    const int kt0 = lo >> 6, ktend = 2*qb + 1;

    a_load_kv(ST0, kt0*64, browg, tid, kvh, kh_, kl_, vh_, vl_);

    uint32_t qfh[8][4], qfl[8][4];
    float O[16][4];
    #pragma unroll
    for (int t=0;t<16;++t){O[t][0]=0;O[t][1]=0;O[t][2]=0;O[t][3]=0;}
    float m0 = -1e30f, m1 = -1e30f, l0 = 0.f, l1 = 0.f;

    const uint32_t a_row  = (uint32_t)(w*16 + (lane&15));
    const uint32_t a_colb = (uint32_t)((lane>>4)*16);
    const uint32_t kb_row = (uint32_t)((lane&7) + ((lane>>4)<<3));
    const uint32_t kb_col = (uint32_t)(((lane>>3)&1)*16);
    const uint32_t vb_row = (uint32_t)((lane&7) + (lane&8));
    const uint32_t vb_col = (uint32_t)((lane>>4)*16);

    for (int kt = kt0; kt <= ktend; ++kt){
        const int s = (kt - kt0) & 1;
        const uint32_t ST = ST0 + (uint32_t)s*KVSTG;
        if (kt < ktend){
            a_load_kv(ST0 + (uint32_t)(s^1)*KVSTG, (kt+1)*64, browg, tid, kvh,
                      kh_, kl_, vh_, vl_);
            CPA_WAIT1();
        } else {
            CPA_WAIT0();
        }
        __syncthreads();

        if (kt == kt0){
            #pragma unroll
            for (int kk=0; kk<8; ++kk){
                uint32_t aa = QH + a_row*AROWB + kk*32 + a_colb;
                LDSM4(qfh[kk], aa);
                LDSM4(qfl[kk], aa + QSZ);
            }
        }

        // ---- S = Q K^T (3-term split) ----
        float p[8][4];
        #pragma unroll
        for (int t=0;t<8;++t){p[t][0]=0;p[t][1]=0;p[t][2]=0;p[t][3]=0;}
        #pragma unroll
        for (int kk=0; kk<8; ++kk){
            #pragma unroll
            for (int np=0; np<4; ++np){
                uint32_t ba = ST + (np*16 + kb_row)*AROWB + kk*32 + kb_col;
                uint32_t kf[4], kfl[4];
                LDSM4(kf, ba);
                LDSM4(kfl, ba + KVARR);
                MMA_BF16(p[2*np],   qfh[kk], kf);
                MMA_BF16(p[2*np+1], qfh[kk], kf+2);
                MMA_BF16(p[2*np],   qfh[kk], kfl);
                MMA_BF16(p[2*np+1], qfh[kk], kfl+2);
                MMA_BF16(p[2*np],   qfl[kk], kf);
                MMA_BF16(p[2*np+1], qfl[kk], kf+2);
            }
        }

        // ---- mask + online softmax ----
        const int kbase = kt*64;
        const int r0 = q0 + w*16 + g, r1 = r0 + 8;
        float rm0 = -1e30f, rm1 = -1e30f;
        #pragma unroll
        for (int t=0; t<8; ++t){
            #pragma unroll
            for (int e=0; e<2; ++e){
                int kj = kbase + t*8 + colc + e;
                if (!((kj<=r0)&&(r0-kj<WIN))) p[t][e]   = -1e30f;
                if (!((kj<=r1)&&(r1-kj<WIN))) p[t][2+e] = -1e30f;
            }
            rm0 = fmaxf(rm0, fmaxf(p[t][0], p[t][1]));
            rm1 = fmaxf(rm1, fmaxf(p[t][2], p[t][3]));
        }
        rm0 = fmaxf(rm0, __shfl_xor_sync(~0u, rm0, 1));
        rm0 = fmaxf(rm0, __shfl_xor_sync(~0u, rm0, 2));
        rm1 = fmaxf(rm1, __shfl_xor_sync(~0u, rm1, 1));
        rm1 = fmaxf(rm1, __shfl_xor_sync(~0u, rm1, 2));
        float mn0 = fmaxf(m0, rm0), mn1 = fmaxf(m1, rm1);
        float sc0 = __expf(m0 - mn0), sc1 = __expf(m1 - mn1);
        m0 = mn0; m1 = mn1;
        float rs0 = 0.f, rs1 = 0.f;
        #pragma unroll
        for (int t=0; t<8; ++t){
            p[t][0] = __expf(p[t][0]-mn0); p[t][1] = __expf(p[t][1]-mn0);
            p[t][2] = __expf(p[t][2]-mn1); p[t][3] = __expf(p[t][3]-mn1);
            rs0 += p[t][0] + p[t][1];
            rs1 += p[t][2] + p[t][3];
        }
        rs0 += __shfl_xor_sync(~0u, rs0, 1); rs0 += __shfl_xor_sync(~0u, rs0, 2);
        rs1 += __shfl_xor_sync(~0u, rs1, 1); rs1 += __shfl_xor_sync(~0u, rs1, 2);
        l0 = l0*sc0 + rs0; l1 = l1*sc1 + rs1;
        #pragma unroll
        for (int t=0; t<16; ++t){
            O[t][0]*=sc0; O[t][1]*=sc0; O[t][2]*=sc1; O[t][3]*=sc1;
        }

        // ---- O += P V (3-term split, register-repacked P) ----
        const uint32_t VB = ST + 2*KVARR;
        #pragma unroll
        for (int kk=0; kk<4; ++kk){
            uint32_t pha[4], pla[4];
            pha[0] = splitpk(p[2*kk][0],   p[2*kk][1],   pla[0]);
            pha[1] = splitpk(p[2*kk][2],   p[2*kk][3],   pla[1]);
            pha[2] = splitpk(p[2*kk+1][0], p[2*kk+1][1], pla[2]);
            pha[3] = splitpk(p[2*kk+1][2], p[2*kk+1][3], pla[3]);
            #pragma unroll
            for (int vp=0; vp<8; ++vp){
                uint32_t va = VB + (kk*16 + vb_row)*AROWB + vp*32 + vb_col;
                uint32_t vf[4], vfl[4];
                LDSM4T(vf, va);
                LDSM4T(vfl, va + KVARR);
                MMA_BF16(O[2*vp],   pha, vf);
                MMA_BF16(O[2*vp+1], pha, vf+2);
                MMA_BF16(O[2*vp],   pha, vfl);
                MMA_BF16(O[2*vp+1], pha, vfl+2);
                MMA_BF16(O[2*vp],   pla, vf);
                MMA_BF16(O[2*vp+1], pla, vf+2);
            }
        }
        __syncthreads();
    }

    // ---- epilogue: normalize, split, write aoh/aol ----
    float il0 = 1.0f/l0, il1 = 1.0f/l1;
    const size_t row0 = (size_t)(browg + q0 + w*16 + g);
    #pragma unroll
    for (int nt=0; nt<16; ++nt){
        size_t o0 = row0*QDIM + hh*HD + nt*8 + colc;
        size_t o1 = o0 + 8*QDIM;
        uint32_t hr, lr;
        hr = splitpk(O[nt][0]*il0, O[nt][1]*il0, lr);
        *(uint32_t*)&aoh[o0] = hr; *(uint32_t*)&aol[o0] = lr;
        hr = splitpk(O[nt][2]*il1, O[nt][3]*il1, lr);
        *(uint32_t*)&aoh[o1] = hr; *(uint32_t*)&aol[o1] = lr;
    }
}

// ---------------------------------------------------------------------------
extern "C" void kernel_launch(void* const* d_in, const int* in_sizes, int n_in,
                              void* d_out, int out_size)
{
    const float* X  = (const float*)d_in[0];
    const float* Wq = (const float*)d_in[1];
    const float* Wk = (const float*)d_in[2];
    const float* Wv = (const float*)d_in[3];
    const float* Wo = (const float*)d_in[4];
    float* out = (float*)d_out;

    float *q,*kv;
    bf16 *xh,*xl,*wqh,*wql,*wkh,*wkl,*woh,*wol;
    bf16 *qh,*ql,*kh,*kl,*vh,*vl,*aoh,*aol;
    cudaGetSymbolAddress((void**)&q,  g_Q);
    cudaGetSymbolAddress((void**)&kv, g_KV);
    cudaGetSymbolAddress((void**)&xh, g_xh);  cudaGetSymbolAddress((void**)&xl, g_xl);
    cudaGetSymbolAddress((void**)&wqh,g_wqh); cudaGetSymbolAddress((void**)&wql,g_wql);
    cudaGetSymbolAddress((void**)&wkh,g_wkh); cudaGetSymbolAddress((void**)&wkl,g_wkl);
    cudaGetSymbolAddress((void**)&woh,g_woh); cudaGetSymbolAddress((void**)&wol,g_wol);
    cudaGetSymbolAddress((void**)&qh, g_qh);  cudaGetSymbolAddress((void**)&ql, g_ql);
    cudaGetSymbolAddress((void**)&kh, g_kh);  cudaGetSymbolAddress((void**)&kl, g_kl);
    cudaGetSymbolAddress((void**)&vh, g_vh);  cudaGetSymbolAddress((void**)&vl, g_vl);
    cudaGetSymbolAddress((void**)&aoh,g_aoh); cudaGetSymbolAddress((void**)&aol,g_aol);

    const size_t KVW = (size_t)1024*HID;

    split_bf<<<(int)(((size_t)MROWS*HID)/1024), 256>>>(X,  xh,  xl);
    split_bf<<<(int)(((size_t)QDIM*HID)/1024),  256>>>(Wq, wqh, wql);
    split_bf<<<(int)(KVW/1024), 256>>>(Wk, wkh,       wkl);
    split_bf<<<(int)(KVW/1024), 256>>>(Wv, wkh + KVW, wkl + KVW);
    split_bf<<<(int)(((size_t)HID*QDIM)/1024),  256>>>(Wo, woh, wol);

    cudaFuncSetAttribute(gemm_bf16s, cudaFuncAttributeMaxDynamicSharedMemorySize, GSMEM);
    gemm_bf16s<<<dim3(QDIM/128, MROWS/128), 256, GSMEM>>>(xh,xl,wqh,wql,q,  QDIM);
    gemm_bf16s<<<dim3(KVLD/128, MROWS/128), 256, GSMEM>>>(xh,xl,wkh,wkl,kv, KVLD);

    const float SC = 0.08838834764831845f;
    rope_split<<<(MROWS*NH *64)/256, 256>>>(q,  qh, ql, NH,  QDIM, SC);
    rope_split<<<(MROWS*NKV*64)/256, 256>>>(kv, kh, kl, NKV, KVLD, 1.0f);
    split_v<<<(int)(((size_t)MROWS*KVDIM)/1024), 256>>>(kv + 1024, vh, vl);

    cudaFuncSetAttribute(attn_mma, cudaFuncAttributeMaxDynamicSharedMemorySize, ASMEM);
    attn_mma<<<dim3(S_LEN/128, NH, 2), 256, ASMEM>>>(qh,ql,kh,kl,vh,vl,aoh,aol);

    gemm_bf16s<<<dim3(QDIM/128, MROWS/128), 256, GSMEM>>>(aoh,aol,woh,wol,out,QDIM);
}

// round 6
// speedup vs baseline: 3.3971x; 1.3872x over previous
#include <cuda_runtime.h>
#include <cuda_fp16.h>
#include <math.h>
#include <stdint.h>

#define S_LEN 2048
#define HID   4096
#define NH    32
#define NKV   8
#define HD    128
#define WIN   1024
#define QDIM  4096
#define KVLD  2048
#define KVDIM 1024
#define MROWS 4096

typedef __half hlf;

__device__ float g_Q  [(size_t)MROWS*QDIM];
__device__ float g_KV [(size_t)MROWS*KVLD];
__device__ hlf g_xh [(size_t)MROWS*HID],  g_xl [(size_t)MROWS*HID];
__device__ hlf g_wqh[(size_t)QDIM*HID];
__device__ hlf g_wkh[(size_t)KVLD*HID];
__device__ hlf g_woh[(size_t)HID*QDIM];
__device__ hlf g_qh [(size_t)MROWS*QDIM], g_ql [(size_t)MROWS*QDIM];
__device__ hlf g_kh [(size_t)MROWS*KVDIM];
__device__ hlf g_vh [(size_t)MROWS*KVDIM];
__device__ hlf g_aoh[(size_t)MROWS*QDIM], g_aol[(size_t)MROWS*QDIM];

// ---------------- PTX helpers ----------------
__device__ __forceinline__ uint32_t s2u(const void* p){
    uint32_t a;
    asm("{ .reg .u64 t; cvta.to.shared.u64 t,%1; cvt.u32.u64 %0,t; }":"=r"(a):"l"(p));
    return a;
}
#define CPA(dst,src) asm volatile( \
    "cp.async.cg.shared.global [%0],[%1],16;" :: "r"(dst),"l"(src) : "memory")
#define CPA_COMMIT() asm volatile("cp.async.commit_group;" ::: "memory")
#define CPA_WAIT0()  asm volatile("cp.async.wait_group 0;" ::: "memory")
#define CPA_WAIT1()  asm volatile("cp.async.wait_group 1;" ::: "memory")
#define CPA_WAIT2()  asm volatile("cp.async.wait_group 2;" ::: "memory")

#define LDSM4(r,addr) asm volatile( \
    "ldmatrix.sync.aligned.m8n8.x4.shared.b16 {%0,%1,%2,%3},[%4];" \
    : "=r"((r)[0]),"=r"((r)[1]),"=r"((r)[2]),"=r"((r)[3]) : "r"(addr))
#define LDSM4T(r,addr) asm volatile( \
    "ldmatrix.sync.aligned.m8n8.x4.trans.shared.b16 {%0,%1,%2,%3},[%4];" \
    : "=r"((r)[0]),"=r"((r)[1]),"=r"((r)[2]),"=r"((r)[3]) : "r"(addr))

#define MMA_F16(c,a,b) asm volatile( \
    "mma.sync.aligned.m16n8k16.row.col.f32.f16.f16.f32 " \
    "{%0,%1,%2,%3},{%4,%5,%6,%7},{%8,%9},{%0,%1,%2,%3};" \
    : "+f"((c)[0]),"+f"((c)[1]),"+f"((c)[2]),"+f"((c)[3]) \
    : "r"((a)[0]),"r"((a)[1]),"r"((a)[2]),"r"((a)[3]),"r"((b)[0]),"r"((b)[1]))

__device__ __forceinline__ uint32_t h2u(__half2 h){ return *reinterpret_cast<uint32_t*>(&h); }

// split-pack: returns fp16x2(a,b) (a in low half), writes residual pack
__device__ __forceinline__ uint32_t splitpk(float a, float b, uint32_t &res){
    __half2 h = __floats2half2_rn(a, b);
    float2 f = __half22float2(h);
    res = h2u(__floats2half2_rn(a - f.x, b - f.y));
    return h2u(h);
}

// ---------------------------------------------------------------------------
// fp16 split GEMM: C[M,N] = A[M,K]·B[N,K]^T,  C = Ah·Bh + Al·Bh  (fp32 acc)
// CTA 128x128, BK=32, 4-stage cp.async, 8 warps (4m x 2n).
// ---------------------------------------------------------------------------
#define GK      4096
#define NCHG    128
#define ROWB    80
#define ARR_B   10240
#define STG_B   30720
#define OFF_AL  10240
#define OFF_BH  20480
#define GSMEM   (4*STG_B)   // 122880

static __device__ __forceinline__ void load_stage(
    uint32_t sb, int stage, int kc, int m0, int n0, int tid,
    const hlf* __restrict__ Ah, const hlf* __restrict__ Al,
    const hlf* __restrict__ Bh)
{
    uint32_t st = sb + stage*STG_B;
    #pragma unroll
    for (int it=0; it<2; ++it){
        int idx = tid + it*256;
        int r = idx>>2, ch = idx&3;
        uint32_t so = (uint32_t)(r*ROWB + ch*16);
        size_t gA = (size_t)(m0+r)*GK + kc + ch*8;
        size_t gB = (size_t)(n0+r)*GK + kc + ch*8;
        CPA(st+so,        Ah+gA);
        CPA(st+OFF_AL+so, Al+gA);
        CPA(st+OFF_BH+so, Bh+gB);
    }
    CPA_COMMIT();
}

__global__ void __launch_bounds__(256) gemm_f16s(
    const hlf* __restrict__ Ah, const hlf* __restrict__ Al,
    const hlf* __restrict__ Bh, float* __restrict__ C, int ldC)
{
    extern __shared__ __align__(128) char sm[];
    const uint32_t sb = s2u(sm);
    const int tid = threadIdx.x, wid = tid>>5, lane = tid&31;
    const int wm = wid&3, wn = wid>>2;
    const int g = lane>>2, tg = lane&3;
    const int m0 = blockIdx.y*128, n0 = blockIdx.x*128;

    float acc[2][8][4];
    #pragma unroll
    for (int i=0;i<2;++i)
        #pragma unroll
        for (int j=0;j<8;++j){acc[i][j][0]=0;acc[i][j][1]=0;acc[i][j][2]=0;acc[i][j][3]=0;}

    load_stage(sb,0,0, m0,n0,tid,Ah,Al,Bh);
    load_stage(sb,1,32,m0,n0,tid,Ah,Al,Bh);
    load_stage(sb,2,64,m0,n0,tid,Ah,Al,Bh);

    const uint32_t a_row  = (uint32_t)(wm*32 + (lane&15));
    const uint32_t a_colb = (uint32_t)((lane>>4)*16);
    const uint32_t b_row  = (uint32_t)(wn*64 + (lane&7) + ((lane>>4)<<3));
    const uint32_t b_colb = (uint32_t)(((lane>>3)&1)*16);

    for (int c=0; c<NCHG; ++c){
        CPA_WAIT2();
        __syncthreads();
        if (c+3 < NCHG) load_stage(sb,(c+3)&3,(c+3)*32, m0,n0,tid,Ah,Al,Bh);
        else CPA_COMMIT();

        const uint32_t st = sb + (c&3)*STG_B;
        #pragma unroll
        for (int s=0; s<2; ++s){
            uint32_t ah[2][4], al[2][4];
            #pragma unroll
            for (int mt=0; mt<2; ++mt){
                uint32_t aa = st + (a_row + mt*16)*ROWB + s*32 + a_colb;
                LDSM4(ah[mt], aa);
                LDSM4(al[mt], aa + OFF_AL);
            }
            uint32_t bh[8][2];
            #pragma unroll
            for (int p=0; p<4; ++p){
                uint32_t ba = st + OFF_BH + (b_row + p*16)*ROWB + s*32 + b_colb;
                uint32_t r[4];
                LDSM4(r, ba);
                bh[2*p][0]=r[0]; bh[2*p][1]=r[1]; bh[2*p+1][0]=r[2]; bh[2*p+1][1]=r[3];
            }
            #pragma unroll
            for (int mt=0; mt<2; ++mt)
                #pragma unroll
                for (int nt=0; nt<8; ++nt){
                    MMA_F16(acc[mt][nt], ah[mt], bh[nt]);
                    MMA_F16(acc[mt][nt], al[mt], bh[nt]);
                }
        }
    }
    #pragma unroll
    for (int mt=0; mt<2; ++mt)
        #pragma unroll
        for (int nt=0; nt<8; ++nt){
            int row = m0 + wm*32 + mt*16 + g;
            int col = n0 + wn*64 + nt*8 + tg*2;
            float2 v0 = {acc[mt][nt][0], acc[mt][nt][1]};
            float2 v1 = {acc[mt][nt][2], acc[mt][nt][3]};
            *(float2*)&C[(size_t)row*ldC + col]     = v0;
            *(float2*)&C[(size_t)(row+8)*ldC + col] = v1;
        }
}

// ---------------- conversions ----------------
__global__ void split_h(const float* __restrict__ in,
                        hlf* __restrict__ hi, hlf* __restrict__ lo)
{
    size_t i = ((size_t)blockIdx.x*blockDim.x + threadIdx.x)*4;
    float4 v = *(const float4*)(in+i);
    uint32_t r0, r1, h0, h1;
    h0 = splitpk(v.x, v.y, r0);
    h1 = splitpk(v.z, v.w, r1);
    *(uint32_t*)&hi[i]   = h0; *(uint32_t*)&hi[i+2] = h1;
    *(uint32_t*)&lo[i]   = r0; *(uint32_t*)&lo[i+2] = r1;
}
__global__ void conv_h(const float* __restrict__ in, hlf* __restrict__ out)
{
    size_t i = ((size_t)blockIdx.x*blockDim.x + threadIdx.x)*4;
    float4 v = *(const float4*)(in+i);
    *(uint32_t*)&out[i]   = h2u(__floats2half2_rn(v.x, v.y));
    *(uint32_t*)&out[i+2] = h2u(__floats2half2_rn(v.z, v.w));
}
// V half of KV (strided) -> single fp16
__global__ void conv_v(const float* __restrict__ v, hlf* __restrict__ out)
{
    size_t idx = (size_t)blockIdx.x*blockDim.x + threadIdx.x;
    size_t r = idx >> 8;
    int c = (int)(idx & 255) * 4;
    float4 x = *(const float4*)&v[r*KVLD + c];
    size_t o = r*KVDIM + c;
    *(uint32_t*)&out[o]   = h2u(__floats2half2_rn(x.x, x.y));
    *(uint32_t*)&out[o+2] = h2u(__floats2half2_rn(x.z, x.w));
}

// ---------------- RoPE ----------------
__global__ void rope_split(const float* __restrict__ buf, hlf* __restrict__ oh,
                           hlf* __restrict__ ol, int nheads, int rstride, float scale)
{
    int idx = blockIdx.x*blockDim.x + threadIdx.x;
    int i = idx & 63, t = idx >> 6;
    int h = t % nheads, row = t / nheads;
    int s = row & (S_LEN-1);
    float inv = powf(10000.0f, -(float)i*(1.0f/64.0f));
    float sn, cs; sincosf((float)s*inv, &sn, &cs);
    const float* p = buf + (size_t)row*rstride + h*HD;
    float x1 = p[i], x2 = p[i+64];
    float y1 = (x1*cs - x2*sn)*scale;
    float y2 = (x2*cs + x1*sn)*scale;
    size_t o = (size_t)row*(nheads*HD) + h*HD + i;
    hlf h1 = __float2half_rn(y1), h2 = __float2half_rn(y2);
    oh[o]=h1;    ol[o]   =__float2half_rn(y1-__half2float(h1));
    oh[o+64]=h2; ol[o+64]=__float2half_rn(y2-__half2float(h2));
}
__global__ void rope_single(const float* __restrict__ buf, hlf* __restrict__ oh,
                            int nheads, int rstride)
{
    int idx = blockIdx.x*blockDim.x + threadIdx.x;
    int i = idx & 63, t = idx >> 6;
    int h = t % nheads, row = t / nheads;
    int s = row & (S_LEN-1);
    float inv = powf(10000.0f, -(float)i*(1.0f/64.0f));
    float sn, cs; sincosf((float)s*inv, &sn, &cs);
    const float* p = buf + (size_t)row*rstride + h*HD;
    float x1 = p[i], x2 = p[i+64];
    size_t o = (size_t)row*(nheads*HD) + h*HD + i;
    oh[o]    = __float2half_rn(x1*cs - x2*sn);
    oh[o+64] = __float2half_rn(x2*cs + x1*sn);
}

// ---------------------------------------------------------------------------
// fp16 HMMA flash attention: BQ=128, BK=64, Q split / K,V single.
// ---------------------------------------------------------------------------
#define AROWB 272
#define QSZ   34816      // 128*272
#define KVARR 17408      // 64*272
#define KVSTG 34816      // K + V
#define ASMEM (2*QSZ + 2*KVSTG)   // 139264

static __device__ __forceinline__ void a_load_kv(
    uint32_t st, int kbase, int brow, int tid, int kvh,
    const hlf* __restrict__ kh, const hlf* __restrict__ vh)
{
    #pragma unroll
    for (int it=0; it<4; ++it){
        int idx = tid + it*256;
        int r = idx>>4, ch = idx&15;
        uint32_t so = (uint32_t)(r*AROWB + ch*16);
        size_t gsrc = (size_t)(brow + kbase + r)*KVDIM + kvh*HD + ch*8;
        CPA(st + so,         kh + gsrc);
        CPA(st + KVARR + so, vh + gsrc);
    }
    CPA_COMMIT();
}

__global__ void __launch_bounds__(256,1) attn_mma(
    const hlf* __restrict__ qh_, const hlf* __restrict__ ql_,
    const hlf* __restrict__ kh_, const hlf* __restrict__ vh_,
    hlf* __restrict__ aoh, hlf* __restrict__ aol)
{
    extern __shared__ __align__(128) char sm[];
    const uint32_t sb = s2u(sm);
    const uint32_t QH = sb, QL = sb + QSZ, ST0 = sb + 2*QSZ;

    const int tid = threadIdx.x, w = tid>>5, lane = tid&31;
    const int qb = blockIdx.x, hh = blockIdx.y, b = blockIdx.z;
    const int q0 = qb*128, kvh = hh>>2;
    const int g = lane>>2, colc = (lane&3)*2;
    const int browg = b*S_LEN;

    #pragma unroll
    for (int it=0; it<8; ++it){
        int idx = tid + it*256;
        int r = idx>>4, ch = idx&15;
        uint32_t so = (uint32_t)(r*AROWB + ch*16);
        size_t gsrc = (size_t)(browg + q0 + r)*QDIM + hh*HD + ch*8;
        CPA(QH + so, qh_ + gsrc);
        CPA(QL + so, ql_ + gsrc);
    }
    CPA_COMMIT();

    int lo = q0 - (WIN-1); if (lo < 0) lo = 0;
    const int kt0 = lo >> 6, ktend = 2*qb + 1;

    a_load_kv(ST0, kt0*64, browg, tid, kvh, kh_, vh_);

    uint32_t qfh[8][4], qfl[8][4];
    float O[16][4];
    #pragma unroll
    for (int t=0;t<16;++t){O[t][0]=0;O[t][1]=0;O[t][2]=0;O[t][3]=0;}
    float m0 = -1e30f, m1 = -1e30f, l0 = 0.f, l1 = 0.f;

    const uint32_t a_row  = (uint32_t)(w*16 + (lane&15));
    const uint32_t a_colb = (uint32_t)((lane>>4)*16);
    const uint32_t kb_row = (uint32_t)((lane&7) + ((lane>>4)<<3));
    const uint32_t kb_col = (uint32_t)(((lane>>3)&1)*16);
    const uint32_t vb_row = (uint32_t)((lane&7) + (lane&8));
    const uint32_t vb_col = (uint32_t)((lane>>4)*16);

    const int rmin_w = q0 + w*16;   // warp's lowest q row

    for (int kt = kt0; kt <= ktend; ++kt){
        const int s = (kt - kt0) & 1;
        const uint32_t ST = ST0 + (uint32_t)s*KVSTG;
        if (kt < ktend){
            a_load_kv(ST0 + (uint32_t)(s^1)*KVSTG, (kt+1)*64, browg, tid, kvh, kh_, vh_);
            CPA_WAIT1();
        } else {
            CPA_WAIT0();
        }
        __syncthreads();

        if (kt == kt0){
            #pragma unroll
            for (int kk=0; kk<8; ++kk){
                uint32_t aa = QH + a_row*AROWB + kk*32 + a_colb;
                LDSM4(qfh[kk], aa);
                LDSM4(qfl[kk], aa + QSZ);
            }
        }

        const int kbase = kt*64;
        // warp-level tile skip: fully above causal edge or below window
        if ((kbase <= rmin_w + 15) && (kbase + 63 > rmin_w - WIN)){
            // ---- S = Q K^T (2-term) ----
            float p[8][4];
            #pragma unroll
            for (int t=0;t<8;++t){p[t][0]=0;p[t][1]=0;p[t][2]=0;p[t][3]=0;}
            #pragma unroll
            for (int kk=0; kk<8; ++kk){
                #pragma unroll
                for (int np=0; np<4; ++np){
                    uint32_t ba = ST + (np*16 + kb_row)*AROWB + kk*32 + kb_col;
                    uint32_t kf[4];
                    LDSM4(kf, ba);
                    MMA_F16(p[2*np],   qfh[kk], kf);
                    MMA_F16(p[2*np+1], qfh[kk], kf+2);
                    MMA_F16(p[2*np],   qfl[kk], kf);
                    MMA_F16(p[2*np+1], qfl[kk], kf+2);
                }
            }

            // ---- mask + online softmax ----
            const int r0 = rmin_w + g, r1 = r0 + 8;
            float rm0 = -1e30f, rm1 = -1e30f;
            #pragma unroll
            for (int t=0; t<8; ++t){
                #pragma unroll
                for (int e=0; e<2; ++e){
                    int kj = kbase + t*8 + colc + e;
                    if (!((kj<=r0)&&(r0-kj<WIN))) p[t][e]   = -1e30f;
                    if (!((kj<=r1)&&(r1-kj<WIN))) p[t][2+e] = -1e30f;
                }
                rm0 = fmaxf(rm0, fmaxf(p[t][0], p[t][1]));
                rm1 = fmaxf(rm1, fmaxf(p[t][2], p[t][3]));
            }
            rm0 = fmaxf(rm0, __shfl_xor_sync(~0u, rm0, 1));
            rm0 = fmaxf(rm0, __shfl_xor_sync(~0u, rm0, 2));
            rm1 = fmaxf(rm1, __shfl_xor_sync(~0u, rm1, 1));
            rm1 = fmaxf(rm1, __shfl_xor_sync(~0u, rm1, 2));
            float mn0 = fmaxf(m0, rm0), mn1 = fmaxf(m1, rm1);
            float sc0 = __expf(m0 - mn0), sc1 = __expf(m1 - mn1);
            m0 = mn0; m1 = mn1;
            float rs0 = 0.f, rs1 = 0.f;
            #pragma unroll
            for (int t=0; t<8; ++t){
                p[t][0] = __expf(p[t][0]-mn0); p[t][1] = __expf(p[t][1]-mn0);
                p[t][2] = __expf(p[t][2]-mn1); p[t][3] = __expf(p[t][3]-mn1);
                rs0 += p[t][0] + p[t][1];
                rs1 += p[t][2] + p[t][3];
            }
            rs0 += __shfl_xor_sync(~0u, rs0, 1); rs0 += __shfl_xor_sync(~0u, rs0, 2);
            rs1 += __shfl_xor_sync(~0u, rs1, 1); rs1 += __shfl_xor_sync(~0u, rs1, 2);
            l0 = l0*sc0 + rs0; l1 = l1*sc1 + rs1;
            #pragma unroll
            for (int t=0; t<16; ++t){
                O[t][0]*=sc0; O[t][1]*=sc0; O[t][2]*=sc1; O[t][3]*=sc1;
            }

            // ---- O += P V (2-term) ----
            const uint32_t VB = ST + KVARR;
            #pragma unroll
            for (int kk=0; kk<4; ++kk){
                uint32_t pha[4], pla[4];
                pha[0] = splitpk(p[2*kk][0],   p[2*kk][1],   pla[0]);
                pha[1] = splitpk(p[2*kk][2],   p[2*kk][3],   pla[1]);
                pha[2] = splitpk(p[2*kk+1][0], p[2*kk+1][1], pla[2]);
                pha[3] = splitpk(p[2*kk+1][2], p[2*kk+1][3], pla[3]);
                #pragma unroll
                for (int vp=0; vp<8; ++vp){
                    uint32_t va = VB + (kk*16 + vb_row)*AROWB + vp*32 + vb_col;
                    uint32_t vf[4];
                    LDSM4T(vf, va);
                    MMA_F16(O[2*vp],   pha, vf);
                    MMA_F16(O[2*vp+1], pha, vf+2);
                    MMA_F16(O[2*vp],   pla, vf);
                    MMA_F16(O[2*vp+1], pla, vf+2);
                }
            }
        }
        __syncthreads();
    }

    // ---- epilogue: normalize, split, write ----
    float il0 = 1.0f/l0, il1 = 1.0f/l1;
    const size_t row0 = (size_t)(browg + q0 + w*16 + g);
    #pragma unroll
    for (int nt=0; nt<16; ++nt){
        size_t o0 = row0*QDIM + hh*HD + nt*8 + colc;
        size_t o1 = o0 + 8*QDIM;
        uint32_t hr, lr;
        hr = splitpk(O[nt][0]*il0, O[nt][1]*il0, lr);
        *(uint32_t*)&aoh[o0] = hr; *(uint32_t*)&aol[o0] = lr;
        hr = splitpk(O[nt][2]*il1, O[nt][3]*il1, lr);
        *(uint32_t*)&aoh[o1] = hr; *(uint32_t*)&aol[o1] = lr;
    }
}

// ---------------------------------------------------------------------------
extern "C" void kernel_launch(void* const* d_in, const int* in_sizes, int n_in,
                              void* d_out, int out_size)
{
    const float* X  = (const float*)d_in[0];
    const float* Wq = (const float*)d_in[1];
    const float* Wk = (const float*)d_in[2];
    const float* Wv = (const float*)d_in[3];
    const float* Wo = (const float*)d_in[4];
    float* out = (float*)d_out;

    float *q,*kv;
    hlf *xh,*xl,*wqh,*wkh,*woh,*qh,*ql,*kh,*vh,*aoh,*aol;
    cudaGetSymbolAddress((void**)&q,  g_Q);
    cudaGetSymbolAddress((void**)&kv, g_KV);
    cudaGetSymbolAddress((void**)&xh, g_xh);  cudaGetSymbolAddress((void**)&xl, g_xl);
    cudaGetSymbolAddress((void**)&wqh,g_wqh);
    cudaGetSymbolAddress((void**)&wkh,g_wkh);
    cudaGetSymbolAddress((void**)&woh,g_woh);
    cudaGetSymbolAddress((void**)&qh, g_qh);  cudaGetSymbolAddress((void**)&ql, g_ql);
    cudaGetSymbolAddress((void**)&kh, g_kh);
    cudaGetSymbolAddress((void**)&vh, g_vh);
    cudaGetSymbolAddress((void**)&aoh,g_aoh); cudaGetSymbolAddress((void**)&aol,g_aol);

    const size_t KVW = (size_t)1024*HID;

    split_h<<<(int)(((size_t)MROWS*HID)/1024), 256>>>(X, xh, xl);
    conv_h <<<(int)(((size_t)QDIM*HID)/1024),  256>>>(Wq, wqh);
    conv_h <<<(int)(KVW/1024), 256>>>(Wk, wkh);
    conv_h <<<(int)(KVW/1024), 256>>>(Wv, wkh + KVW);
    conv_h <<<(int)(((size_t)HID*QDIM)/1024),  256>>>(Wo, woh);

    cudaFuncSetAttribute(gemm_f16s, cudaFuncAttributeMaxDynamicSharedMemorySize, GSMEM);
    gemm_f16s<<<dim3(QDIM/128, MROWS/128), 256, GSMEM>>>(xh, xl, wqh, q,  QDIM);
    gemm_f16s<<<dim3(KVLD/128, MROWS/128), 256, GSMEM>>>(xh, xl, wkh, kv, KVLD);

    const float SC = 0.08838834764831845f;
    rope_split <<<(MROWS*NH *64)/256, 256>>>(q,  qh, ql, NH,  QDIM, SC);
    rope_single<<<(MROWS*NKV*64)/256, 256>>>(kv, kh, NKV, KVLD);
    conv_v<<<(int)(((size_t)MROWS*KVDIM)/1024), 256>>>(kv + 1024, vh);

    cudaFuncSetAttribute(attn_mma, cudaFuncAttributeMaxDynamicSharedMemorySize, ASMEM);
    attn_mma<<<dim3(S_LEN/128, NH, 2), 256, ASMEM>>>(qh, ql, kh, vh, aoh, aol);

    gemm_f16s<<<dim3(QDIM/128, MROWS/128), 256, GSMEM>>>(aoh, aol, woh, out, QDIM);
}

// round 7
// speedup vs baseline: 3.9202x; 1.1540x over previous
#include <cuda_runtime.h>
#include <cuda_fp16.h>
#include <math.h>
#include <stdint.h>

#define S_LEN 2048
#define HID   4096
#define NH    32
#define NKV   8
#define HD    128
#define WIN   1024
#define QDIM  4096
#define KVLD  2048
#define KVDIM 1024
#define MROWS 4096

typedef __half hlf;

__device__ float g_Q  [(size_t)MROWS*QDIM];
__device__ float g_KV [(size_t)MROWS*KVLD];
__device__ hlf g_xh [(size_t)MROWS*HID],  g_xl [(size_t)MROWS*HID];
__device__ hlf g_wqh[(size_t)QDIM*HID];
__device__ hlf g_wkh[(size_t)KVLD*HID];
__device__ hlf g_woh[(size_t)HID*QDIM];
__device__ hlf g_qh [(size_t)MROWS*QDIM], g_ql [(size_t)MROWS*QDIM];
__device__ hlf g_kh [(size_t)MROWS*KVDIM];
__device__ hlf g_vh [(size_t)MROWS*KVDIM];
__device__ hlf g_aoh[(size_t)MROWS*QDIM], g_aol[(size_t)MROWS*QDIM];

// ---------------- PTX helpers ----------------
__device__ __forceinline__ uint32_t s2u(const void* p){
    uint32_t a;
    asm("{ .reg .u64 t; cvta.to.shared.u64 t,%1; cvt.u32.u64 %0,t; }":"=r"(a):"l"(p));
    return a;
}
#define CPA(dst,src) asm volatile( \
    "cp.async.cg.shared.global [%0],[%1],16;" :: "r"(dst),"l"(src) : "memory")
#define CPA_COMMIT() asm volatile("cp.async.commit_group;" ::: "memory")
#define CPA_WAIT0()  asm volatile("cp.async.wait_group 0;" ::: "memory")
#define CPA_WAIT1()  asm volatile("cp.async.wait_group 1;" ::: "memory")
#define CPA_WAIT2()  asm volatile("cp.async.wait_group 2;" ::: "memory")

#define LDSM4(r,addr) asm volatile( \
    "ldmatrix.sync.aligned.m8n8.x4.shared.b16 {%0,%1,%2,%3},[%4];" \
    : "=r"((r)[0]),"=r"((r)[1]),"=r"((r)[2]),"=r"((r)[3]) : "r"(addr))
#define LDSM4T(r,addr) asm volatile( \
    "ldmatrix.sync.aligned.m8n8.x4.trans.shared.b16 {%0,%1,%2,%3},[%4];" \
    : "=r"((r)[0]),"=r"((r)[1]),"=r"((r)[2]),"=r"((r)[3]) : "r"(addr))

#define MMA_F16(c,a,b) asm volatile( \
    "mma.sync.aligned.m16n8k16.row.col.f32.f16.f16.f32 " \
    "{%0,%1,%2,%3},{%4,%5,%6,%7},{%8,%9},{%0,%1,%2,%3};" \
    : "+f"((c)[0]),"+f"((c)[1]),"+f"((c)[2]),"+f"((c)[3]) \
    : "r"((a)[0]),"r"((a)[1]),"r"((a)[2]),"r"((a)[3]),"r"((b)[0]),"r"((b)[1]))

__device__ __forceinline__ uint32_t h2u(__half2 h){ return *reinterpret_cast<uint32_t*>(&h); }

__device__ __forceinline__ uint32_t splitpk(float a, float b, uint32_t &res){
    __half2 h = __floats2half2_rn(a, b);
    float2 f = __half22float2(h);
    res = h2u(__floats2half2_rn(a - f.x, b - f.y));
    return h2u(h);
}

// ---------------------------------------------------------------------------
// fp16 split GEMM: C[M,N] = A[M,K]·B[N,K]^T,  C = Ah·Bh + Al·Bh
// CTA tile 128x256, BK=32, 512 threads (16 warps: 4m x 4n), 4-stage cp.async.
// ---------------------------------------------------------------------------
#define GK      4096
#define NCHG    128
#define ROWB    80
#define STG_B   40960
#define OFF_AL  10240
#define OFF_BH  20480
#define GSMEM   (4*STG_B)   // 163840

static __device__ __forceinline__ void load_stage(
    uint32_t sb, int stage, int kc, int m0, int n0, int tid,
    const hlf* __restrict__ Ah, const hlf* __restrict__ Al,
    const hlf* __restrict__ Bh)
{
    uint32_t st = sb + stage*STG_B;
    {   // A hi+lo: 128 rows x 4 quads = 512
        int r = tid>>2, ch = tid&3;
        uint32_t so = (uint32_t)(r*ROWB + ch*16);
        size_t gA = (size_t)(m0+r)*GK + kc + ch*8;
        CPA(st+so,        Ah+gA);
        CPA(st+OFF_AL+so, Al+gA);
    }
    #pragma unroll
    for (int it=0; it<2; ++it){   // B: 256 rows x 4 quads = 1024
        int idx = tid + it*512;
        int r = idx>>2, ch = idx&3;
        uint32_t so = (uint32_t)(r*ROWB + ch*16);
        size_t gB = (size_t)(n0+r)*GK + kc + ch*8;
        CPA(st+OFF_BH+so, Bh+gB);
    }
    CPA_COMMIT();
}

__global__ void __launch_bounds__(512,1) gemm_f16s(
    const hlf* __restrict__ Ah, const hlf* __restrict__ Al,
    const hlf* __restrict__ Bh, float* __restrict__ C, int ldC)
{
    extern __shared__ __align__(128) char sm[];
    const uint32_t sb = s2u(sm);
    const int tid = threadIdx.x, wid = tid>>5, lane = tid&31;
    const int wm = wid&3, wn = wid>>2;       // 4 x 4 warps
    const int g = lane>>2, tg = lane&3;
    const int m0 = blockIdx.y*128, n0 = blockIdx.x*256;

    float acc[2][8][4];
    #pragma unroll
    for (int i=0;i<2;++i)
        #pragma unroll
        for (int j=0;j<8;++j){acc[i][j][0]=0;acc[i][j][1]=0;acc[i][j][2]=0;acc[i][j][3]=0;}

    load_stage(sb,0,0, m0,n0,tid,Ah,Al,Bh);
    load_stage(sb,1,32,m0,n0,tid,Ah,Al,Bh);
    load_stage(sb,2,64,m0,n0,tid,Ah,Al,Bh);

    const uint32_t a_row  = (uint32_t)(wm*32 + (lane&15));
    const uint32_t a_colb = (uint32_t)((lane>>4)*16);
    const uint32_t b_row  = (uint32_t)(wn*64 + (lane&7) + ((lane>>4)<<3));
    const uint32_t b_colb = (uint32_t)(((lane>>3)&1)*16);

    for (int c=0; c<NCHG; ++c){
        CPA_WAIT2();
        __syncthreads();
        if (c+3 < NCHG) load_stage(sb,(c+3)&3,(c+3)*32, m0,n0,tid,Ah,Al,Bh);
        else CPA_COMMIT();

        const uint32_t st = sb + (c&3)*STG_B;
        #pragma unroll
        for (int s=0; s<2; ++s){
            uint32_t ah[2][4], al[2][4];
            #pragma unroll
            for (int mt=0; mt<2; ++mt){
                uint32_t aa = st + (a_row + mt*16)*ROWB + s*32 + a_colb;
                LDSM4(ah[mt], aa);
                LDSM4(al[mt], aa + OFF_AL);
            }
            uint32_t bh[8][2];
            #pragma unroll
            for (int p=0; p<4; ++p){
                uint32_t ba = st + OFF_BH + (b_row + p*16)*ROWB + s*32 + b_colb;
                uint32_t r[4];
                LDSM4(r, ba);
                bh[2*p][0]=r[0]; bh[2*p][1]=r[1]; bh[2*p+1][0]=r[2]; bh[2*p+1][1]=r[3];
            }
            #pragma unroll
            for (int mt=0; mt<2; ++mt)
                #pragma unroll
                for (int nt=0; nt<8; ++nt){
                    MMA_F16(acc[mt][nt], ah[mt], bh[nt]);
                    MMA_F16(acc[mt][nt], al[mt], bh[nt]);
                }
        }
    }
    #pragma unroll
    for (int mt=0; mt<2; ++mt)
        #pragma unroll
        for (int nt=0; nt<8; ++nt){
            int row = m0 + wm*32 + mt*16 + g;
            int col = n0 + wn*64 + nt*8 + tg*2;
            float2 v0 = {acc[mt][nt][0], acc[mt][nt][1]};
            float2 v1 = {acc[mt][nt][2], acc[mt][nt][3]};
            *(float2*)&C[(size_t)row*ldC + col]     = v0;
            *(float2*)&C[(size_t)(row+8)*ldC + col] = v1;
        }
}

// ---------------- conversions (8 elems/thread) ----------------
__global__ void split_h(const float* __restrict__ in,
                        hlf* __restrict__ hi, hlf* __restrict__ lo)
{
    size_t i = ((size_t)blockIdx.x*blockDim.x + threadIdx.x)*8;
    #pragma unroll
    for (int u=0; u<2; ++u){
        float4 v = *(const float4*)(in+i+u*4);
        uint32_t r0, r1, h0, h1;
        h0 = splitpk(v.x, v.y, r0);
        h1 = splitpk(v.z, v.w, r1);
        *(uint32_t*)&hi[i+u*4]   = h0; *(uint32_t*)&hi[i+u*4+2] = h1;
        *(uint32_t*)&lo[i+u*4]   = r0; *(uint32_t*)&lo[i+u*4+2] = r1;
    }
}
__global__ void conv_h(const float* __restrict__ in, hlf* __restrict__ out)
{
    size_t i = ((size_t)blockIdx.x*blockDim.x + threadIdx.x)*8;
    #pragma unroll
    for (int u=0; u<2; ++u){
        float4 v = *(const float4*)(in+i+u*4);
        *(uint32_t*)&out[i+u*4]   = h2u(__floats2half2_rn(v.x, v.y));
        *(uint32_t*)&out[i+u*4+2] = h2u(__floats2half2_rn(v.z, v.w));
    }
}
__global__ void conv_v(const float* __restrict__ v, hlf* __restrict__ out)
{
    size_t idx = (size_t)blockIdx.x*blockDim.x + threadIdx.x;
    size_t r = idx >> 7;                // 128 quads per row
    int c = (int)(idx & 127) * 8;
    #pragma unroll
    for (int u=0; u<2; ++u){
        float4 x = *(const float4*)&v[r*KVLD + c + u*4];
        size_t o = r*KVDIM + c + u*4;
        *(uint32_t*)&out[o]   = h2u(__floats2half2_rn(x.x, x.y));
        *(uint32_t*)&out[o+2] = h2u(__floats2half2_rn(x.z, x.w));
    }
}

// ---------------- RoPE ----------------
__global__ void rope_split(const float* __restrict__ buf, hlf* __restrict__ oh,
                           hlf* __restrict__ ol, int nheads, int rstride, float scale)
{
    int idx = blockIdx.x*blockDim.x + threadIdx.x;
    int i = idx & 63, t = idx >> 6;
    int h = t % nheads, row = t / nheads;
    int s = row & (S_LEN-1);
    float inv = powf(10000.0f, -(float)i*(1.0f/64.0f));
    float sn, cs; sincosf((float)s*inv, &sn, &cs);
    const float* p = buf + (size_t)row*rstride + h*HD;
    float x1 = p[i], x2 = p[i+64];
    float y1 = (x1*cs - x2*sn)*scale;
    float y2 = (x2*cs + x1*sn)*scale;
    size_t o = (size_t)row*(nheads*HD) + h*HD + i;
    hlf h1 = __float2half_rn(y1), h2 = __float2half_rn(y2);
    oh[o]=h1;    ol[o]   =__float2half_rn(y1-__half2float(h1));
    oh[o+64]=h2; ol[o+64]=__float2half_rn(y2-__half2float(h2));
}
__global__ void rope_single(const float* __restrict__ buf, hlf* __restrict__ oh,
                            int nheads, int rstride)
{
    int idx = blockIdx.x*blockDim.x + threadIdx.x;
    int i = idx & 63, t = idx >> 6;
    int h = t % nheads, row = t / nheads;
    int s = row & (S_LEN-1);
    float inv = powf(10000.0f, -(float)i*(1.0f/64.0f));
    float sn, cs; sincosf((float)s*inv, &sn, &cs);
    const float* p = buf + (size_t)row*rstride + h*HD;
    float x1 = p[i], x2 = p[i+64];
    size_t o = (size_t)row*(nheads*HD) + h*HD + i;
    oh[o]    = __float2half_rn(x1*cs - x2*sn);
    oh[o+64] = __float2half_rn(x2*cs + x1*sn);
}

// ---------------------------------------------------------------------------
// fp16 HMMA flash attention (base-2 softmax domain, mask fast path)
// ---------------------------------------------------------------------------
#define AROWB 272
#define QSZ   34816
#define KVARR 17408
#define KVSTG 34816
#define ASMEM (2*QSZ + 2*KVSTG)   // 139264

static __device__ __forceinline__ void a_load_kv(
    uint32_t st, int kbase, int brow, int tid, int kvh,
    const hlf* __restrict__ kh, const hlf* __restrict__ vh)
{
    #pragma unroll
    for (int it=0; it<4; ++it){
        int idx = tid + it*256;
        int r = idx>>4, ch = idx&15;
        uint32_t so = (uint32_t)(r*AROWB + ch*16);
        size_t gsrc = (size_t)(brow + kbase + r)*KVDIM + kvh*HD + ch*8;
        CPA(st + so,         kh + gsrc);
        CPA(st + KVARR + so, vh + gsrc);
    }
    CPA_COMMIT();
}

__global__ void __launch_bounds__(256,1) attn_mma(
    const hlf* __restrict__ qh_, const hlf* __restrict__ ql_,
    const hlf* __restrict__ kh_, const hlf* __restrict__ vh_,
    hlf* __restrict__ aoh, hlf* __restrict__ aol)
{
    extern __shared__ __align__(128) char sm[];
    const uint32_t sb = s2u(sm);
    const uint32_t QH = sb, ST0 = sb + 2*QSZ;

    const int tid = threadIdx.x, w = tid>>5, lane = tid&31;
    const int qb = blockIdx.x, hh = blockIdx.y, b = blockIdx.z;
    const int q0 = qb*128, kvh = hh>>2;
    const int g = lane>>2, colc = (lane&3)*2;
    const int browg = b*S_LEN;

    #pragma unroll
    for (int it=0; it<8; ++it){
        int idx = tid + it*256;
        int r = idx>>4, ch = idx&15;
        uint32_t so = (uint32_t)(r*AROWB + ch*16);
        size_t gsrc = (size_t)(browg + q0 + r)*QDIM + hh*HD + ch*8;
        CPA(QH + so, qh_ + gsrc);
        CPA(QH + QSZ + so, ql_ + gsrc);
    }
    CPA_COMMIT();

    int lo = q0 - (WIN-1); if (lo < 0) lo = 0;
    const int kt0 = lo >> 6, ktend = 2*qb + 1;

    a_load_kv(ST0, kt0*64, browg, tid, kvh, kh_, vh_);

    uint32_t qfh[8][4], qfl[8][4];
    float O[16][4];
    #pragma unroll
    for (int t=0;t<16;++t){O[t][0]=0;O[t][1]=0;O[t][2]=0;O[t][3]=0;}
    float m0 = -1e30f, m1 = -1e30f, l0 = 0.f, l1 = 0.f;

    const uint32_t a_row  = (uint32_t)(w*16 + (lane&15));
    const uint32_t a_colb = (uint32_t)((lane>>4)*16);
    const uint32_t kb_row = (uint32_t)((lane&7) + ((lane>>4)<<3));
    const uint32_t kb_col = (uint32_t)(((lane>>3)&1)*16);
    const uint32_t vb_row = (uint32_t)((lane&7) + (lane&8));
    const uint32_t vb_col = (uint32_t)((lane>>4)*16);

    const int rmin_w = q0 + w*16;

    for (int kt = kt0; kt <= ktend; ++kt){
        const int s = (kt - kt0) & 1;
        const uint32_t ST = ST0 + (uint32_t)s*KVSTG;
        if (kt < ktend){
            a_load_kv(ST0 + (uint32_t)(s^1)*KVSTG, (kt+1)*64, browg, tid, kvh, kh_, vh_);
            CPA_WAIT1();
        } else {
            CPA_WAIT0();
        }
        __syncthreads();

        if (kt == kt0){
            #pragma unroll
            for (int kk=0; kk<8; ++kk){
                uint32_t aa = QH + a_row*AROWB + kk*32 + a_colb;
                LDSM4(qfh[kk], aa);
                LDSM4(qfl[kk], aa + QSZ);
            }
        }

        const int kbase = kt*64;
        if ((kbase <= rmin_w + 15) && (kbase + 63 > rmin_w - WIN)){
            // ---- S = Q K^T (2-term) ----
            float p[8][4];
            #pragma unroll
            for (int t=0;t<8;++t){p[t][0]=0;p[t][1]=0;p[t][2]=0;p[t][3]=0;}
            #pragma unroll
            for (int kk=0; kk<8; ++kk){
                #pragma unroll
                for (int np=0; np<4; ++np){
                    uint32_t ba = ST + (np*16 + kb_row)*AROWB + kk*32 + kb_col;
                    uint32_t kf[4];
                    LDSM4(kf, ba);
                    MMA_F16(p[2*np],   qfh[kk], kf);
                    MMA_F16(p[2*np+1], qfh[kk], kf+2);
                    MMA_F16(p[2*np],   qfl[kk], kf);
                    MMA_F16(p[2*np+1], qfl[kk], kf+2);
                }
            }

            // ---- mask (skipped for interior tiles) ----
            const int r0 = rmin_w + g, r1 = r0 + 8;
            const bool full = (kbase + 63 <= rmin_w) && (kbase >= rmin_w + 16 - WIN);
            if (!full){
                #pragma unroll
                for (int t=0; t<8; ++t){
                    #pragma unroll
                    for (int e=0; e<2; ++e){
                        int kj = kbase + t*8 + colc + e;
                        if (!((kj<=r0)&&(r0-kj<WIN))) p[t][e]   = -1e30f;
                        if (!((kj<=r1)&&(r1-kj<WIN))) p[t][2+e] = -1e30f;
                    }
                }
            }
            // ---- online softmax (base-2: log2e folded into Q scale) ----
            float rm0 = -1e30f, rm1 = -1e30f;
            #pragma unroll
            for (int t=0; t<8; ++t){
                rm0 = fmaxf(rm0, fmaxf(p[t][0], p[t][1]));
                rm1 = fmaxf(rm1, fmaxf(p[t][2], p[t][3]));
            }
            rm0 = fmaxf(rm0, __shfl_xor_sync(~0u, rm0, 1));
            rm0 = fmaxf(rm0, __shfl_xor_sync(~0u, rm0, 2));
            rm1 = fmaxf(rm1, __shfl_xor_sync(~0u, rm1, 1));
            rm1 = fmaxf(rm1, __shfl_xor_sync(~0u, rm1, 2));
            float mn0 = fmaxf(m0, rm0), mn1 = fmaxf(m1, rm1);
            float sc0 = exp2f(m0 - mn0), sc1 = exp2f(m1 - mn1);
            m0 = mn0; m1 = mn1;
            float rs0 = 0.f, rs1 = 0.f;
            #pragma unroll
            for (int t=0; t<8; ++t){
                p[t][0] = exp2f(p[t][0]-mn0); p[t][1] = exp2f(p[t][1]-mn0);
                p[t][2] = exp2f(p[t][2]-mn1); p[t][3] = exp2f(p[t][3]-mn1);
                rs0 += p[t][0] + p[t][1];
                rs1 += p[t][2] + p[t][3];
            }
            rs0 += __shfl_xor_sync(~0u, rs0, 1); rs0 += __shfl_xor_sync(~0u, rs0, 2);
            rs1 += __shfl_xor_sync(~0u, rs1, 1); rs1 += __shfl_xor_sync(~0u, rs1, 2);
            l0 = l0*sc0 + rs0; l1 = l1*sc1 + rs1;
            #pragma unroll
            for (int t=0; t<16; ++t){
                O[t][0]*=sc0; O[t][1]*=sc0; O[t][2]*=sc1; O[t][3]*=sc1;
            }

            // ---- O += P V (2-term) ----
            const uint32_t VB = ST + KVARR;
            #pragma unroll
            for (int kk=0; kk<4; ++kk){
                uint32_t pha[4], pla[4];
                pha[0] = splitpk(p[2*kk][0],   p[2*kk][1],   pla[0]);
                pha[1] = splitpk(p[2*kk][2],   p[2*kk][3],   pla[1]);
                pha[2] = splitpk(p[2*kk+1][0], p[2*kk+1][1], pla[2]);
                pha[3] = splitpk(p[2*kk+1][2], p[2*kk+1][3], pla[3]);
                #pragma unroll
                for (int vp=0; vp<8; ++vp){
                    uint32_t va = VB + (kk*16 + vb_row)*AROWB + vp*32 + vb_col;
                    uint32_t vf[4];
                    LDSM4T(vf, va);
                    MMA_F16(O[2*vp],   pha, vf);
                    MMA_F16(O[2*vp+1], pha, vf+2);
                    MMA_F16(O[2*vp],   pla, vf);
                    MMA_F16(O[2*vp+1], pla, vf+2);
                }
            }
        }
        __syncthreads();
    }

    float il0 = 1.0f/l0, il1 = 1.0f/l1;
    const size_t row0 = (size_t)(browg + q0 + w*16 + g);
    #pragma unroll
    for (int nt=0; nt<16; ++nt){
        size_t o0 = row0*QDIM + hh*HD + nt*8 + colc;
        size_t o1 = o0 + 8*QDIM;
        uint32_t hr, lr;
        hr = splitpk(O[nt][0]*il0, O[nt][1]*il0, lr);
        *(uint32_t*)&aoh[o0] = hr; *(uint32_t*)&aol[o0] = lr;
        hr = splitpk(O[nt][2]*il1, O[nt][3]*il1, lr);
        *(uint32_t*)&aoh[o1] = hr; *(uint32_t*)&aol[o1] = lr;
    }
}

// ---------------------------------------------------------------------------
extern "C" void kernel_launch(void* const* d_in, const int* in_sizes, int n_in,
                              void* d_out, int out_size)
{
    const float* X  = (const float*)d_in[0];
    const float* Wq = (const float*)d_in[1];
    const float* Wk = (const float*)d_in[2];
    const float* Wv = (const float*)d_in[3];
    const float* Wo = (const float*)d_in[4];
    float* out = (float*)d_out;

    float *q,*kv;
    hlf *xh,*xl,*wqh,*wkh,*woh,*qh,*ql,*kh,*vh,*aoh,*aol;
    cudaGetSymbolAddress((void**)&q,  g_Q);
    cudaGetSymbolAddress((void**)&kv, g_KV);
    cudaGetSymbolAddress((void**)&xh, g_xh);  cudaGetSymbolAddress((void**)&xl, g_xl);
    cudaGetSymbolAddress((void**)&wqh,g_wqh);
    cudaGetSymbolAddress((void**)&wkh,g_wkh);
    cudaGetSymbolAddress((void**)&woh,g_woh);
    cudaGetSymbolAddress((void**)&qh, g_qh);  cudaGetSymbolAddress((void**)&ql, g_ql);
    cudaGetSymbolAddress((void**)&kh, g_kh);
    cudaGetSymbolAddress((void**)&vh, g_vh);
    cudaGetSymbolAddress((void**)&aoh,g_aoh); cudaGetSymbolAddress((void**)&aol,g_aol);

    const size_t KVW = (size_t)1024*HID;

    split_h<<<(int)(((size_t)MROWS*HID)/2048), 256>>>(X, xh, xl);
    conv_h <<<(int)(((size_t)QDIM*HID)/2048),  256>>>(Wq, wqh);
    conv_h <<<(int)(KVW/2048), 256>>>(Wk, wkh);
    conv_h <<<(int)(KVW/2048), 256>>>(Wv, wkh + KVW);
    conv_h <<<(int)(((size_t)HID*QDIM)/2048),  256>>>(Wo, woh);

    cudaFuncSetAttribute(gemm_f16s, cudaFuncAttributeMaxDynamicSharedMemorySize, GSMEM);
    gemm_f16s<<<dim3(QDIM/256, MROWS/128), 512, GSMEM>>>(xh, xl, wqh, q,  QDIM);
    gemm_f16s<<<dim3(KVLD/256, MROWS/128), 512, GSMEM>>>(xh, xl, wkh, kv, KVLD);

    // scale * log2(e) folded into Q so softmax runs in base-2 domain
    const float SCL2 = 0.08838834764831845f * 1.4426950408889634f;
    rope_split <<<(MROWS*NH *64)/256, 256>>>(q,  qh, ql, NH,  QDIM, SCL2);
    rope_single<<<(MROWS*NKV*64)/256, 256>>>(kv, kh, NKV, KVLD);
    conv_v<<<(int)(((size_t)MROWS*KVDIM)/2048), 256>>>(kv + 1024, vh);

    cudaFuncSetAttribute(attn_mma, cudaFuncAttributeMaxDynamicSharedMemorySize, ASMEM);
    attn_mma<<<dim3(S_LEN/128, NH, 2), 256, ASMEM>>>(qh, ql, kh, vh, aoh, aol);

    gemm_f16s<<<dim3(QDIM/256, MROWS/128), 512, GSMEM>>>(aoh, aol, woh, out, QDIM);
}

// round 8
// speedup vs baseline: 4.4108x; 1.1251x over previous
#include <cuda_runtime.h>
#include <cuda_fp16.h>
#include <math.h>
#include <stdint.h>

#define S_LEN 2048
#define HID   4096
#define NH    32
#define NKV   8
#define HD    128
#define WIN   1024
#define QDIM  4096
#define QKVN  6144      // fused Q|K|V output width
#define KVDIM 1024
#define MROWS 4096

typedef __half hlf;

__device__ float g_QKV[(size_t)MROWS*QKVN];
__device__ hlf g_xh [(size_t)MROWS*HID],  g_xl [(size_t)MROWS*HID];
__device__ hlf g_wf [(size_t)QKVN*HID];                 // Wq|Wk|Wv combined
__device__ hlf g_woh[(size_t)HID*QDIM];
__device__ hlf g_qh [(size_t)MROWS*QDIM], g_ql [(size_t)MROWS*QDIM];
__device__ hlf g_kh [(size_t)MROWS*KVDIM];
__device__ hlf g_vh [(size_t)MROWS*KVDIM];
__device__ hlf g_aoh[(size_t)MROWS*QDIM];

// ---------------- PTX helpers ----------------
__device__ __forceinline__ uint32_t s2u(const void* p){
    uint32_t a;
    asm("{ .reg .u64 t; cvta.to.shared.u64 t,%1; cvt.u32.u64 %0,t; }":"=r"(a):"l"(p));
    return a;
}
#define CPA(dst,src) asm volatile( \
    "cp.async.cg.shared.global [%0],[%1],16;" :: "r"(dst),"l"(src) : "memory")
#define CPA_COMMIT() asm volatile("cp.async.commit_group;" ::: "memory")
#define CPA_WAIT0()  asm volatile("cp.async.wait_group 0;" ::: "memory")
#define CPA_WAIT1()  asm volatile("cp.async.wait_group 1;" ::: "memory")
#define CPA_WAIT2()  asm volatile("cp.async.wait_group 2;" ::: "memory")

#define LDSM4(r,addr) asm volatile( \
    "ldmatrix.sync.aligned.m8n8.x4.shared.b16 {%0,%1,%2,%3},[%4];" \
    : "=r"((r)[0]),"=r"((r)[1]),"=r"((r)[2]),"=r"((r)[3]) : "r"(addr))
#define LDSM4T(r,addr) asm volatile( \
    "ldmatrix.sync.aligned.m8n8.x4.trans.shared.b16 {%0,%1,%2,%3},[%4];" \
    : "=r"((r)[0]),"=r"((r)[1]),"=r"((r)[2]),"=r"((r)[3]) : "r"(addr))

#define MMA_F16(c,a,b) asm volatile( \
    "mma.sync.aligned.m16n8k16.row.col.f32.f16.f16.f32 " \
    "{%0,%1,%2,%3},{%4,%5,%6,%7},{%8,%9},{%0,%1,%2,%3};" \
    : "+f"((c)[0]),"+f"((c)[1]),"+f"((c)[2]),"+f"((c)[3]) \
    : "r"((a)[0]),"r"((a)[1]),"r"((a)[2]),"r"((a)[3]),"r"((b)[0]),"r"((b)[1]))

__device__ __forceinline__ uint32_t h2u(__half2 h){ return *reinterpret_cast<uint32_t*>(&h); }

__device__ __forceinline__ uint32_t splitpk(float a, float b, uint32_t &res){
    __half2 h = __floats2half2_rn(a, b);
    float2 f = __half22float2(h);
    res = h2u(__floats2half2_rn(a - f.x, b - f.y));
    return h2u(h);
}

// ---------------------------------------------------------------------------
// 2-term fp16 GEMM (A split): C = Ah·Bh + Al·Bh. CTA 128x256, BK=32, 512 thr.
// ---------------------------------------------------------------------------
#define GK      4096
#define NCHG    128
#define ROWB    80
#define STG_B   40960
#define OFF_AL  10240
#define OFF_BH  20480
#define GSMEM   (4*STG_B)   // 163840

static __device__ __forceinline__ void load_stage(
    uint32_t sb, int stage, int kc, int m0, int n0, int tid,
    const hlf* __restrict__ Ah, const hlf* __restrict__ Al,
    const hlf* __restrict__ Bh)
{
    uint32_t st = sb + stage*STG_B;
    {
        int r = tid>>2, ch = tid&3;
        uint32_t so = (uint32_t)(r*ROWB + ch*16);
        size_t gA = (size_t)(m0+r)*GK + kc + ch*8;
        CPA(st+so,        Ah+gA);
        CPA(st+OFF_AL+so, Al+gA);
    }
    #pragma unroll
    for (int it=0; it<2; ++it){
        int idx = tid + it*512;
        int r = idx>>2, ch = idx&3;
        uint32_t so = (uint32_t)(r*ROWB + ch*16);
        size_t gB = (size_t)(n0+r)*GK + kc + ch*8;
        CPA(st+OFF_BH+so, Bh+gB);
    }
    CPA_COMMIT();
}

__global__ void __launch_bounds__(512,1) gemm_f16s(
    const hlf* __restrict__ Ah, const hlf* __restrict__ Al,
    const hlf* __restrict__ Bh, float* __restrict__ C, int ldC)
{
    extern __shared__ __align__(128) char sm[];
    const uint32_t sb = s2u(sm);
    const int tid = threadIdx.x, wid = tid>>5, lane = tid&31;
    const int wm = wid&3, wn = wid>>2;
    const int g = lane>>2, tg = lane&3;
    const int m0 = blockIdx.y*128, n0 = blockIdx.x*256;

    float acc[2][8][4];
    #pragma unroll
    for (int i=0;i<2;++i)
        #pragma unroll
        for (int j=0;j<8;++j){acc[i][j][0]=0;acc[i][j][1]=0;acc[i][j][2]=0;acc[i][j][3]=0;}

    load_stage(sb,0,0, m0,n0,tid,Ah,Al,Bh);
    load_stage(sb,1,32,m0,n0,tid,Ah,Al,Bh);
    load_stage(sb,2,64,m0,n0,tid,Ah,Al,Bh);

    const uint32_t a_row  = (uint32_t)(wm*32 + (lane&15));
    const uint32_t a_colb = (uint32_t)((lane>>4)*16);
    const uint32_t b_row  = (uint32_t)(wn*64 + (lane&7) + ((lane>>4)<<3));
    const uint32_t b_colb = (uint32_t)(((lane>>3)&1)*16);

    for (int c=0; c<NCHG; ++c){
        CPA_WAIT2();
        __syncthreads();
        if (c+3 < NCHG) load_stage(sb,(c+3)&3,(c+3)*32, m0,n0,tid,Ah,Al,Bh);
        else CPA_COMMIT();

        const uint32_t st = sb + (c&3)*STG_B;
        #pragma unroll
        for (int s=0; s<2; ++s){
            uint32_t ah[2][4], al[2][4];
            #pragma unroll
            for (int mt=0; mt<2; ++mt){
                uint32_t aa = st + (a_row + mt*16)*ROWB + s*32 + a_colb;
                LDSM4(ah[mt], aa);
                LDSM4(al[mt], aa + OFF_AL);
            }
            uint32_t bh[8][2];
            #pragma unroll
            for (int p=0; p<4; ++p){
                uint32_t ba = st + OFF_BH + (b_row + p*16)*ROWB + s*32 + b_colb;
                uint32_t r[4];
                LDSM4(r, ba);
                bh[2*p][0]=r[0]; bh[2*p][1]=r[1]; bh[2*p+1][0]=r[2]; bh[2*p+1][1]=r[3];
            }
            #pragma unroll
            for (int mt=0; mt<2; ++mt)
                #pragma unroll
                for (int nt=0; nt<8; ++nt){
                    MMA_F16(acc[mt][nt], ah[mt], bh[nt]);
                    MMA_F16(acc[mt][nt], al[mt], bh[nt]);
                }
        }
    }
    #pragma unroll
    for (int mt=0; mt<2; ++mt)
        #pragma unroll
        for (int nt=0; nt<8; ++nt){
            int row = m0 + wm*32 + mt*16 + g;
            int col = n0 + wn*64 + nt*8 + tg*2;
            float2 v0 = {acc[mt][nt][0], acc[mt][nt][1]};
            float2 v1 = {acc[mt][nt][2], acc[mt][nt][3]};
            *(float2*)&C[(size_t)row*ldC + col]     = v0;
            *(float2*)&C[(size_t)(row+8)*ldC + col] = v1;
        }
}

// ---------------------------------------------------------------------------
// 1-term fp16 GEMM (A single): C = A·B^T. CTA 128x256, BK=32, 512 thr.
// ---------------------------------------------------------------------------
#define ST1_B  30720
#define OFF1_B 10240
#define GSMEM1 (4*ST1_B)   // 122880

static __device__ __forceinline__ void load_stage1(
    uint32_t sb, int stage, int kc, int m0, int n0, int tid,
    const hlf* __restrict__ A, const hlf* __restrict__ Bh)
{
    uint32_t st = sb + stage*ST1_B;
    {
        int r = tid>>2, ch = tid&3;
        uint32_t so = (uint32_t)(r*ROWB + ch*16);
        CPA(st+so, A + (size_t)(m0+r)*GK + kc + ch*8);
    }
    #pragma unroll
    for (int it=0; it<2; ++it){
        int idx = tid + it*512;
        int r = idx>>2, ch = idx&3;
        uint32_t so = (uint32_t)(r*ROWB + ch*16);
        CPA(st+OFF1_B+so, Bh + (size_t)(n0+r)*GK + kc + ch*8);
    }
    CPA_COMMIT();
}

__global__ void __launch_bounds__(512,1) gemm_f16(
    const hlf* __restrict__ A, const hlf* __restrict__ Bh,
    float* __restrict__ C, int ldC)
{
    extern __shared__ __align__(128) char sm[];
    const uint32_t sb = s2u(sm);
    const int tid = threadIdx.x, wid = tid>>5, lane = tid&31;
    const int wm = wid&3, wn = wid>>2;
    const int g = lane>>2, tg = lane&3;
    const int m0 = blockIdx.y*128, n0 = blockIdx.x*256;

    float acc[2][8][4];
    #pragma unroll
    for (int i=0;i<2;++i)
        #pragma unroll
        for (int j=0;j<8;++j){acc[i][j][0]=0;acc[i][j][1]=0;acc[i][j][2]=0;acc[i][j][3]=0;}

    load_stage1(sb,0,0, m0,n0,tid,A,Bh);
    load_stage1(sb,1,32,m0,n0,tid,A,Bh);
    load_stage1(sb,2,64,m0,n0,tid,A,Bh);

    const uint32_t a_row  = (uint32_t)(wm*32 + (lane&15));
    const uint32_t a_colb = (uint32_t)((lane>>4)*16);
    const uint32_t b_row  = (uint32_t)(wn*64 + (lane&7) + ((lane>>4)<<3));
    const uint32_t b_colb = (uint32_t)(((lane>>3)&1)*16);

    for (int c=0; c<NCHG; ++c){
        CPA_WAIT2();
        __syncthreads();
        if (c+3 < NCHG) load_stage1(sb,(c+3)&3,(c+3)*32, m0,n0,tid,A,Bh);
        else CPA_COMMIT();

        const uint32_t st = sb + (c&3)*ST1_B;
        #pragma unroll
        for (int s=0; s<2; ++s){
            uint32_t ah[2][4];
            #pragma unroll
            for (int mt=0; mt<2; ++mt)
                LDSM4(ah[mt], st + (a_row + mt*16)*ROWB + s*32 + a_colb);
            uint32_t bh[8][2];
            #pragma unroll
            for (int p=0; p<4; ++p){
                uint32_t ba = st + OFF1_B + (b_row + p*16)*ROWB + s*32 + b_colb;
                uint32_t r[4];
                LDSM4(r, ba);
                bh[2*p][0]=r[0]; bh[2*p][1]=r[1]; bh[2*p+1][0]=r[2]; bh[2*p+1][1]=r[3];
            }
            #pragma unroll
            for (int mt=0; mt<2; ++mt)
                #pragma unroll
                for (int nt=0; nt<8; ++nt)
                    MMA_F16(acc[mt][nt], ah[mt], bh[nt]);
        }
    }
    #pragma unroll
    for (int mt=0; mt<2; ++mt)
        #pragma unroll
        for (int nt=0; nt<8; ++nt){
            int row = m0 + wm*32 + mt*16 + g;
            int col = n0 + wn*64 + nt*8 + tg*2;
            float2 v0 = {acc[mt][nt][0], acc[mt][nt][1]};
            float2 v1 = {acc[mt][nt][2], acc[mt][nt][3]};
            *(float2*)&C[(size_t)row*ldC + col]     = v0;
            *(float2*)&C[(size_t)(row+8)*ldC + col] = v1;
        }
}

// ---------------- conversions ----------------
__global__ void split_h(const float* __restrict__ in,
                        hlf* __restrict__ hi, hlf* __restrict__ lo)
{
    size_t i = ((size_t)blockIdx.x*blockDim.x + threadIdx.x)*8;
    #pragma unroll
    for (int u=0; u<2; ++u){
        float4 v = *(const float4*)(in+i+u*4);
        uint32_t r0, r1, h0, h1;
        h0 = splitpk(v.x, v.y, r0);
        h1 = splitpk(v.z, v.w, r1);
        *(uint32_t*)&hi[i+u*4]   = h0; *(uint32_t*)&hi[i+u*4+2] = h1;
        *(uint32_t*)&lo[i+u*4]   = r0; *(uint32_t*)&lo[i+u*4+2] = r1;
    }
}
__global__ void conv_h(const float* __restrict__ in, hlf* __restrict__ out)
{
    size_t i = ((size_t)blockIdx.x*blockDim.x + threadIdx.x)*8;
    #pragma unroll
    for (int u=0; u<2; ++u){
        float4 v = *(const float4*)(in+i+u*4);
        *(uint32_t*)&out[i+u*4]   = h2u(__floats2half2_rn(v.x, v.y));
        *(uint32_t*)&out[i+u*4+2] = h2u(__floats2half2_rn(v.z, v.w));
    }
}
// strided fp32 -> fp16 (V slab of fused QKV)
__global__ void conv_v(const float* __restrict__ v, hlf* __restrict__ out)
{
    size_t idx = (size_t)blockIdx.x*blockDim.x + threadIdx.x;
    size_t r = idx >> 7;
    int c = (int)(idx & 127) * 8;
    #pragma unroll
    for (int u=0; u<2; ++u){
        float4 x = *(const float4*)&v[r*QKVN + c + u*4];
        size_t o = r*KVDIM + c + u*4;
        *(uint32_t*)&out[o]   = h2u(__floats2half2_rn(x.x, x.y));
        *(uint32_t*)&out[o+2] = h2u(__floats2half2_rn(x.z, x.w));
    }
}

// ---------------- RoPE ----------------
__global__ void rope_split(const float* __restrict__ buf, hlf* __restrict__ oh,
                           hlf* __restrict__ ol, int nheads, int rstride, float scale)
{
    int idx = blockIdx.x*blockDim.x + threadIdx.x;
    int i = idx & 63, t = idx >> 6;
    int h = t % nheads, row = t / nheads;
    int s = row & (S_LEN-1);
    float inv = powf(10000.0f, -(float)i*(1.0f/64.0f));
    float sn, cs; sincosf((float)s*inv, &sn, &cs);
    const float* p = buf + (size_t)row*rstride + h*HD;
    float x1 = p[i], x2 = p[i+64];
    float y1 = (x1*cs - x2*sn)*scale;
    float y2 = (x2*cs + x1*sn)*scale;
    size_t o = (size_t)row*(nheads*HD) + h*HD + i;
    hlf h1 = __float2half_rn(y1), h2 = __float2half_rn(y2);
    oh[o]=h1;    ol[o]   =__float2half_rn(y1-__half2float(h1));
    oh[o+64]=h2; ol[o+64]=__float2half_rn(y2-__half2float(h2));
}
__global__ void rope_single(const float* __restrict__ buf, hlf* __restrict__ oh,
                            int nheads, int rstride)
{
    int idx = blockIdx.x*blockDim.x + threadIdx.x;
    int i = idx & 63, t = idx >> 6;
    int h = t % nheads, row = t / nheads;
    int s = row & (S_LEN-1);
    float inv = powf(10000.0f, -(float)i*(1.0f/64.0f));
    float sn, cs; sincosf((float)s*inv, &sn, &cs);
    const float* p = buf + (size_t)row*rstride + h*HD;
    float x1 = p[i], x2 = p[i+64];
    size_t o = (size_t)row*(nheads*HD) + h*HD + i;
    oh[o]    = __float2half_rn(x1*cs - x2*sn);
    oh[o+64] = __float2half_rn(x2*cs + x1*sn);
}

// ---------------------------------------------------------------------------
// fp16 HMMA flash attention (base-2 softmax, mask fast path, fp16 output)
// ---------------------------------------------------------------------------
#define AROWB 272
#define QSZ   34816
#define KVARR 17408
#define KVSTG 34816
#define ASMEM (2*QSZ + 2*KVSTG)   // 139264

static __device__ __forceinline__ void a_load_kv(
    uint32_t st, int kbase, int brow, int tid, int kvh,
    const hlf* __restrict__ kh, const hlf* __restrict__ vh)
{
    #pragma unroll
    for (int it=0; it<4; ++it){
        int idx = tid + it*256;
        int r = idx>>4, ch = idx&15;
        uint32_t so = (uint32_t)(r*AROWB + ch*16);
        size_t gsrc = (size_t)(brow + kbase + r)*KVDIM + kvh*HD + ch*8;
        CPA(st + so,         kh + gsrc);
        CPA(st + KVARR + so, vh + gsrc);
    }
    CPA_COMMIT();
}

__global__ void __launch_bounds__(256,1) attn_mma(
    const hlf* __restrict__ qh_, const hlf* __restrict__ ql_,
    const hlf* __restrict__ kh_, const hlf* __restrict__ vh_,
    hlf* __restrict__ aoh)
{
    extern __shared__ __align__(128) char sm[];
    const uint32_t sb = s2u(sm);
    const uint32_t QH = sb, ST0 = sb + 2*QSZ;

    const int tid = threadIdx.x, w = tid>>5, lane = tid&31;
    const int qb = blockIdx.x, hh = blockIdx.y, b = blockIdx.z;
    const int q0 = qb*128, kvh = hh>>2;
    const int g = lane>>2, colc = (lane&3)*2;
    const int browg = b*S_LEN;

    #pragma unroll
    for (int it=0; it<8; ++it){
        int idx = tid + it*256;
        int r = idx>>4, ch = idx&15;
        uint32_t so = (uint32_t)(r*AROWB + ch*16);
        size_t gsrc = (size_t)(browg + q0 + r)*QDIM + hh*HD + ch*8;
        CPA(QH + so, qh_ + gsrc);
        CPA(QH + QSZ + so, ql_ + gsrc);
    }
    CPA_COMMIT();

    int lo = q0 - (WIN-1); if (lo < 0) lo = 0;
    const int kt0 = lo >> 6, ktend = 2*qb + 1;

    a_load_kv(ST0, kt0*64, browg, tid, kvh, kh_, vh_);

    uint32_t qfh[8][4], qfl[8][4];
    float O[16][4];
    #pragma unroll
    for (int t=0;t<16;++t){O[t][0]=0;O[t][1]=0;O[t][2]=0;O[t][3]=0;}
    float m0 = -1e30f, m1 = -1e30f, l0 = 0.f, l1 = 0.f;

    const uint32_t a_row  = (uint32_t)(w*16 + (lane&15));
    const uint32_t a_colb = (uint32_t)((lane>>4)*16);
    const uint32_t kb_row = (uint32_t)((lane&7) + ((lane>>4)<<3));
    const uint32_t kb_col = (uint32_t)(((lane>>3)&1)*16);
    const uint32_t vb_row = (uint32_t)((lane&7) + (lane&8));
    const uint32_t vb_col = (uint32_t)((lane>>4)*16);

    const int rmin_w = q0 + w*16;

    for (int kt = kt0; kt <= ktend; ++kt){
        const int s = (kt - kt0) & 1;
        const uint32_t ST = ST0 + (uint32_t)s*KVSTG;
        if (kt < ktend){
            a_load_kv(ST0 + (uint32_t)(s^1)*KVSTG, (kt+1)*64, browg, tid, kvh, kh_, vh_);
            CPA_WAIT1();
        } else {
            CPA_WAIT0();
        }
        __syncthreads();

        if (kt == kt0){
            #pragma unroll
            for (int kk=0; kk<8; ++kk){
                uint32_t aa = QH + a_row*AROWB + kk*32 + a_colb;
                LDSM4(qfh[kk], aa);
                LDSM4(qfl[kk], aa + QSZ);
            }
        }

        const int kbase = kt*64;
        if ((kbase <= rmin_w + 15) && (kbase + 63 > rmin_w - WIN)){
            float p[8][4];
            #pragma unroll
            for (int t=0;t<8;++t){p[t][0]=0;p[t][1]=0;p[t][2]=0;p[t][3]=0;}
            #pragma unroll
            for (int kk=0; kk<8; ++kk){
                #pragma unroll
                for (int np=0; np<4; ++np){
                    uint32_t ba = ST + (np*16 + kb_row)*AROWB + kk*32 + kb_col;
                    uint32_t kf[4];
                    LDSM4(kf, ba);
                    MMA_F16(p[2*np],   qfh[kk], kf);
                    MMA_F16(p[2*np+1], qfh[kk], kf+2);
                    MMA_F16(p[2*np],   qfl[kk], kf);
                    MMA_F16(p[2*np+1], qfl[kk], kf+2);
                }
            }

            const int r0 = rmin_w + g, r1 = r0 + 8;
            const bool full = (kbase + 63 <= rmin_w) && (kbase >= rmin_w + 16 - WIN);
            if (!full){
                #pragma unroll
                for (int t=0; t<8; ++t){
                    #pragma unroll
                    for (int e=0; e<2; ++e){
                        int kj = kbase + t*8 + colc + e;
                        if (!((kj<=r0)&&(r0-kj<WIN))) p[t][e]   = -1e30f;
                        if (!((kj<=r1)&&(r1-kj<WIN))) p[t][2+e] = -1e30f;
                    }
                }
            }
            float rm0 = -1e30f, rm1 = -1e30f;
            #pragma unroll
            for (int t=0; t<8; ++t){
                rm0 = fmaxf(rm0, fmaxf(p[t][0], p[t][1]));
                rm1 = fmaxf(rm1, fmaxf(p[t][2], p[t][3]));
            }
            rm0 = fmaxf(rm0, __shfl_xor_sync(~0u, rm0, 1));
            rm0 = fmaxf(rm0, __shfl_xor_sync(~0u, rm0, 2));
            rm1 = fmaxf(rm1, __shfl_xor_sync(~0u, rm1, 1));
            rm1 = fmaxf(rm1, __shfl_xor_sync(~0u, rm1, 2));
            float mn0 = fmaxf(m0, rm0), mn1 = fmaxf(m1, rm1);
            float sc0 = exp2f(m0 - mn0), sc1 = exp2f(m1 - mn1);
            m0 = mn0; m1 = mn1;
            float rs0 = 0.f, rs1 = 0.f;
            #pragma unroll
            for (int t=0; t<8; ++t){
                p[t][0] = exp2f(p[t][0]-mn0); p[t][1] = exp2f(p[t][1]-mn0);
                p[t][2] = exp2f(p[t][2]-mn1); p[t][3] = exp2f(p[t][3]-mn1);
                rs0 += p[t][0] + p[t][1];
                rs1 += p[t][2] + p[t][3];
            }
            rs0 += __shfl_xor_sync(~0u, rs0, 1); rs0 += __shfl_xor_sync(~0u, rs0, 2);
            rs1 += __shfl_xor_sync(~0u, rs1, 1); rs1 += __shfl_xor_sync(~0u, rs1, 2);
            l0 = l0*sc0 + rs0; l1 = l1*sc1 + rs1;
            #pragma unroll
            for (int t=0; t<16; ++t){
                O[t][0]*=sc0; O[t][1]*=sc0; O[t][2]*=sc1; O[t][3]*=sc1;
            }

            const uint32_t VB = ST + KVARR;
            #pragma unroll
            for (int kk=0; kk<4; ++kk){
                uint32_t pha[4], pla[4];
                pha[0] = splitpk(p[2*kk][0],   p[2*kk][1],   pla[0]);
                pha[1] = splitpk(p[2*kk][2],   p[2*kk][3],   pla[1]);
                pha[2] = splitpk(p[2*kk+1][0], p[2*kk+1][1], pla[2]);
                pha[3] = splitpk(p[2*kk+1][2], p[2*kk+1][3], pla[3]);
                #pragma unroll
                for (int vp=0; vp<8; ++vp){
                    uint32_t va = VB + (kk*16 + vb_row)*AROWB + vp*32 + vb_col;
                    uint32_t vf[4];
                    LDSM4T(vf, va);
                    MMA_F16(O[2*vp],   pha, vf);
                    MMA_F16(O[2*vp+1], pha, vf+2);
                    MMA_F16(O[2*vp],   pla, vf);
                    MMA_F16(O[2*vp+1], pla, vf+2);
                }
            }
        }
        __syncthreads();
    }

    // epilogue: normalize, single fp16 write
    float il0 = 1.0f/l0, il1 = 1.0f/l1;
    const size_t row0 = (size_t)(browg + q0 + w*16 + g);
    #pragma unroll
    for (int nt=0; nt<16; ++nt){
        size_t o0 = row0*QDIM + hh*HD + nt*8 + colc;
        size_t o1 = o0 + 8*QDIM;
        *(uint32_t*)&aoh[o0] = h2u(__floats2half2_rn(O[nt][0]*il0, O[nt][1]*il0));
        *(uint32_t*)&aoh[o1] = h2u(__floats2half2_rn(O[nt][2]*il1, O[nt][3]*il1));
    }
}

// ---------------------------------------------------------------------------
extern "C" void kernel_launch(void* const* d_in, const int* in_sizes, int n_in,
                              void* d_out, int out_size)
{
    const float* X  = (const float*)d_in[0];
    const float* Wq = (const float*)d_in[1];
    const float* Wk = (const float*)d_in[2];
    const float* Wv = (const float*)d_in[3];
    const float* Wo = (const float*)d_in[4];
    float* out = (float*)d_out;

    float *qkv;
    hlf *xh,*xl,*wf,*woh,*qh,*ql,*kh,*vh,*aoh;
    cudaGetSymbolAddress((void**)&qkv, g_QKV);
    cudaGetSymbolAddress((void**)&xh, g_xh);  cudaGetSymbolAddress((void**)&xl, g_xl);
    cudaGetSymbolAddress((void**)&wf, g_wf);
    cudaGetSymbolAddress((void**)&woh,g_woh);
    cudaGetSymbolAddress((void**)&qh, g_qh);  cudaGetSymbolAddress((void**)&ql, g_ql);
    cudaGetSymbolAddress((void**)&kh, g_kh);
    cudaGetSymbolAddress((void**)&vh, g_vh);
    cudaGetSymbolAddress((void**)&aoh,g_aoh);

    const size_t KVW = (size_t)1024*HID;        // 4,194,304
    const size_t QW  = (size_t)QDIM*HID;        // 16,777,216

    split_h<<<(int)((MROWS*(size_t)HID)/2048), 256>>>(X, xh, xl);
    conv_h <<<(int)(QW/2048),  256>>>(Wq, wf);
    conv_h <<<(int)(KVW/2048), 256>>>(Wk, wf + QW);
    conv_h <<<(int)(KVW/2048), 256>>>(Wv, wf + QW + KVW);
    conv_h <<<(int)(QW/2048),  256>>>(Wo, woh);

    // fused Q|K|V projection: one GEMM, N=6144
    cudaFuncSetAttribute(gemm_f16s, cudaFuncAttributeMaxDynamicSharedMemorySize, GSMEM);
    gemm_f16s<<<dim3(QKVN/256, MROWS/128), 512, GSMEM>>>(xh, xl, wf, qkv, QKVN);

    const float SCL2 = 0.08838834764831845f * 1.4426950408889634f;
    rope_split <<<(MROWS*NH *64)/256, 256>>>(qkv,        qh, ql, NH,  QKVN, SCL2);
    rope_single<<<(MROWS*NKV*64)/256, 256>>>(qkv + 4096, kh,     NKV, QKVN);
    conv_v<<<(int)(((size_t)MROWS*KVDIM)/2048), 256>>>(qkv + 5120, vh);

    cudaFuncSetAttribute(attn_mma, cudaFuncAttributeMaxDynamicSharedMemorySize, ASMEM);
    attn_mma<<<dim3(S_LEN/128, NH, 2), 256, ASMEM>>>(qh, ql, kh, vh, aoh);

    // O projection: 1-term (ao single fp16)
    cudaFuncSetAttribute(gemm_f16, cudaFuncAttributeMaxDynamicSharedMemorySize, GSMEM1);
    gemm_f16<<<dim3(QDIM/256, MROWS/128), 512, GSMEM1>>>(aoh, woh, out, QDIM);
}

// round 9
// speedup vs baseline: 4.8385x; 1.0970x over previous
#include <cuda_runtime.h>
#include <cuda_fp16.h>
#include <math.h>
#include <stdint.h>

#define S_LEN 2048
#define HID   4096
#define NH    32
#define NKV   8
#define HD    128
#define WIN   1024
#define QDIM  4096
#define KVLD  2048
#define KVDIM 1024
#define MROWS 4096

typedef __half hlf;

__device__ float g_Qp [(size_t)MROWS*QDIM];
__device__ float g_KVp[(size_t)MROWS*KVLD];
__device__ hlf g_xh [(size_t)MROWS*HID],  g_xl [(size_t)MROWS*HID];
__device__ hlf g_wqh[(size_t)QDIM*HID];
__device__ hlf g_wkv[(size_t)KVLD*HID];
__device__ hlf g_woh[(size_t)HID*QDIM];
__device__ hlf g_qh [(size_t)MROWS*QDIM], g_ql [(size_t)MROWS*QDIM];
__device__ hlf g_kh [(size_t)MROWS*KVDIM];
__device__ hlf g_vh [(size_t)MROWS*KVDIM];
__device__ hlf g_aoh[(size_t)MROWS*QDIM];

// ---------------- PTX helpers ----------------
__device__ __forceinline__ uint32_t s2u(const void* p){
    uint32_t a;
    asm("{ .reg .u64 t; cvta.to.shared.u64 t,%1; cvt.u32.u64 %0,t; }":"=r"(a):"l"(p));
    return a;
}
#define CPA(dst,src) asm volatile( \
    "cp.async.cg.shared.global [%0],[%1],16;" :: "r"(dst),"l"(src) : "memory")
#define CPA_COMMIT() asm volatile("cp.async.commit_group;" ::: "memory")
#define CPA_WAIT0()  asm volatile("cp.async.wait_group 0;" ::: "memory")
#define CPA_WAIT1()  asm volatile("cp.async.wait_group 1;" ::: "memory")
#define CPA_WAIT2()  asm volatile("cp.async.wait_group 2;" ::: "memory")

#define LDSM4(r,addr) asm volatile( \
    "ldmatrix.sync.aligned.m8n8.x4.shared.b16 {%0,%1,%2,%3},[%4];" \
    : "=r"((r)[0]),"=r"((r)[1]),"=r"((r)[2]),"=r"((r)[3]) : "r"(addr))
#define LDSM4T(r,addr) asm volatile( \
    "ldmatrix.sync.aligned.m8n8.x4.trans.shared.b16 {%0,%1,%2,%3},[%4];" \
    : "=r"((r)[0]),"=r"((r)[1]),"=r"((r)[2]),"=r"((r)[3]) : "r"(addr))

#define MMA_F16(c,a,b) asm volatile( \
    "mma.sync.aligned.m16n8k16.row.col.f32.f16.f16.f32 " \
    "{%0,%1,%2,%3},{%4,%5,%6,%7},{%8,%9},{%0,%1,%2,%3};" \
    : "+f"((c)[0]),"+f"((c)[1]),"+f"((c)[2]),"+f"((c)[3]) \
    : "r"((a)[0]),"r"((a)[1]),"r"((a)[2]),"r"((a)[3]),"r"((b)[0]),"r"((b)[1]))

__device__ __forceinline__ uint32_t h2u(__half2 h){ return *reinterpret_cast<uint32_t*>(&h); }

__device__ __forceinline__ uint32_t splitpk(float a, float b, uint32_t &res){
    __half2 h = __floats2half2_rn(a, b);
    float2 f = __half22float2(h);
    res = h2u(__floats2half2_rn(a - f.x, b - f.y));
    return h2u(h);
}

// ---------------------------------------------------------------------------
// 2-term fp16 GEMM (A split): C = Ah·Bh + Al·Bh. CTA 128x256, BK=32, 512 thr.
// ---------------------------------------------------------------------------
#define GK      4096
#define NCHG    128
#define ROWB    80
#define STG_B   40960
#define OFF_AL  10240
#define OFF_BH  20480
#define GSMEM   (4*STG_B)   // 163840

static __device__ __forceinline__ void load_stage(
    uint32_t sb, int stage, int kc, int m0, int n0, int tid,
    const hlf* __restrict__ Ah, const hlf* __restrict__ Al,
    const hlf* __restrict__ Bh)
{
    uint32_t st = sb + stage*STG_B;
    {
        int r = tid>>2, ch = tid&3;
        uint32_t so = (uint32_t)(r*ROWB + ch*16);
        size_t gA = (size_t)(m0+r)*GK + kc + ch*8;
        CPA(st+so,        Ah+gA);
        CPA(st+OFF_AL+so, Al+gA);
    }
    #pragma unroll
    for (int it=0; it<2; ++it){
        int idx = tid + it*512;
        int r = idx>>2, ch = idx&3;
        uint32_t so = (uint32_t)(r*ROWB + ch*16);
        size_t gB = (size_t)(n0+r)*GK + kc + ch*8;
        CPA(st+OFF_BH+so, Bh+gB);
    }
    CPA_COMMIT();
}

__global__ void __launch_bounds__(512,1) gemm_f16s(
    const hlf* __restrict__ Ah, const hlf* __restrict__ Al,
    const hlf* __restrict__ Bh, float* __restrict__ C, int ldC)
{
    extern __shared__ __align__(128) char sm[];
    const uint32_t sb = s2u(sm);
    const int tid = threadIdx.x, wid = tid>>5, lane = tid&31;
    const int wm = wid&3, wn = wid>>2;
    const int g = lane>>2, tg = lane&3;
    const int m0 = blockIdx.y*128, n0 = blockIdx.x*256;

    float acc[2][8][4];
    #pragma unroll
    for (int i=0;i<2;++i)
        #pragma unroll
        for (int j=0;j<8;++j){acc[i][j][0]=0;acc[i][j][1]=0;acc[i][j][2]=0;acc[i][j][3]=0;}

    load_stage(sb,0,0, m0,n0,tid,Ah,Al,Bh);
    load_stage(sb,1,32,m0,n0,tid,Ah,Al,Bh);
    load_stage(sb,2,64,m0,n0,tid,Ah,Al,Bh);

    const uint32_t a_row  = (uint32_t)(wm*32 + (lane&15));
    const uint32_t a_colb = (uint32_t)((lane>>4)*16);
    const uint32_t b_row  = (uint32_t)(wn*64 + (lane&7) + ((lane>>4)<<3));
    const uint32_t b_colb = (uint32_t)(((lane>>3)&1)*16);

    for (int c=0; c<NCHG; ++c){
        CPA_WAIT2();
        __syncthreads();
        if (c+3 < NCHG) load_stage(sb,(c+3)&3,(c+3)*32, m0,n0,tid,Ah,Al,Bh);
        else CPA_COMMIT();

        const uint32_t st = sb + (c&3)*STG_B;
        #pragma unroll
        for (int s=0; s<2; ++s){
            uint32_t ah[2][4], al[2][4];
            #pragma unroll
            for (int mt=0; mt<2; ++mt){
                uint32_t aa = st + (a_row + mt*16)*ROWB + s*32 + a_colb;
                LDSM4(ah[mt], aa);
                LDSM4(al[mt], aa + OFF_AL);
            }
            uint32_t bh[8][2];
            #pragma unroll
            for (int p=0; p<4; ++p){
                uint32_t ba = st + OFF_BH + (b_row + p*16)*ROWB + s*32 + b_colb;
                uint32_t r[4];
                LDSM4(r, ba);
                bh[2*p][0]=r[0]; bh[2*p][1]=r[1]; bh[2*p+1][0]=r[2]; bh[2*p+1][1]=r[3];
            }
            #pragma unroll
            for (int mt=0; mt<2; ++mt)
                #pragma unroll
                for (int nt=0; nt<8; ++nt){
                    MMA_F16(acc[mt][nt], ah[mt], bh[nt]);
                    MMA_F16(acc[mt][nt], al[mt], bh[nt]);
                }
        }
    }
    #pragma unroll
    for (int mt=0; mt<2; ++mt)
        #pragma unroll
        for (int nt=0; nt<8; ++nt){
            int row = m0 + wm*32 + mt*16 + g;
            int col = n0 + wn*64 + nt*8 + tg*2;
            float2 v0 = {acc[mt][nt][0], acc[mt][nt][1]};
            float2 v1 = {acc[mt][nt][2], acc[mt][nt][3]};
            *(float2*)&C[(size_t)row*ldC + col]     = v0;
            *(float2*)&C[(size_t)(row+8)*ldC + col] = v1;
        }
}

// ---------------------------------------------------------------------------
// 1-term fp16 GEMM: C = A·B^T. CTA 128x256, BK=32, 512 thr.
// ---------------------------------------------------------------------------
#define ST1_B  30720
#define OFF1_B 10240
#define GSMEM1 (4*ST1_B)   // 122880

static __device__ __forceinline__ void load_stage1(
    uint32_t sb, int stage, int kc, int m0, int n0, int tid,
    const hlf* __restrict__ A, const hlf* __restrict__ Bh)
{
    uint32_t st = sb + stage*ST1_B;
    {
        int r = tid>>2, ch = tid&3;
        uint32_t so = (uint32_t)(r*ROWB + ch*16);
        CPA(st+so, A + (size_t)(m0+r)*GK + kc + ch*8);
    }
    #pragma unroll
    for (int it=0; it<2; ++it){
        int idx = tid + it*512;
        int r = idx>>2, ch = idx&3;
        uint32_t so = (uint32_t)(r*ROWB + ch*16);
        CPA(st+OFF1_B+so, Bh + (size_t)(n0+r)*GK + kc + ch*8);
    }
    CPA_COMMIT();
}

__global__ void __launch_bounds__(512,1) gemm_f16(
    const hlf* __restrict__ A, const hlf* __restrict__ Bh,
    float* __restrict__ C, int ldC)
{
    extern __shared__ __align__(128) char sm[];
    const uint32_t sb = s2u(sm);
    const int tid = threadIdx.x, wid = tid>>5, lane = tid&31;
    const int wm = wid&3, wn = wid>>2;
    const int g = lane>>2, tg = lane&3;
    const int m0 = blockIdx.y*128, n0 = blockIdx.x*256;

    float acc[2][8][4];
    #pragma unroll
    for (int i=0;i<2;++i)
        #pragma unroll
        for (int j=0;j<8;++j){acc[i][j][0]=0;acc[i][j][1]=0;acc[i][j][2]=0;acc[i][j][3]=0;}

    load_stage1(sb,0,0, m0,n0,tid,A,Bh);
    load_stage1(sb,1,32,m0,n0,tid,A,Bh);
    load_stage1(sb,2,64,m0,n0,tid,A,Bh);

    const uint32_t a_row  = (uint32_t)(wm*32 + (lane&15));
    const uint32_t a_colb = (uint32_t)((lane>>4)*16);
    const uint32_t b_row  = (uint32_t)(wn*64 + (lane&7) + ((lane>>4)<<3));
    const uint32_t b_colb = (uint32_t)(((lane>>3)&1)*16);

    for (int c=0; c<NCHG; ++c){
        CPA_WAIT2();
        __syncthreads();
        if (c+3 < NCHG) load_stage1(sb,(c+3)&3,(c+3)*32, m0,n0,tid,A,Bh);
        else CPA_COMMIT();

        const uint32_t st = sb + (c&3)*ST1_B;
        #pragma unroll
        for (int s=0; s<2; ++s){
            uint32_t ah[2][4];
            #pragma unroll
            for (int mt=0; mt<2; ++mt)
                LDSM4(ah[mt], st + (a_row + mt*16)*ROWB + s*32 + a_colb);
            uint32_t bh[8][2];
            #pragma unroll
            for (int p=0; p<4; ++p){
                uint32_t ba = st + OFF1_B + (b_row + p*16)*ROWB + s*32 + b_colb;
                uint32_t r[4];
                LDSM4(r, ba);
                bh[2*p][0]=r[0]; bh[2*p][1]=r[1]; bh[2*p+1][0]=r[2]; bh[2*p+1][1]=r[3];
            }
            #pragma unroll
            for (int mt=0; mt<2; ++mt)
                #pragma unroll
                for (int nt=0; nt<8; ++nt)
                    MMA_F16(acc[mt][nt], ah[mt], bh[nt]);
        }
    }
    #pragma unroll
    for (int mt=0; mt<2; ++mt)
        #pragma unroll
        for (int nt=0; nt<8; ++nt){
            int row = m0 + wm*32 + mt*16 + g;
            int col = n0 + wn*64 + nt*8 + tg*2;
            float2 v0 = {acc[mt][nt][0], acc[mt][nt][1]};
            float2 v1 = {acc[mt][nt][2], acc[mt][nt][3]};
            *(float2*)&C[(size_t)row*ldC + col]     = v0;
            *(float2*)&C[(size_t)(row+8)*ldC + col] = v1;
        }
}

// ---------------- conversions ----------------
__global__ void split_h(const float* __restrict__ in,
                        hlf* __restrict__ hi, hlf* __restrict__ lo)
{
    size_t i = ((size_t)blockIdx.x*blockDim.x + threadIdx.x)*8;
    #pragma unroll
    for (int u=0; u<2; ++u){
        float4 v = *(const float4*)(in+i+u*4);
        uint32_t r0, r1, h0, h1;
        h0 = splitpk(v.x, v.y, r0);
        h1 = splitpk(v.z, v.w, r1);
        *(uint32_t*)&hi[i+u*4]   = h0; *(uint32_t*)&hi[i+u*4+2] = h1;
        *(uint32_t*)&lo[i+u*4]   = r0; *(uint32_t*)&lo[i+u*4+2] = r1;
    }
}
__global__ void conv_h(const float* __restrict__ in, hlf* __restrict__ out)
{
    size_t i = ((size_t)blockIdx.x*blockDim.x + threadIdx.x)*8;
    #pragma unroll
    for (int u=0; u<2; ++u){
        float4 v = *(const float4*)(in+i+u*4);
        *(uint32_t*)&out[i+u*4]   = h2u(__floats2half2_rn(v.x, v.y));
        *(uint32_t*)&out[i+u*4+2] = h2u(__floats2half2_rn(v.z, v.w));
    }
}
__global__ void conv_v(const float* __restrict__ v, hlf* __restrict__ out)
{
    size_t idx = (size_t)blockIdx.x*blockDim.x + threadIdx.x;
    size_t r = idx >> 7;
    int c = (int)(idx & 127) * 8;
    #pragma unroll
    for (int u=0; u<2; ++u){
        float4 x = *(const float4*)&v[r*KVLD + c + u*4];
        size_t o = r*KVDIM + c + u*4;
        *(uint32_t*)&out[o]   = h2u(__floats2half2_rn(x.x, x.y));
        *(uint32_t*)&out[o+2] = h2u(__floats2half2_rn(x.z, x.w));
    }
}

// ---------------- RoPE ----------------
__global__ void rope_split(const float* __restrict__ buf, hlf* __restrict__ oh,
                           hlf* __restrict__ ol, int nheads, int rstride, float scale)
{
    int idx = blockIdx.x*blockDim.x + threadIdx.x;
    int i = idx & 63, t = idx >> 6;
    int h = t % nheads, row = t / nheads;
    int s = row & (S_LEN-1);
    float inv = powf(10000.0f, -(float)i*(1.0f/64.0f));
    float sn, cs; sincosf((float)s*inv, &sn, &cs);
    const float* p = buf + (size_t)row*rstride + h*HD;
    float x1 = p[i], x2 = p[i+64];
    float y1 = (x1*cs - x2*sn)*scale;
    float y2 = (x2*cs + x1*sn)*scale;
    size_t o = (size_t)row*(nheads*HD) + h*HD + i;
    hlf h1 = __float2half_rn(y1), h2 = __float2half_rn(y2);
    oh[o]=h1;    ol[o]   =__float2half_rn(y1-__half2float(h1));
    oh[o+64]=h2; ol[o+64]=__float2half_rn(y2-__half2float(h2));
}
__global__ void rope_single(const float* __restrict__ buf, hlf* __restrict__ oh,
                            int nheads, int rstride)
{
    int idx = blockIdx.x*blockDim.x + threadIdx.x;
    int i = idx & 63, t = idx >> 6;
    int h = t % nheads, row = t / nheads;
    int s = row & (S_LEN-1);
    float inv = powf(10000.0f, -(float)i*(1.0f/64.0f));
    float sn, cs; sincosf((float)s*inv, &sn, &cs);
    const float* p = buf + (size_t)row*rstride + h*HD;
    float x1 = p[i], x2 = p[i+64];
    size_t o = (size_t)row*(nheads*HD) + h*HD + i;
    oh[o]    = __float2half_rn(x1*cs - x2*sn);
    oh[o+64] = __float2half_rn(x2*cs + x1*sn);
}

// ---------------------------------------------------------------------------
// fp16 HMMA flash attention (base-2 softmax, PV 1-term, reversed qb order)
// ---------------------------------------------------------------------------
#define AROWB 272
#define QSZ   34816
#define KVARR 17408
#define KVSTG 34816
#define ASMEM (2*QSZ + 2*KVSTG)   // 139264

static __device__ __forceinline__ void a_load_kv(
    uint32_t st, int kbase, int brow, int tid, int kvh,
    const hlf* __restrict__ kh, const hlf* __restrict__ vh)
{
    #pragma unroll
    for (int it=0; it<4; ++it){
        int idx = tid + it*256;
        int r = idx>>4, ch = idx&15;
        uint32_t so = (uint32_t)(r*AROWB + ch*16);
        size_t gsrc = (size_t)(brow + kbase + r)*KVDIM + kvh*HD + ch*8;
        CPA(st + so,         kh + gsrc);
        CPA(st + KVARR + so, vh + gsrc);
    }
    CPA_COMMIT();
}

__global__ void __launch_bounds__(256,1) attn_mma(
    const hlf* __restrict__ qh_, const hlf* __restrict__ ql_,
    const hlf* __restrict__ kh_, const hlf* __restrict__ vh_,
    hlf* __restrict__ aoh)
{
    extern __shared__ __align__(128) char sm[];
    const uint32_t sb = s2u(sm);
    const uint32_t QH = sb, ST0 = sb + 2*QSZ;

    const int tid = threadIdx.x, w = tid>>5, lane = tid&31;
    const int qb = (int)(gridDim.x - 1 - blockIdx.x);   // heavy tiles first
    const int hh = blockIdx.y, b = blockIdx.z;
    const int q0 = qb*128, kvh = hh>>2;
    const int g = lane>>2, colc = (lane&3)*2;
    const int browg = b*S_LEN;

    #pragma unroll
    for (int it=0; it<8; ++it){
        int idx = tid + it*256;
        int r = idx>>4, ch = idx&15;
        uint32_t so = (uint32_t)(r*AROWB + ch*16);
        size_t gsrc = (size_t)(browg + q0 + r)*QDIM + hh*HD + ch*8;
        CPA(QH + so, qh_ + gsrc);
        CPA(QH + QSZ + so, ql_ + gsrc);
    }
    CPA_COMMIT();

    int lo = q0 - (WIN-1); if (lo < 0) lo = 0;
    const int kt0 = lo >> 6, ktend = 2*qb + 1;

    a_load_kv(ST0, kt0*64, browg, tid, kvh, kh_, vh_);

    uint32_t qfh[8][4], qfl[8][4];
    float O[16][4];
    #pragma unroll
    for (int t=0;t<16;++t){O[t][0]=0;O[t][1]=0;O[t][2]=0;O[t][3]=0;}
    float m0 = -1e30f, m1 = -1e30f, l0 = 0.f, l1 = 0.f;

    const uint32_t a_row  = (uint32_t)(w*16 + (lane&15));
    const uint32_t a_colb = (uint32_t)((lane>>4)*16);
    const uint32_t kb_row = (uint32_t)((lane&7) + ((lane>>4)<<3));
    const uint32_t kb_col = (uint32_t)(((lane>>3)&1)*16);
    const uint32_t vb_row = (uint32_t)((lane&7) + (lane&8));
    const uint32_t vb_col = (uint32_t)((lane>>4)*16);

    const int rmin_w = q0 + w*16;

    for (int kt = kt0; kt <= ktend; ++kt){
        const int s = (kt - kt0) & 1;
        const uint32_t ST = ST0 + (uint32_t)s*KVSTG;
        if (kt < ktend){
            a_load_kv(ST0 + (uint32_t)(s^1)*KVSTG, (kt+1)*64, browg, tid, kvh, kh_, vh_);
            CPA_WAIT1();
        } else {
            CPA_WAIT0();
        }
        __syncthreads();

        if (kt == kt0){
            #pragma unroll
            for (int kk=0; kk<8; ++kk){
                uint32_t aa = QH + a_row*AROWB + kk*32 + a_colb;
                LDSM4(qfh[kk], aa);
                LDSM4(qfl[kk], aa + QSZ);
            }
        }

        const int kbase = kt*64;
        if ((kbase <= rmin_w + 15) && (kbase + 63 > rmin_w - WIN)){
            float p[8][4];
            #pragma unroll
            for (int t=0;t<8;++t){p[t][0]=0;p[t][1]=0;p[t][2]=0;p[t][3]=0;}
            #pragma unroll
            for (int kk=0; kk<8; ++kk){
                #pragma unroll
                for (int np=0; np<4; ++np){
                    uint32_t ba = ST + (np*16 + kb_row)*AROWB + kk*32 + kb_col;
                    uint32_t kf[4];
                    LDSM4(kf, ba);
                    MMA_F16(p[2*np],   qfh[kk], kf);
                    MMA_F16(p[2*np+1], qfh[kk], kf+2);
                    MMA_F16(p[2*np],   qfl[kk], kf);
                    MMA_F16(p[2*np+1], qfl[kk], kf+2);
                }
            }

            const int r0 = rmin_w + g, r1 = r0 + 8;
            const bool full = (kbase + 63 <= rmin_w) && (kbase >= rmin_w + 16 - WIN);
            if (!full){
                #pragma unroll
                for (int t=0; t<8; ++t){
                    #pragma unroll
                    for (int e=0; e<2; ++e){
                        int kj = kbase + t*8 + colc + e;
                        if (!((kj<=r0)&&(r0-kj<WIN))) p[t][e]   = -1e30f;
                        if (!((kj<=r1)&&(r1-kj<WIN))) p[t][2+e] = -1e30f;
                    }
                }
            }
            float rm0 = -1e30f, rm1 = -1e30f;
            #pragma unroll
            for (int t=0; t<8; ++t){
                rm0 = fmaxf(rm0, fmaxf(p[t][0], p[t][1]));
                rm1 = fmaxf(rm1, fmaxf(p[t][2], p[t][3]));
            }
            rm0 = fmaxf(rm0, __shfl_xor_sync(~0u, rm0, 1));
            rm0 = fmaxf(rm0, __shfl_xor_sync(~0u, rm0, 2));
            rm1 = fmaxf(rm1, __shfl_xor_sync(~0u, rm1, 1));
            rm1 = fmaxf(rm1, __shfl_xor_sync(~0u, rm1, 2));
            float mn0 = fmaxf(m0, rm0), mn1 = fmaxf(m1, rm1);
            float sc0 = exp2f(m0 - mn0), sc1 = exp2f(m1 - mn1);
            m0 = mn0; m1 = mn1;
            float rs0 = 0.f, rs1 = 0.f;
            #pragma unroll
            for (int t=0; t<8; ++t){
                p[t][0] = exp2f(p[t][0]-mn0); p[t][1] = exp2f(p[t][1]-mn0);
                p[t][2] = exp2f(p[t][2]-mn1); p[t][3] = exp2f(p[t][3]-mn1);
                rs0 += p[t][0] + p[t][1];
                rs1 += p[t][2] + p[t][3];
            }
            rs0 += __shfl_xor_sync(~0u, rs0, 1); rs0 += __shfl_xor_sync(~0u, rs0, 2);
            rs1 += __shfl_xor_sync(~0u, rs1, 1); rs1 += __shfl_xor_sync(~0u, rs1, 2);
            l0 = l0*sc0 + rs0; l1 = l1*sc1 + rs1;
            #pragma unroll
            for (int t=0; t<16; ++t){
                O[t][0]*=sc0; O[t][1]*=sc0; O[t][2]*=sc1; O[t][3]*=sc1;
            }

            // ---- O += P V (1-term: P rounded to fp16) ----
            const uint32_t VB = ST + KVARR;
            #pragma unroll
            for (int kk=0; kk<4; ++kk){
                uint32_t pha[4];
                pha[0] = h2u(__floats2half2_rn(p[2*kk][0],   p[2*kk][1]));
                pha[1] = h2u(__floats2half2_rn(p[2*kk][2],   p[2*kk][3]));
                pha[2] = h2u(__floats2half2_rn(p[2*kk+1][0], p[2*kk+1][1]));
                pha[3] = h2u(__floats2half2_rn(p[2*kk+1][2], p[2*kk+1][3]));
                #pragma unroll
                for (int vp=0; vp<8; ++vp){
                    uint32_t va = VB + (kk*16 + vb_row)*AROWB + vp*32 + vb_col;
                    uint32_t vf[4];
                    LDSM4T(vf, va);
                    MMA_F16(O[2*vp],   pha, vf);
                    MMA_F16(O[2*vp+1], pha, vf+2);
                }
            }
        }
        __syncthreads();
    }

    float il0 = 1.0f/l0, il1 = 1.0f/l1;
    const size_t row0 = (size_t)(browg + q0 + w*16 + g);
    #pragma unroll
    for (int nt=0; nt<16; ++nt){
        size_t o0 = row0*QDIM + hh*HD + nt*8 + colc;
        size_t o1 = o0 + 8*QDIM;
        *(uint32_t*)&aoh[o0] = h2u(__floats2half2_rn(O[nt][0]*il0, O[nt][1]*il0));
        *(uint32_t*)&aoh[o1] = h2u(__floats2half2_rn(O[nt][2]*il1, O[nt][3]*il1));
    }
}

// ---------------------------------------------------------------------------
extern "C" void kernel_launch(void* const* d_in, const int* in_sizes, int n_in,
                              void* d_out, int out_size)
{
    const float* X  = (const float*)d_in[0];
    const float* Wq = (const float*)d_in[1];
    const float* Wk = (const float*)d_in[2];
    const float* Wv = (const float*)d_in[3];
    const float* Wo = (const float*)d_in[4];
    float* out = (float*)d_out;

    float *qp,*kvp;
    hlf *xh,*xl,*wqh,*wkv,*woh,*qh,*ql,*kh,*vh,*aoh;
    cudaGetSymbolAddress((void**)&qp,  g_Qp);
    cudaGetSymbolAddress((void**)&kvp, g_KVp);
    cudaGetSymbolAddress((void**)&xh, g_xh);  cudaGetSymbolAddress((void**)&xl, g_xl);
    cudaGetSymbolAddress((void**)&wqh,g_wqh);
    cudaGetSymbolAddress((void**)&wkv,g_wkv);
    cudaGetSymbolAddress((void**)&woh,g_woh);
    cudaGetSymbolAddress((void**)&qh, g_qh);  cudaGetSymbolAddress((void**)&ql, g_ql);
    cudaGetSymbolAddress((void**)&kh, g_kh);
    cudaGetSymbolAddress((void**)&vh, g_vh);
    cudaGetSymbolAddress((void**)&aoh,g_aoh);

    const size_t KVW = (size_t)1024*HID;
    const size_t QW  = (size_t)QDIM*HID;

    split_h<<<(int)((MROWS*(size_t)HID)/2048), 256>>>(X, xh, xl);
    conv_h <<<(int)(QW/2048),  256>>>(Wq, wqh);
    conv_h <<<(int)(KVW/2048), 256>>>(Wk, wkv);
    conv_h <<<(int)(KVW/2048), 256>>>(Wv, wkv + KVW);
    conv_h <<<(int)(QW/2048),  256>>>(Wo, woh);

    // Q projection: 2-term (X split); KV projection: 1-term
    cudaFuncSetAttribute(gemm_f16s, cudaFuncAttributeMaxDynamicSharedMemorySize, GSMEM);
    cudaFuncSetAttribute(gemm_f16,  cudaFuncAttributeMaxDynamicSharedMemorySize, GSMEM1);
    gemm_f16s<<<dim3(QDIM/256, MROWS/128), 512, GSMEM >>>(xh, xl, wqh, qp, QDIM);
    gemm_f16 <<<dim3(KVLD/256, MROWS/128), 512, GSMEM1>>>(xh, wkv, kvp, KVLD);

    const float SCL2 = 0.08838834764831845f * 1.4426950408889634f;
    rope_split <<<(MROWS*NH *64)/256, 256>>>(qp,  qh, ql, NH,  QDIM, SCL2);
    rope_single<<<(MROWS*NKV*64)/256, 256>>>(kvp, kh, NKV, KVLD);
    conv_v<<<(int)(((size_t)MROWS*KVDIM)/2048), 256>>>(kvp + 1024, vh);

    cudaFuncSetAttribute(attn_mma, cudaFuncAttributeMaxDynamicSharedMemorySize, ASMEM);
    attn_mma<<<dim3(S_LEN/128, NH, 2), 256, ASMEM>>>(qh, ql, kh, vh, aoh);

    gemm_f16<<<dim3(QDIM/256, MROWS/128), 512, GSMEM1>>>(aoh, woh, out, QDIM);
}

// round 10
// speedup vs baseline: 5.6130x; 1.1601x over previous
#include <cuda_runtime.h>
#include <cuda_fp16.h>
#include <math.h>
#include <stdint.h>

#define S_LEN 2048
#define HID   4096
#define NH    32
#define NKV   8
#define HD    128
#define WIN   1024
#define QDIM  4096
#define QKVN  6144
#define KVDIM 1024
#define MROWS 4096

typedef __half hlf;

__device__ float g_QKV[(size_t)MROWS*QKVN];
__device__ hlf g_xh [(size_t)MROWS*HID];
__device__ hlf g_wf [(size_t)QKVN*HID];     // Wq|Wk|Wv
__device__ hlf g_woh[(size_t)HID*QDIM];
__device__ hlf g_qh [(size_t)MROWS*QDIM], g_ql [(size_t)MROWS*QDIM];
__device__ hlf g_kh [(size_t)MROWS*KVDIM];
__device__ hlf g_vh [(size_t)MROWS*KVDIM];
__device__ hlf g_aoh[(size_t)MROWS*QDIM];

// ---------------- PTX helpers ----------------
__device__ __forceinline__ uint32_t s2u(const void* p){
    uint32_t a;
    asm("{ .reg .u64 t; cvta.to.shared.u64 t,%1; cvt.u32.u64 %0,t; }":"=r"(a):"l"(p));
    return a;
}
#define CPA(dst,src) asm volatile( \
    "cp.async.cg.shared.global [%0],[%1],16;" :: "r"(dst),"l"(src) : "memory")
#define CPA_COMMIT() asm volatile("cp.async.commit_group;" ::: "memory")
#define CPA_WAIT0()  asm volatile("cp.async.wait_group 0;" ::: "memory")
#define CPA_WAIT1()  asm volatile("cp.async.wait_group 1;" ::: "memory")
#define CPA_WAIT2()  asm volatile("cp.async.wait_group 2;" ::: "memory")

#define LDSM4(r,addr) asm volatile( \
    "ldmatrix.sync.aligned.m8n8.x4.shared.b16 {%0,%1,%2,%3},[%4];" \
    : "=r"((r)[0]),"=r"((r)[1]),"=r"((r)[2]),"=r"((r)[3]) : "r"(addr))
#define LDSM4T(r,addr) asm volatile( \
    "ldmatrix.sync.aligned.m8n8.x4.trans.shared.b16 {%0,%1,%2,%3},[%4];" \
    : "=r"((r)[0]),"=r"((r)[1]),"=r"((r)[2]),"=r"((r)[3]) : "r"(addr))

#define MMA_F16(c,a,b) asm volatile( \
    "mma.sync.aligned.m16n8k16.row.col.f32.f16.f16.f32 " \
    "{%0,%1,%2,%3},{%4,%5,%6,%7},{%8,%9},{%0,%1,%2,%3};" \
    : "+f"((c)[0]),"+f"((c)[1]),"+f"((c)[2]),"+f"((c)[3]) \
    : "r"((a)[0]),"r"((a)[1]),"r"((a)[2]),"r"((a)[3]),"r"((b)[0]),"r"((b)[1]))

__device__ __forceinline__ uint32_t h2u(__half2 h){ return *reinterpret_cast<uint32_t*>(&h); }

// ---------------------------------------------------------------------------
// 1-term fp16 GEMM: C = A·B^T. CTA 128x256, BK=32, 512 thr, 4-stage cp.async.
// ---------------------------------------------------------------------------
#define GK      4096
#define NCHG    128
#define ROWB    80
#define ST1_B   30720
#define OFF1_B  10240
#define GSMEM1  (4*ST1_B)   // 122880

static __device__ __forceinline__ void load_stage1(
    uint32_t sb, int stage, int kc, int m0, int n0, int tid,
    const hlf* __restrict__ A, const hlf* __restrict__ Bh)
{
    uint32_t st = sb + stage*ST1_B;
    {
        int r = tid>>2, ch = tid&3;
        uint32_t so = (uint32_t)(r*ROWB + ch*16);
        CPA(st+so, A + (size_t)(m0+r)*GK + kc + ch*8);
    }
    #pragma unroll
    for (int it=0; it<2; ++it){
        int idx = tid + it*512;
        int r = idx>>2, ch = idx&3;
        uint32_t so = (uint32_t)(r*ROWB + ch*16);
        CPA(st+OFF1_B+so, Bh + (size_t)(n0+r)*GK + kc + ch*8);
    }
    CPA_COMMIT();
}

__global__ void __launch_bounds__(512,1) gemm_f16(
    const hlf* __restrict__ A, const hlf* __restrict__ Bh,
    float* __restrict__ C, int ldC)
{
    extern __shared__ __align__(128) char sm[];
    const uint32_t sb = s2u(sm);
    const int tid = threadIdx.x, wid = tid>>5, lane = tid&31;
    const int wm = wid&3, wn = wid>>2;
    const int g = lane>>2, tg = lane&3;
    const int m0 = blockIdx.y*128, n0 = blockIdx.x*256;

    float acc[2][8][4];
    #pragma unroll
    for (int i=0;i<2;++i)
        #pragma unroll
        for (int j=0;j<8;++j){acc[i][j][0]=0;acc[i][j][1]=0;acc[i][j][2]=0;acc[i][j][3]=0;}

    load_stage1(sb,0,0, m0,n0,tid,A,Bh);
    load_stage1(sb,1,32,m0,n0,tid,A,Bh);
    load_stage1(sb,2,64,m0,n0,tid,A,Bh);

    const uint32_t a_row  = (uint32_t)(wm*32 + (lane&15));
    const uint32_t a_colb = (uint32_t)((lane>>4)*16);
    const uint32_t b_row  = (uint32_t)(wn*64 + (lane&7) + ((lane>>4)<<3));
    const uint32_t b_colb = (uint32_t)(((lane>>3)&1)*16);

    for (int c=0; c<NCHG; ++c){
        CPA_WAIT2();
        __syncthreads();
        if (c+3 < NCHG) load_stage1(sb,(c+3)&3,(c+3)*32, m0,n0,tid,A,Bh);
        else CPA_COMMIT();

        const uint32_t st = sb + (c&3)*ST1_B;
        #pragma unroll
        for (int s=0; s<2; ++s){
            uint32_t ah[2][4];
            #pragma unroll
            for (int mt=0; mt<2; ++mt)
                LDSM4(ah[mt], st + (a_row + mt*16)*ROWB + s*32 + a_colb);
            uint32_t bh[8][2];
            #pragma unroll
            for (int p=0; p<4; ++p){
                uint32_t ba = st + OFF1_B + (b_row + p*16)*ROWB + s*32 + b_colb;
                uint32_t r[4];
                LDSM4(r, ba);
                bh[2*p][0]=r[0]; bh[2*p][1]=r[1]; bh[2*p+1][0]=r[2]; bh[2*p+1][1]=r[3];
            }
            #pragma unroll
            for (int mt=0; mt<2; ++mt)
                #pragma unroll
                for (int nt=0; nt<8; ++nt)
                    MMA_F16(acc[mt][nt], ah[mt], bh[nt]);
        }
    }
    #pragma unroll
    for (int mt=0; mt<2; ++mt)
        #pragma unroll
        for (int nt=0; nt<8; ++nt){
            int row = m0 + wm*32 + mt*16 + g;
            int col = n0 + wn*64 + nt*8 + tg*2;
            float2 v0 = {acc[mt][nt][0], acc[mt][nt][1]};
            float2 v1 = {acc[mt][nt][2], acc[mt][nt][3]};
            *(float2*)&C[(size_t)row*ldC + col]     = v0;
            *(float2*)&C[(size_t)(row+8)*ldC + col] = v1;
        }
}

// ---------------- conversions ----------------
__global__ void conv_h(const float* __restrict__ in, hlf* __restrict__ out)
{
    size_t i = ((size_t)blockIdx.x*blockDim.x + threadIdx.x)*8;
    #pragma unroll
    for (int u=0; u<2; ++u){
        float4 v = *(const float4*)(in+i+u*4);
        *(uint32_t*)&out[i+u*4]   = h2u(__floats2half2_rn(v.x, v.y));
        *(uint32_t*)&out[i+u*4+2] = h2u(__floats2half2_rn(v.z, v.w));
    }
}
// V slab of fused QKV (stride QKVN) -> fp16
__global__ void conv_v(const float* __restrict__ v, hlf* __restrict__ out)
{
    size_t idx = (size_t)blockIdx.x*blockDim.x + threadIdx.x;
    size_t r = idx >> 7;
    int c = (int)(idx & 127) * 8;
    #pragma unroll
    for (int u=0; u<2; ++u){
        float4 x = *(const float4*)&v[r*QKVN + c + u*4];
        size_t o = r*KVDIM + c + u*4;
        *(uint32_t*)&out[o]   = h2u(__floats2half2_rn(x.x, x.y));
        *(uint32_t*)&out[o+2] = h2u(__floats2half2_rn(x.z, x.w));
    }
}

// ---------------- RoPE ----------------
__global__ void rope_split(const float* __restrict__ buf, hlf* __restrict__ oh,
                           hlf* __restrict__ ol, int nheads, int rstride, float scale)
{
    int idx = blockIdx.x*blockDim.x + threadIdx.x;
    int i = idx & 63, t = idx >> 6;
    int h = t % nheads, row = t / nheads;
    int s = row & (S_LEN-1);
    float inv = powf(10000.0f, -(float)i*(1.0f/64.0f));
    float sn, cs; sincosf((float)s*inv, &sn, &cs);
    const float* p = buf + (size_t)row*rstride + h*HD;
    float x1 = p[i], x2 = p[i+64];
    float y1 = (x1*cs - x2*sn)*scale;
    float y2 = (x2*cs + x1*sn)*scale;
    size_t o = (size_t)row*(nheads*HD) + h*HD + i;
    hlf h1 = __float2half_rn(y1), h2 = __float2half_rn(y2);
    oh[o]=h1;    ol[o]   =__float2half_rn(y1-__half2float(h1));
    oh[o+64]=h2; ol[o+64]=__float2half_rn(y2-__half2float(h2));
}
__global__ void rope_single(const float* __restrict__ buf, hlf* __restrict__ oh,
                            int nheads, int rstride)
{
    int idx = blockIdx.x*blockDim.x + threadIdx.x;
    int i = idx & 63, t = idx >> 6;
    int h = t % nheads, row = t / nheads;
    int s = row & (S_LEN-1);
    float inv = powf(10000.0f, -(float)i*(1.0f/64.0f));
    float sn, cs; sincosf((float)s*inv, &sn, &cs);
    const float* p = buf + (size_t)row*rstride + h*HD;
    float x1 = p[i], x2 = p[i+64];
    size_t o = (size_t)row*(nheads*HD) + h*HD + i;
    oh[o]    = __float2half_rn(x1*cs - x2*sn);
    oh[o+64] = __float2half_rn(x2*cs + x1*sn);
}

// ---------------------------------------------------------------------------
// fp16 HMMA flash attention (base-2 softmax, QK 2-term / PV 1-term)
// ---------------------------------------------------------------------------
#define AROWB 272
#define QSZ   34816
#define KVARR 17408
#define KVSTG 34816
#define ASMEM (2*QSZ + 2*KVSTG)   // 139264

static __device__ __forceinline__ void a_load_kv(
    uint32_t st, int kbase, int brow, int tid, int kvh,
    const hlf* __restrict__ kh, const hlf* __restrict__ vh)
{
    #pragma unroll
    for (int it=0; it<4; ++it){
        int idx = tid + it*256;
        int r = idx>>4, ch = idx&15;
        uint32_t so = (uint32_t)(r*AROWB + ch*16);
        size_t gsrc = (size_t)(brow + kbase + r)*KVDIM + kvh*HD + ch*8;
        CPA(st + so,         kh + gsrc);
        CPA(st + KVARR + so, vh + gsrc);
    }
    CPA_COMMIT();
}

__global__ void __launch_bounds__(256,1) attn_mma(
    const hlf* __restrict__ qh_, const hlf* __restrict__ ql_,
    const hlf* __restrict__ kh_, const hlf* __restrict__ vh_,
    hlf* __restrict__ aoh)
{
    extern __shared__ __align__(128) char sm[];
    const uint32_t sb = s2u(sm);
    const uint32_t QH = sb, ST0 = sb + 2*QSZ;

    const int tid = threadIdx.x, w = tid>>5, lane = tid&31;
    const int qb = (int)(gridDim.x - 1 - blockIdx.x);   // heavy tiles first
    const int hh = blockIdx.y, b = blockIdx.z;
    const int q0 = qb*128, kvh = hh>>2;
    const int g = lane>>2, colc = (lane&3)*2;
    const int browg = b*S_LEN;

    #pragma unroll
    for (int it=0; it<8; ++it){
        int idx = tid + it*256;
        int r = idx>>4, ch = idx&15;
        uint32_t so = (uint32_t)(r*AROWB + ch*16);
        size_t gsrc = (size_t)(browg + q0 + r)*QDIM + hh*HD + ch*8;
        CPA(QH + so, qh_ + gsrc);
        CPA(QH + QSZ + so, ql_ + gsrc);
    }
    CPA_COMMIT();

    int lo = q0 - (WIN-1); if (lo < 0) lo = 0;
    const int kt0 = lo >> 6, ktend = 2*qb + 1;

    a_load_kv(ST0, kt0*64, browg, tid, kvh, kh_, vh_);

    uint32_t qfh[8][4], qfl[8][4];
    float O[16][4];
    #pragma unroll
    for (int t=0;t<16;++t){O[t][0]=0;O[t][1]=0;O[t][2]=0;O[t][3]=0;}
    float m0 = -1e30f, m1 = -1e30f, l0 = 0.f, l1 = 0.f;

    const uint32_t a_row  = (uint32_t)(w*16 + (lane&15));
    const uint32_t a_colb = (uint32_t)((lane>>4)*16);
    const uint32_t kb_row = (uint32_t)((lane&7) + ((lane>>4)<<3));
    const uint32_t kb_col = (uint32_t)(((lane>>3)&1)*16);
    const uint32_t vb_row = (uint32_t)((lane&7) + (lane&8));
    const uint32_t vb_col = (uint32_t)((lane>>4)*16);

    const int rmin_w = q0 + w*16;

    for (int kt = kt0; kt <= ktend; ++kt){
        const int s = (kt - kt0) & 1;
        const uint32_t ST = ST0 + (uint32_t)s*KVSTG;
        if (kt < ktend){
            a_load_kv(ST0 + (uint32_t)(s^1)*KVSTG, (kt+1)*64, browg, tid, kvh, kh_, vh_);
            CPA_WAIT1();
        } else {
            CPA_WAIT0();
        }
        __syncthreads();

        if (kt == kt0){
            #pragma unroll
            for (int kk=0; kk<8; ++kk){
                uint32_t aa = QH + a_row*AROWB + kk*32 + a_colb;
                LDSM4(qfh[kk], aa);
                LDSM4(qfl[kk], aa + QSZ);
            }
        }

        const int kbase = kt*64;
        if ((kbase <= rmin_w + 15) && (kbase + 63 > rmin_w - WIN)){
            float p[8][4];
            #pragma unroll
            for (int t=0;t<8;++t){p[t][0]=0;p[t][1]=0;p[t][2]=0;p[t][3]=0;}
            #pragma unroll
            for (int kk=0; kk<8; ++kk){
                #pragma unroll
                for (int np=0; np<4; ++np){
                    uint32_t ba = ST + (np*16 + kb_row)*AROWB + kk*32 + kb_col;
                    uint32_t kf[4];
                    LDSM4(kf, ba);
                    MMA_F16(p[2*np],   qfh[kk], kf);
                    MMA_F16(p[2*np+1], qfh[kk], kf+2);
                    MMA_F16(p[2*np],   qfl[kk], kf);
                    MMA_F16(p[2*np+1], qfl[kk], kf+2);
                }
            }

            const int r0 = rmin_w + g, r1 = r0 + 8;
            const bool full = (kbase + 63 <= rmin_w) && (kbase >= rmin_w + 16 - WIN);
            if (!full){
                #pragma unroll
                for (int t=0; t<8; ++t){
                    #pragma unroll
                    for (int e=0; e<2; ++e){
                        int kj = kbase + t*8 + colc + e;
                        if (!((kj<=r0)&&(r0-kj<WIN))) p[t][e]   = -1e30f;
                        if (!((kj<=r1)&&(r1-kj<WIN))) p[t][2+e] = -1e30f;
                    }
                }
            }
            float rm0 = -1e30f, rm1 = -1e30f;
            #pragma unroll
            for (int t=0; t<8; ++t){
                rm0 = fmaxf(rm0, fmaxf(p[t][0], p[t][1]));
                rm1 = fmaxf(rm1, fmaxf(p[t][2], p[t][3]));
            }
            rm0 = fmaxf(rm0, __shfl_xor_sync(~0u, rm0, 1));
            rm0 = fmaxf(rm0, __shfl_xor_sync(~0u, rm0, 2));
            rm1 = fmaxf(rm1, __shfl_xor_sync(~0u, rm1, 1));
            rm1 = fmaxf(rm1, __shfl_xor_sync(~0u, rm1, 2));
            float mn0 = fmaxf(m0, rm0), mn1 = fmaxf(m1, rm1);
            float sc0 = exp2f(m0 - mn0), sc1 = exp2f(m1 - mn1);
            m0 = mn0; m1 = mn1;
            float rs0 = 0.f, rs1 = 0.f;
            #pragma unroll
            for (int t=0; t<8; ++t){
                p[t][0] = exp2f(p[t][0]-mn0); p[t][1] = exp2f(p[t][1]-mn0);
                p[t][2] = exp2f(p[t][2]-mn1); p[t][3] = exp2f(p[t][3]-mn1);
                rs0 += p[t][0] + p[t][1];
                rs1 += p[t][2] + p[t][3];
            }
            rs0 += __shfl_xor_sync(~0u, rs0, 1); rs0 += __shfl_xor_sync(~0u, rs0, 2);
            rs1 += __shfl_xor_sync(~0u, rs1, 1); rs1 += __shfl_xor_sync(~0u, rs1, 2);
            l0 = l0*sc0 + rs0; l1 = l1*sc1 + rs1;
            #pragma unroll
            for (int t=0; t<16; ++t){
                O[t][0]*=sc0; O[t][1]*=sc0; O[t][2]*=sc1; O[t][3]*=sc1;
            }

            const uint32_t VB = ST + KVARR;
            #pragma unroll
            for (int kk=0; kk<4; ++kk){
                uint32_t pha[4];
                pha[0] = h2u(__floats2half2_rn(p[2*kk][0],   p[2*kk][1]));
                pha[1] = h2u(__floats2half2_rn(p[2*kk][2],   p[2*kk][3]));
                pha[2] = h2u(__floats2half2_rn(p[2*kk+1][0], p[2*kk+1][1]));
                pha[3] = h2u(__floats2half2_rn(p[2*kk+1][2], p[2*kk+1][3]));
                #pragma unroll
                for (int vp=0; vp<8; ++vp){
                    uint32_t va = VB + (kk*16 + vb_row)*AROWB + vp*32 + vb_col;
                    uint32_t vf[4];
                    LDSM4T(vf, va);
                    MMA_F16(O[2*vp],   pha, vf);
                    MMA_F16(O[2*vp+1], pha, vf+2);
                }
            }
        }
        __syncthreads();
    }

    float il0 = 1.0f/l0, il1 = 1.0f/l1;
    const size_t row0 = (size_t)(browg + q0 + w*16 + g);
    #pragma unroll
    for (int nt=0; nt<16; ++nt){
        size_t o0 = row0*QDIM + hh*HD + nt*8 + colc;
        size_t o1 = o0 + 8*QDIM;
        *(uint32_t*)&aoh[o0] = h2u(__floats2half2_rn(O[nt][0]*il0, O[nt][1]*il0));
        *(uint32_t*)&aoh[o1] = h2u(__floats2half2_rn(O[nt][2]*il1, O[nt][3]*il1));
    }
}

// ---------------------------------------------------------------------------
extern "C" void kernel_launch(void* const* d_in, const int* in_sizes, int n_in,
                              void* d_out, int out_size)
{
    const float* X  = (const float*)d_in[0];
    const float* Wq = (const float*)d_in[1];
    const float* Wk = (const float*)d_in[2];
    const float* Wv = (const float*)d_in[3];
    const float* Wo = (const float*)d_in[4];
    float* out = (float*)d_out;

    float *qkv;
    hlf *xh,*wf,*woh,*qh,*ql,*kh,*vh,*aoh;
    cudaGetSymbolAddress((void**)&qkv, g_QKV);
    cudaGetSymbolAddress((void**)&xh, g_xh);
    cudaGetSymbolAddress((void**)&wf, g_wf);
    cudaGetSymbolAddress((void**)&woh,g_woh);
    cudaGetSymbolAddress((void**)&qh, g_qh);  cudaGetSymbolAddress((void**)&ql, g_ql);
    cudaGetSymbolAddress((void**)&kh, g_kh);
    cudaGetSymbolAddress((void**)&vh, g_vh);
    cudaGetSymbolAddress((void**)&aoh,g_aoh);

    const size_t KVW = (size_t)1024*HID;
    const size_t QW  = (size_t)QDIM*HID;

    conv_h<<<(int)((MROWS*(size_t)HID)/2048), 256>>>(X, xh);
    conv_h<<<(int)(QW/2048),  256>>>(Wq, wf);
    conv_h<<<(int)(KVW/2048), 256>>>(Wk, wf + QW);
    conv_h<<<(int)(KVW/2048), 256>>>(Wv, wf + QW + KVW);
    conv_h<<<(int)(QW/2048),  256>>>(Wo, woh);

    // fused Q|K|V projection: one 1-term GEMM, N=6144
    cudaFuncSetAttribute(gemm_f16, cudaFuncAttributeMaxDynamicSharedMemorySize, GSMEM1);
    gemm_f16<<<dim3(QKVN/256, MROWS/128), 512, GSMEM1>>>(xh, wf, qkv, QKVN);

    const float SCL2 = 0.08838834764831845f * 1.4426950408889634f;
    rope_split <<<(MROWS*NH *64)/256, 256>>>(qkv,        qh, ql, NH,  QKVN, SCL2);
    rope_single<<<(MROWS*NKV*64)/256, 256>>>(qkv + 4096, kh, NKV, QKVN);
    conv_v<<<(int)(((size_t)MROWS*KVDIM)/2048), 256>>>(qkv + 5120, vh);

    cudaFuncSetAttribute(attn_mma, cudaFuncAttributeMaxDynamicSharedMemorySize, ASMEM);
    attn_mma<<<dim3(S_LEN/128, NH, 2), 256, ASMEM>>>(qh, ql, kh, vh, aoh);

    gemm_f16<<<dim3(QDIM/256, MROWS/128), 512, GSMEM1>>>(aoh, woh, out, QDIM);
}

// round 11
// speedup vs baseline: 5.8335x; 1.0393x over previous
#include <cuda_runtime.h>
#include <cuda_fp16.h>
#include <math.h>
#include <stdint.h>

#define S_LEN 2048
#define HID   4096
#define NH    32
#define NKV   8
#define HD    128
#define WIN   1024
#define QDIM  4096
#define QKVN  6144
#define KVDIM 1024
#define MROWS 4096

typedef __half hlf;

__device__ float g_QKV[(size_t)MROWS*QKVN];
__device__ hlf g_xh [(size_t)MROWS*HID];
__device__ hlf g_wf [(size_t)QKVN*HID];     // Wq|Wk|Wv
__device__ hlf g_woh[(size_t)HID*QDIM];
__device__ hlf g_qh [(size_t)MROWS*QDIM];
__device__ hlf g_kh [(size_t)MROWS*KVDIM];
__device__ hlf g_vh [(size_t)MROWS*KVDIM];
__device__ hlf g_aoh[(size_t)MROWS*QDIM];

// ---------------- PTX helpers ----------------
__device__ __forceinline__ uint32_t s2u(const void* p){
    uint32_t a;
    asm("{ .reg .u64 t; cvta.to.shared.u64 t,%1; cvt.u32.u64 %0,t; }":"=r"(a):"l"(p));
    return a;
}
#define CPA(dst,src) asm volatile( \
    "cp.async.cg.shared.global [%0],[%1],16;" :: "r"(dst),"l"(src) : "memory")
#define CPA_COMMIT() asm volatile("cp.async.commit_group;" ::: "memory")
#define CPA_WAIT0()  asm volatile("cp.async.wait_group 0;" ::: "memory")
#define CPA_WAIT1()  asm volatile("cp.async.wait_group 1;" ::: "memory")
#define CPA_WAIT2()  asm volatile("cp.async.wait_group 2;" ::: "memory")

#define LDSM4(r,addr) asm volatile( \
    "ldmatrix.sync.aligned.m8n8.x4.shared.b16 {%0,%1,%2,%3},[%4];" \
    : "=r"((r)[0]),"=r"((r)[1]),"=r"((r)[2]),"=r"((r)[3]) : "r"(addr))
#define LDSM4T(r,addr) asm volatile( \
    "ldmatrix.sync.aligned.m8n8.x4.trans.shared.b16 {%0,%1,%2,%3},[%4];" \
    : "=r"((r)[0]),"=r"((r)[1]),"=r"((r)[2]),"=r"((r)[3]) : "r"(addr))

#define MMA_F16(c,a,b) asm volatile( \
    "mma.sync.aligned.m16n8k16.row.col.f32.f16.f16.f32 " \
    "{%0,%1,%2,%3},{%4,%5,%6,%7},{%8,%9},{%0,%1,%2,%3};" \
    : "+f"((c)[0]),"+f"((c)[1]),"+f"((c)[2]),"+f"((c)[3]) \
    : "r"((a)[0]),"r"((a)[1]),"r"((a)[2]),"r"((a)[3]),"r"((b)[0]),"r"((b)[1]))

__device__ __forceinline__ uint32_t h2u(__half2 h){ return *reinterpret_cast<uint32_t*>(&h); }

// ---------------------------------------------------------------------------
// 1-term fp16 GEMM: C = A·B^T. CTA 128x256, BK=32, 512 thr, 4-stage cp.async.
// ---------------------------------------------------------------------------
#define GK      4096
#define NCHG    128
#define ROWB    80
#define ST1_B   30720
#define OFF1_B  10240
#define GSMEM1  (4*ST1_B)   // 122880

static __device__ __forceinline__ void load_stage1(
    uint32_t sb, int stage, int kc, int m0, int n0, int tid,
    const hlf* __restrict__ A, const hlf* __restrict__ Bh)
{
    uint32_t st = sb + stage*ST1_B;
    {
        int r = tid>>2, ch = tid&3;
        uint32_t so = (uint32_t)(r*ROWB + ch*16);
        CPA(st+so, A + (size_t)(m0+r)*GK + kc + ch*8);
    }
    #pragma unroll
    for (int it=0; it<2; ++it){
        int idx = tid + it*512;
        int r = idx>>2, ch = idx&3;
        uint32_t so = (uint32_t)(r*ROWB + ch*16);
        CPA(st+OFF1_B+so, Bh + (size_t)(n0+r)*GK + kc + ch*8);
    }
    CPA_COMMIT();
}

__global__ void __launch_bounds__(512,1) gemm_f16(
    const hlf* __restrict__ A, const hlf* __restrict__ Bh,
    float* __restrict__ C, int ldC)
{
    extern __shared__ __align__(128) char sm[];
    const uint32_t sb = s2u(sm);
    const int tid = threadIdx.x, wid = tid>>5, lane = tid&31;
    const int wm = wid&3, wn = wid>>2;
    const int g = lane>>2, tg = lane&3;
    const int m0 = blockIdx.y*128, n0 = blockIdx.x*256;

    float acc[2][8][4];
    #pragma unroll
    for (int i=0;i<2;++i)
        #pragma unroll
        for (int j=0;j<8;++j){acc[i][j][0]=0;acc[i][j][1]=0;acc[i][j][2]=0;acc[i][j][3]=0;}

    load_stage1(sb,0,0, m0,n0,tid,A,Bh);
    load_stage1(sb,1,32,m0,n0,tid,A,Bh);
    load_stage1(sb,2,64,m0,n0,tid,A,Bh);

    const uint32_t a_row  = (uint32_t)(wm*32 + (lane&15));
    const uint32_t a_colb = (uint32_t)((lane>>4)*16);
    const uint32_t b_row  = (uint32_t)(wn*64 + (lane&7) + ((lane>>4)<<3));
    const uint32_t b_colb = (uint32_t)(((lane>>3)&1)*16);

    for (int c=0; c<NCHG; ++c){
        CPA_WAIT2();
        __syncthreads();
        if (c+3 < NCHG) load_stage1(sb,(c+3)&3,(c+3)*32, m0,n0,tid,A,Bh);
        else CPA_COMMIT();

        const uint32_t st = sb + (c&3)*ST1_B;
        #pragma unroll
        for (int s=0; s<2; ++s){
            uint32_t ah[2][4];
            #pragma unroll
            for (int mt=0; mt<2; ++mt)
                LDSM4(ah[mt], st + (a_row + mt*16)*ROWB + s*32 + a_colb);
            uint32_t bh[8][2];
            #pragma unroll
            for (int p=0; p<4; ++p){
                uint32_t ba = st + OFF1_B + (b_row + p*16)*ROWB + s*32 + b_colb;
                uint32_t r[4];
                LDSM4(r, ba);
                bh[2*p][0]=r[0]; bh[2*p][1]=r[1]; bh[2*p+1][0]=r[2]; bh[2*p+1][1]=r[3];
            }
            #pragma unroll
            for (int mt=0; mt<2; ++mt)
                #pragma unroll
                for (int nt=0; nt<8; ++nt)
                    MMA_F16(acc[mt][nt], ah[mt], bh[nt]);
        }
    }
    #pragma unroll
    for (int mt=0; mt<2; ++mt)
        #pragma unroll
        for (int nt=0; nt<8; ++nt){
            int row = m0 + wm*32 + mt*16 + g;
            int col = n0 + wn*64 + nt*8 + tg*2;
            float2 v0 = {acc[mt][nt][0], acc[mt][nt][1]};
            float2 v1 = {acc[mt][nt][2], acc[mt][nt][3]};
            *(float2*)&C[(size_t)row*ldC + col]     = v0;
            *(float2*)&C[(size_t)(row+8)*ldC + col] = v1;
        }
}

// ---------------------------------------------------------------------------
// fused fp32->fp16 conversion of X + all weights (one launch)
// segments (blocks of 2048 elems): X 8192 | Wq 8192 | Wk 2048 | Wv 2048 | Wo 8192
// ---------------------------------------------------------------------------
__global__ void conv_all(const float* __restrict__ X,  const float* __restrict__ Wq,
                         const float* __restrict__ Wk, const float* __restrict__ Wv,
                         const float* __restrict__ Wo,
                         hlf* __restrict__ xh, hlf* __restrict__ wf, hlf* __restrict__ woh)
{
    const size_t QW  = (size_t)QDIM*HID;
    const size_t KVW = (size_t)1024*HID;
    int bid = blockIdx.x;
    const float* src; hlf* dst; int rel;
    if      (bid <  8192){ src = X;  dst = xh;             rel = bid; }
    else if (bid < 16384){ src = Wq; dst = wf;             rel = bid-8192; }
    else if (bid < 18432){ src = Wk; dst = wf + QW;        rel = bid-16384; }
    else if (bid < 20480){ src = Wv; dst = wf + QW + KVW;  rel = bid-18432; }
    else                 { src = Wo; dst = woh;            rel = bid-20480; }
    size_t i = ((size_t)rel*256 + threadIdx.x)*8;
    #pragma unroll
    for (int u=0; u<2; ++u){
        float4 v = *(const float4*)(src+i+u*4);
        *(uint32_t*)&dst[i+u*4]   = h2u(__floats2half2_rn(v.x, v.y));
        *(uint32_t*)&dst[i+u*4+2] = h2u(__floats2half2_rn(v.z, v.w));
    }
}

// ---------------------------------------------------------------------------
// fused post-QKV: rope Q (scaled) | rope K | conv V  (one launch)
// blocks: Q 32768 | K 8192 | V 2048
// ---------------------------------------------------------------------------
__global__ void postproc(const float* __restrict__ qkv,
                         hlf* __restrict__ qh, hlf* __restrict__ kh,
                         hlf* __restrict__ vh)
{
    const float SCL2 = 0.08838834764831845f * 1.4426950408889634f;
    int bid = blockIdx.x, tid = threadIdx.x;
    if (bid < 32768){                     // Q rope + scale
        int idx = bid*256 + tid;
        int i = idx & 63, t = idx >> 6;
        int h = t & (NH-1), row = t >> 5;
        int s = row & (S_LEN-1);
        float inv = powf(10000.0f, -(float)i*(1.0f/64.0f));
        float sn, cs; sincosf((float)s*inv, &sn, &cs);
        const float* p = qkv + (size_t)row*QKVN + h*HD;
        float x1 = p[i], x2 = p[i+64];
        size_t o = (size_t)row*QDIM + h*HD + i;
        qh[o]    = __float2half_rn((x1*cs - x2*sn)*SCL2);
        qh[o+64] = __float2half_rn((x2*cs + x1*sn)*SCL2);
    } else if (bid < 40960){              // K rope
        int idx = (bid-32768)*256 + tid;
        int i = idx & 63, t = idx >> 6;
        int h = t & (NKV-1), row = t >> 3;
        int s = row & (S_LEN-1);
        float inv = powf(10000.0f, -(float)i*(1.0f/64.0f));
        float sn, cs; sincosf((float)s*inv, &sn, &cs);
        const float* p = qkv + (size_t)row*QKVN + 4096 + h*HD;
        float x1 = p[i], x2 = p[i+64];
        size_t o = (size_t)row*KVDIM + h*HD + i;
        kh[o]    = __float2half_rn(x1*cs - x2*sn);
        kh[o+64] = __float2half_rn(x2*cs + x1*sn);
    } else {                              // V convert
        int idx = (bid-40960)*256 + tid;
        size_t r = (size_t)(idx >> 7);
        int c = (idx & 127)*8;
        #pragma unroll
        for (int u=0; u<2; ++u){
            float4 x = *(const float4*)&qkv[r*QKVN + 5120 + c + u*4];
            size_t o = r*KVDIM + c + u*4;
            *(uint32_t*)&vh[o]   = h2u(__floats2half2_rn(x.x, x.y));
            *(uint32_t*)&vh[o+2] = h2u(__floats2half2_rn(x.z, x.w));
        }
    }
}

// ---------------------------------------------------------------------------
// fp16 HMMA flash attention (QK 1-term, f16x2 EX2 softmax, vote rescale-skip)
// ---------------------------------------------------------------------------
#define AROWB 272
#define QSZ   34816
#define KVARR 17408
#define KVSTG 34816
#define ASMEM (QSZ + 2*KVSTG)   // 104448

static __device__ __forceinline__ void a_load_kv(
    uint32_t st, int kbase, int brow, int tid, int kvh,
    const hlf* __restrict__ kh, const hlf* __restrict__ vh)
{
    #pragma unroll
    for (int it=0; it<4; ++it){
        int idx = tid + it*256;
        int r = idx>>4, ch = idx&15;
        uint32_t so = (uint32_t)(r*AROWB + ch*16);
        size_t gsrc = (size_t)(brow + kbase + r)*KVDIM + kvh*HD + ch*8;
        CPA(st + so,         kh + gsrc);
        CPA(st + KVARR + so, vh + gsrc);
    }
    CPA_COMMIT();
}

__global__ void __launch_bounds__(256,1) attn_mma(
    const hlf* __restrict__ qh_, const hlf* __restrict__ kh_,
    const hlf* __restrict__ vh_, hlf* __restrict__ aoh)
{
    extern __shared__ __align__(128) char sm[];
    const uint32_t sb = s2u(sm);
    const uint32_t QH = sb, ST0 = sb + QSZ;

    const int tid = threadIdx.x, w = tid>>5, lane = tid&31;
    const int qb = (int)(gridDim.x - 1 - blockIdx.x);   // heavy tiles first
    const int hh = blockIdx.y, b = blockIdx.z;
    const int q0 = qb*128, kvh = hh>>2;
    const int g = lane>>2, colc = (lane&3)*2;
    const int browg = b*S_LEN;

    #pragma unroll
    for (int it=0; it<8; ++it){
        int idx = tid + it*256;
        int r = idx>>4, ch = idx&15;
        uint32_t so = (uint32_t)(r*AROWB + ch*16);
        CPA(QH + so, qh_ + (size_t)(browg + q0 + r)*QDIM + hh*HD + ch*8);
    }
    CPA_COMMIT();

    int lo = q0 - (WIN-1); if (lo < 0) lo = 0;
    const int kt0 = lo >> 6, ktend = 2*qb + 1;

    a_load_kv(ST0, kt0*64, browg, tid, kvh, kh_, vh_);

    uint32_t qfh[8][4];
    float O[16][4];
    #pragma unroll
    for (int t=0;t<16;++t){O[t][0]=0;O[t][1]=0;O[t][2]=0;O[t][3]=0;}
    float m0 = -1e30f, m1 = -1e30f, l0 = 0.f, l1 = 0.f;

    const uint32_t a_row  = (uint32_t)(w*16 + (lane&15));
    const uint32_t a_colb = (uint32_t)((lane>>4)*16);
    const uint32_t kb_row = (uint32_t)((lane&7) + ((lane>>4)<<3));
    const uint32_t kb_col = (uint32_t)(((lane>>3)&1)*16);
    const uint32_t vb_row = (uint32_t)((lane&7) + (lane&8));
    const uint32_t vb_col = (uint32_t)((lane>>4)*16);

    const int rmin_w = q0 + w*16;

    for (int kt = kt0; kt <= ktend; ++kt){
        const int s = (kt - kt0) & 1;
        const uint32_t ST = ST0 + (uint32_t)s*KVSTG;
        if (kt < ktend){
            a_load_kv(ST0 + (uint32_t)(s^1)*KVSTG, (kt+1)*64, browg, tid, kvh, kh_, vh_);
            CPA_WAIT1();
        } else {
            CPA_WAIT0();
        }
        __syncthreads();

        if (kt == kt0){
            #pragma unroll
            for (int kk=0; kk<8; ++kk)
                LDSM4(qfh[kk], QH + a_row*AROWB + kk*32 + a_colb);
        }

        const int kbase = kt*64;
        if ((kbase <= rmin_w + 15) && (kbase + 63 > rmin_w - WIN)){
            // ---- S = Q K^T (1-term) ----
            float p[8][4];
            #pragma unroll
            for (int t=0;t<8;++t){p[t][0]=0;p[t][1]=0;p[t][2]=0;p[t][3]=0;}
            #pragma unroll
            for (int kk=0; kk<8; ++kk){
                #pragma unroll
                for (int np=0; np<4; ++np){
                    uint32_t kf[4];
                    LDSM4(kf, ST + (np*16 + kb_row)*AROWB + kk*32 + kb_col);
                    MMA_F16(p[2*np],   qfh[kk], kf);
                    MMA_F16(p[2*np+1], qfh[kk], kf+2);
                }
            }

            const int r0 = rmin_w + g, r1 = r0 + 8;
            const bool full = (kbase + 63 <= rmin_w) && (kbase >= rmin_w + 16 - WIN);
            if (!full){
                #pragma unroll
                for (int t=0; t<8; ++t){
                    #pragma unroll
                    for (int e=0; e<2; ++e){
                        int kj = kbase + t*8 + colc + e;
                        if (!((kj<=r0)&&(r0-kj<WIN))) p[t][e]   = -1e30f;
                        if (!((kj<=r1)&&(r1-kj<WIN))) p[t][2+e] = -1e30f;
                    }
                }
            }
            // ---- online softmax (base-2, f16x2 EX2 producing packed P) ----
            float rm0 = -1e30f, rm1 = -1e30f;
            #pragma unroll
            for (int t=0; t<8; ++t){
                rm0 = fmaxf(rm0, fmaxf(p[t][0], p[t][1]));
                rm1 = fmaxf(rm1, fmaxf(p[t][2], p[t][3]));
            }
            rm0 = fmaxf(rm0, __shfl_xor_sync(~0u, rm0, 1));
            rm0 = fmaxf(rm0, __shfl_xor_sync(~0u, rm0, 2));
            rm1 = fmaxf(rm1, __shfl_xor_sync(~0u, rm1, 1));
            rm1 = fmaxf(rm1, __shfl_xor_sync(~0u, rm1, 2));
            float mn0 = fmaxf(m0, rm0), mn1 = fmaxf(m1, rm1);
            float sc0 = exp2f(m0 - mn0), sc1 = exp2f(m1 - mn1);
            m0 = mn0; m1 = mn1;

            uint32_t eh0[8], eh1[8];
            float rs0 = 0.f, rs1 = 0.f;
            #pragma unroll
            for (int t=0; t<8; ++t){
                uint32_t d0 = h2u(__floats2half2_rn(p[t][0]-mn0, p[t][1]-mn0));
                uint32_t d1 = h2u(__floats2half2_rn(p[t][2]-mn1, p[t][3]-mn1));
                asm("ex2.approx.f16x2 %0,%1;" : "=r"(eh0[t]) : "r"(d0));
                asm("ex2.approx.f16x2 %0,%1;" : "=r"(eh1[t]) : "r"(d1));
                float2 f0 = __half22float2(*reinterpret_cast<__half2*>(&eh0[t]));
                float2 f1 = __half22float2(*reinterpret_cast<__half2*>(&eh1[t]));
                rs0 += f0.x + f0.y;
                rs1 += f1.x + f1.y;
            }
            rs0 += __shfl_xor_sync(~0u, rs0, 1); rs0 += __shfl_xor_sync(~0u, rs0, 2);
            rs1 += __shfl_xor_sync(~0u, rs1, 1); rs1 += __shfl_xor_sync(~0u, rs1, 2);
            l0 = l0*sc0 + rs0; l1 = l1*sc1 + rs1;

            // rescale O only when some row's max moved (warp vote)
            if (!__all_sync(~0u, (sc0==1.0f) && (sc1==1.0f))){
                #pragma unroll
                for (int t=0; t<16; ++t){
                    O[t][0]*=sc0; O[t][1]*=sc0; O[t][2]*=sc1; O[t][3]*=sc1;
                }
            }

            // ---- O += P V (1-term, pre-packed P) ----
            const uint32_t VB = ST + KVARR;
            #pragma unroll
            for (int kk=0; kk<4; ++kk){
                uint32_t pha[4];
                pha[0] = eh0[2*kk];   pha[1] = eh1[2*kk];
                pha[2] = eh0[2*kk+1]; pha[3] = eh1[2*kk+1];
                #pragma unroll
                for (int vp=0; vp<8; ++vp){
                    uint32_t vf[4];
                    LDSM4T(vf, VB + (kk*16 + vb_row)*AROWB + vp*32 + vb_col);
                    MMA_F16(O[2*vp],   pha, vf);
                    MMA_F16(O[2*vp+1], pha, vf+2);
                }
            }
        }
        __syncthreads();
    }

    float il0 = 1.0f/l0, il1 = 1.0f/l1;
    const size_t row0 = (size_t)(browg + q0 + w*16 + g);
    #pragma unroll
    for (int nt=0; nt<16; ++nt){
        size_t o0 = row0*QDIM + hh*HD + nt*8 + colc;
        size_t o1 = o0 + 8*QDIM;
        *(uint32_t*)&aoh[o0] = h2u(__floats2half2_rn(O[nt][0]*il0, O[nt][1]*il0));
        *(uint32_t*)&aoh[o1] = h2u(__floats2half2_rn(O[nt][2]*il1, O[nt][3]*il1));
    }
}

// ---------------------------------------------------------------------------
extern "C" void kernel_launch(void* const* d_in, const int* in_sizes, int n_in,
                              void* d_out, int out_size)
{
    const float* X  = (const float*)d_in[0];
    const float* Wq = (const float*)d_in[1];
    const float* Wk = (const float*)d_in[2];
    const float* Wv = (const float*)d_in[3];
    const float* Wo = (const float*)d_in[4];
    float* out = (float*)d_out;

    float *qkv;
    hlf *xh,*wf,*woh,*qh,*kh,*vh,*aoh;
    cudaGetSymbolAddress((void**)&qkv, g_QKV);
    cudaGetSymbolAddress((void**)&xh, g_xh);
    cudaGetSymbolAddress((void**)&wf, g_wf);
    cudaGetSymbolAddress((void**)&woh,g_woh);
    cudaGetSymbolAddress((void**)&qh, g_qh);
    cudaGetSymbolAddress((void**)&kh, g_kh);
    cudaGetSymbolAddress((void**)&vh, g_vh);
    cudaGetSymbolAddress((void**)&aoh,g_aoh);

    // one fused conversion launch (X + 4 weights)
    conv_all<<<28672, 256>>>(X, Wq, Wk, Wv, Wo, xh, wf, woh);

    // fused Q|K|V projection: one 1-term GEMM, N=6144
    cudaFuncSetAttribute(gemm_f16, cudaFuncAttributeMaxDynamicSharedMemorySize, GSMEM1);
    gemm_f16<<<dim3(QKVN/256, MROWS/128), 512, GSMEM1>>>(xh, wf, qkv, QKVN);

    // fused rope-Q + rope-K + conv-V
    postproc<<<43008, 256>>>(qkv, qh, kh, vh);

    cudaFuncSetAttribute(attn_mma, cudaFuncAttributeMaxDynamicSharedMemorySize, ASMEM);
    attn_mma<<<dim3(S_LEN/128, NH, 2), 256, ASMEM>>>(qh, kh, vh, aoh);

    gemm_f16<<<dim3(QDIM/256, MROWS/128), 512, GSMEM1>>>(aoh, woh, out, QDIM);
}

// round 12
// speedup vs baseline: 6.3102x; 1.0817x over previous
#include <cuda_runtime.h>
#include <cuda_fp16.h>
#include <math.h>
#include <stdint.h>

#define S_LEN 2048
#define HID   4096
#define NH    32
#define NKV   8
#define HD    128
#define WIN   1024
#define QDIM  4096
#define QKVN  6144
#define KVDIM 1024
#define MROWS 4096

typedef __half hlf;

__device__ hlf g_xh [(size_t)MROWS*HID];
__device__ hlf g_wf [(size_t)QKVN*HID];     // Wq|Wk|Wv
__device__ hlf g_woh[(size_t)HID*QDIM];
__device__ hlf g_qh [(size_t)MROWS*QDIM];
__device__ hlf g_kh [(size_t)MROWS*KVDIM];
__device__ hlf g_vh [(size_t)MROWS*KVDIM];
__device__ hlf g_aoh[(size_t)MROWS*QDIM];

// ---------------- PTX helpers ----------------
__device__ __forceinline__ uint32_t s2u(const void* p){
    uint32_t a;
    asm("{ .reg .u64 t; cvta.to.shared.u64 t,%1; cvt.u32.u64 %0,t; }":"=r"(a):"l"(p));
    return a;
}
#define CPA(dst,src) asm volatile( \
    "cp.async.cg.shared.global [%0],[%1],16;" :: "r"(dst),"l"(src) : "memory")
#define CPA_COMMIT() asm volatile("cp.async.commit_group;" ::: "memory")
#define CPA_WAIT0()  asm volatile("cp.async.wait_group 0;" ::: "memory")
#define CPA_WAIT1()  asm volatile("cp.async.wait_group 1;" ::: "memory")
#define CPA_WAIT2()  asm volatile("cp.async.wait_group 2;" ::: "memory")

#define LDSM4(r,addr) asm volatile( \
    "ldmatrix.sync.aligned.m8n8.x4.shared.b16 {%0,%1,%2,%3},[%4];" \
    : "=r"((r)[0]),"=r"((r)[1]),"=r"((r)[2]),"=r"((r)[3]) : "r"(addr))
#define LDSM4T(r,addr) asm volatile( \
    "ldmatrix.sync.aligned.m8n8.x4.trans.shared.b16 {%0,%1,%2,%3},[%4];" \
    : "=r"((r)[0]),"=r"((r)[1]),"=r"((r)[2]),"=r"((r)[3]) : "r"(addr))

#define MMA_F16(c,a,b) asm volatile( \
    "mma.sync.aligned.m16n8k16.row.col.f32.f16.f16.f32 " \
    "{%0,%1,%2,%3},{%4,%5,%6,%7},{%8,%9},{%0,%1,%2,%3};" \
    : "+f"((c)[0]),"+f"((c)[1]),"+f"((c)[2]),"+f"((c)[3]) \
    : "r"((a)[0]),"r"((a)[1]),"r"((a)[2]),"r"((a)[3]),"r"((b)[0]),"r"((b)[1]))

__device__ __forceinline__ uint32_t h2u(__half2 h){ return *reinterpret_cast<uint32_t*>(&h); }

// ---------------------------------------------------------------------------
// GEMM core pieces: CTA tile 128x256, BK=32, 512 thr, 4-stage cp.async
// ---------------------------------------------------------------------------
#define GK      4096
#define NCHG    128
#define ROWB    80
#define ST1_B   30720
#define OFF1_B  10240
#define GSMEM1  (4*ST1_B)   // 122880

static __device__ __forceinline__ void load_stage1(
    uint32_t sb, int stage, int kc, int m0, int n0, int tid,
    const hlf* __restrict__ A, const hlf* __restrict__ Bh)
{
    uint32_t st = sb + stage*ST1_B;
    {
        int r = tid>>2, ch = tid&3;
        uint32_t so = (uint32_t)(r*ROWB + ch*16);
        CPA(st+so, A + (size_t)(m0+r)*GK + kc + ch*8);
    }
    #pragma unroll
    for (int it=0; it<2; ++it){
        int idx = tid + it*512;
        int r = idx>>2, ch = idx&3;
        uint32_t so = (uint32_t)(r*ROWB + ch*16);
        CPA(st+OFF1_B+so, Bh + (size_t)(n0+r)*GK + kc + ch*8);
    }
    CPA_COMMIT();
}

// main K-loop; acc produced in registers
#define GEMM_MAIN(A_, B_, m0_, n0_)                                            \
    load_stage1(sb,0,0, m0_,n0_,tid,A_,B_);                                    \
    load_stage1(sb,1,32,m0_,n0_,tid,A_,B_);                                    \
    load_stage1(sb,2,64,m0_,n0_,tid,A_,B_);                                    \
    for (int c=0; c<NCHG; ++c){                                                \
        CPA_WAIT2();                                                           \
        __syncthreads();                                                       \
        if (c+3 < NCHG) load_stage1(sb,(c+3)&3,(c+3)*32, m0_,n0_,tid,A_,B_);   \
        else CPA_COMMIT();                                                     \
        const uint32_t st = sb + (c&3)*ST1_B;                                  \
        _Pragma("unroll")                                                      \
        for (int s=0; s<2; ++s){                                               \
            uint32_t ah[2][4];                                                 \
            _Pragma("unroll")                                                  \
            for (int mt=0; mt<2; ++mt)                                         \
                LDSM4(ah[mt], st + (a_row + mt*16)*ROWB + s*32 + a_colb);      \
            uint32_t bh[8][2];                                                 \
            _Pragma("unroll")                                                  \
            for (int p=0; p<4; ++p){                                           \
                uint32_t ba = st + OFF1_B + (b_row + p*16)*ROWB + s*32 + b_colb;\
                uint32_t r[4];                                                 \
                LDSM4(r, ba);                                                  \
                bh[2*p][0]=r[0]; bh[2*p][1]=r[1];                              \
                bh[2*p+1][0]=r[2]; bh[2*p+1][1]=r[3];                          \
            }                                                                  \
            _Pragma("unroll")                                                  \
            for (int mt=0; mt<2; ++mt)                                         \
                _Pragma("unroll")                                              \
                for (int nt=0; nt<8; ++nt)                                     \
                    MMA_F16(acc[mt][nt], ah[mt], bh[nt]);                      \
        }                                                                      \
    }

// ---------------------------------------------------------------------------
// Persistent QKV GEMM with fused rope/convert epilogue -> qh/kh/vh (fp16)
// tiles: 32 m x 24 n = 768, m-fast
// ---------------------------------------------------------------------------
__global__ void __launch_bounds__(512,1) gemm_qkv(
    const hlf* __restrict__ A, const hlf* __restrict__ Bh,
    hlf* __restrict__ qh, hlf* __restrict__ kh, hlf* __restrict__ vh)
{
    extern __shared__ __align__(128) char sm[];
    const uint32_t sb = s2u(sm);
    float* fstage = reinterpret_cast<float*>(sm);
    const int tid = threadIdx.x, wid = tid>>5, lane = tid&31;
    const int wm = wid&3, wn = wid>>2;
    const int g = lane>>2, tg = lane&3;
    const float SCL2 = 0.08838834764831845f * 1.4426950408889634f;

    const uint32_t a_row  = (uint32_t)(wm*32 + (lane&15));
    const uint32_t a_colb = (uint32_t)((lane>>4)*16);
    const uint32_t b_row  = (uint32_t)(wn*64 + (lane&7) + ((lane>>4)<<3));
    const uint32_t b_colb = (uint32_t)(((lane>>3)&1)*16);

    for (int tile = blockIdx.x; tile < 768; tile += gridDim.x){
        const int m0 = (tile & 31)*128, n0 = (tile >> 5)*256;

        float acc[2][8][4];
        #pragma unroll
        for (int i=0;i<2;++i)
            #pragma unroll
            for (int j=0;j<8;++j){acc[i][j][0]=0;acc[i][j][1]=0;acc[i][j][2]=0;acc[i][j][3]=0;}

        GEMM_MAIN(A, Bh, m0, n0)

        // ---- fused epilogue: two 128-col halves (each = one head) ----
        #pragma unroll
        for (int hf=0; hf<2; ++hf){
            __syncthreads();   // smem free (main loop / previous half done)
            if ((wn>>1) == hf){
                int cw = (wn&1)*64;
                #pragma unroll
                for (int mt=0; mt<2; ++mt)
                    #pragma unroll
                    for (int nt=0; nt<8; ++nt){
                        int r = wm*32 + mt*16 + g;
                        int cc = cw + nt*8 + tg*2;
                        fstage[r*132+cc]       = acc[mt][nt][0];
                        fstage[r*132+cc+1]     = acc[mt][nt][1];
                        fstage[(r+8)*132+cc]   = acc[mt][nt][2];
                        fstage[(r+8)*132+cc+1] = acc[mt][nt][3];
                    }
            }
            __syncthreads();

            const int ncol = n0 + hf*128;
            hlf* dst; int cbase, stride; float scale; bool isv = false;
            if (ncol < 4096)      { dst = qh; cbase = ncol;        stride = QDIM;  scale = SCL2; }
            else if (ncol < 5120) { dst = kh; cbase = ncol - 4096; stride = KVDIM; scale = 1.0f; }
            else                  { dst = vh; cbase = ncol - 5120; stride = KVDIM; scale = 1.0f; isv = true; }

            #pragma unroll
            for (int it=0; it<16; ++it){
                int idx = tid + it*512;     // 0..8191
                int r = idx >> 6, i = idx & 63;
                float x1 = fstage[r*132 + i], x2 = fstage[r*132 + i + 64];
                float y1, y2;
                if (isv){ y1 = x1; y2 = x2; }
                else {
                    int row = m0 + r;
                    int s = row & (S_LEN-1);
                    float inv = powf(10000.0f, -(float)i*(1.0f/64.0f));
                    float sn, cs; sincosf((float)s*inv, &sn, &cs);
                    y1 = (x1*cs - x2*sn)*scale;
                    y2 = (x2*cs + x1*sn)*scale;
                }
                size_t o = (size_t)(m0 + r)*stride + cbase + i;
                dst[o]      = __float2half_rn(y1);
                dst[o + 64] = __float2half_rn(y2);
            }
        }
        __syncthreads();
    }
}

// ---------------------------------------------------------------------------
// Persistent O-projection GEMM (fp32 out). tiles: 32 m x 16 n = 512, m-fast
// ---------------------------------------------------------------------------
__global__ void __launch_bounds__(512,1) gemm_out(
    const hlf* __restrict__ A, const hlf* __restrict__ Bh,
    float* __restrict__ C)
{
    extern __shared__ __align__(128) char sm[];
    const uint32_t sb = s2u(sm);
    const int tid = threadIdx.x, wid = tid>>5, lane = tid&31;
    const int wm = wid&3, wn = wid>>2;
    const int g = lane>>2, tg = lane&3;

    const uint32_t a_row  = (uint32_t)(wm*32 + (lane&15));
    const uint32_t a_colb = (uint32_t)((lane>>4)*16);
    const uint32_t b_row  = (uint32_t)(wn*64 + (lane&7) + ((lane>>4)<<3));
    const uint32_t b_colb = (uint32_t)(((lane>>3)&1)*16);

    for (int tile = blockIdx.x; tile < 512; tile += gridDim.x){
        const int m0 = (tile & 31)*128, n0 = (tile >> 5)*256;

        float acc[2][8][4];
        #pragma unroll
        for (int i=0;i<2;++i)
            #pragma unroll
            for (int j=0;j<8;++j){acc[i][j][0]=0;acc[i][j][1]=0;acc[i][j][2]=0;acc[i][j][3]=0;}

        GEMM_MAIN(A, Bh, m0, n0)

        #pragma unroll
        for (int mt=0; mt<2; ++mt)
            #pragma unroll
            for (int nt=0; nt<8; ++nt){
                int row = m0 + wm*32 + mt*16 + g;
                int col = n0 + wn*64 + nt*8 + tg*2;
                float2 v0 = {acc[mt][nt][0], acc[mt][nt][1]};
                float2 v1 = {acc[mt][nt][2], acc[mt][nt][3]};
                *(float2*)&C[(size_t)row*QDIM + col]     = v0;
                *(float2*)&C[(size_t)(row+8)*QDIM + col] = v1;
            }
        __syncthreads();
    }
}

// ---------------------------------------------------------------------------
// fused fp32->fp16 conversion of X + all weights (one launch)
// ---------------------------------------------------------------------------
__global__ void conv_all(const float* __restrict__ X,  const float* __restrict__ Wq,
                         const float* __restrict__ Wk, const float* __restrict__ Wv,
                         const float* __restrict__ Wo,
                         hlf* __restrict__ xh, hlf* __restrict__ wf, hlf* __restrict__ woh)
{
    const size_t QW  = (size_t)QDIM*HID;
    const size_t KVW = (size_t)1024*HID;
    int bid = blockIdx.x;
    const float* src; hlf* dst; int rel;
    if      (bid <  8192){ src = X;  dst = xh;             rel = bid; }
    else if (bid < 16384){ src = Wq; dst = wf;             rel = bid-8192; }
    else if (bid < 18432){ src = Wk; dst = wf + QW;        rel = bid-16384; }
    else if (bid < 20480){ src = Wv; dst = wf + QW + KVW;  rel = bid-18432; }
    else                 { src = Wo; dst = woh;            rel = bid-20480; }
    size_t i = ((size_t)rel*256 + threadIdx.x)*8;
    #pragma unroll
    for (int u=0; u<2; ++u){
        float4 v = *(const float4*)(src+i+u*4);
        *(uint32_t*)&dst[i+u*4]   = h2u(__floats2half2_rn(v.x, v.y));
        *(uint32_t*)&dst[i+u*4+2] = h2u(__floats2half2_rn(v.z, v.w));
    }
}

// ---------------------------------------------------------------------------
// fp16 HMMA flash attention (QK 1-term, f16x2 EX2 softmax, vote rescale-skip)
// ---------------------------------------------------------------------------
#define AROWB 272
#define QSZ   34816
#define KVARR 17408
#define KVSTG 34816
#define ASMEM (QSZ + 2*KVSTG)   // 104448

static __device__ __forceinline__ void a_load_kv(
    uint32_t st, int kbase, int brow, int tid, int kvh,
    const hlf* __restrict__ kh, const hlf* __restrict__ vh)
{
    #pragma unroll
    for (int it=0; it<4; ++it){
        int idx = tid + it*256;
        int r = idx>>4, ch = idx&15;
        uint32_t so = (uint32_t)(r*AROWB + ch*16);
        size_t gsrc = (size_t)(brow + kbase + r)*KVDIM + kvh*HD + ch*8;
        CPA(st + so,         kh + gsrc);
        CPA(st + KVARR + so, vh + gsrc);
    }
    CPA_COMMIT();
}

__global__ void __launch_bounds__(256,1) attn_mma(
    const hlf* __restrict__ qh_, const hlf* __restrict__ kh_,
    const hlf* __restrict__ vh_, hlf* __restrict__ aoh)
{
    extern __shared__ __align__(128) char sm[];
    const uint32_t sb = s2u(sm);
    const uint32_t QH = sb, ST0 = sb + QSZ;

    const int tid = threadIdx.x, w = tid>>5, lane = tid&31;
    const int qb = (int)(gridDim.x - 1 - blockIdx.x);
    const int hh = blockIdx.y, b = blockIdx.z;
    const int q0 = qb*128, kvh = hh>>2;
    const int g = lane>>2, colc = (lane&3)*2;
    const int browg = b*S_LEN;

    #pragma unroll
    for (int it=0; it<8; ++it){
        int idx = tid + it*256;
        int r = idx>>4, ch = idx&15;
        uint32_t so = (uint32_t)(r*AROWB + ch*16);
        CPA(QH + so, qh_ + (size_t)(browg + q0 + r)*QDIM + hh*HD + ch*8);
    }
    CPA_COMMIT();

    int lo = q0 - (WIN-1); if (lo < 0) lo = 0;
    const int kt0 = lo >> 6, ktend = 2*qb + 1;

    a_load_kv(ST0, kt0*64, browg, tid, kvh, kh_, vh_);

    uint32_t qfh[8][4];
    float O[16][4];
    #pragma unroll
    for (int t=0;t<16;++t){O[t][0]=0;O[t][1]=0;O[t][2]=0;O[t][3]=0;}
    float m0 = -1e30f, m1 = -1e30f, l0 = 0.f, l1 = 0.f;

    const uint32_t a_row  = (uint32_t)(w*16 + (lane&15));
    const uint32_t a_colb = (uint32_t)((lane>>4)*16);
    const uint32_t kb_row = (uint32_t)((lane&7) + ((lane>>4)<<3));
    const uint32_t kb_col = (uint32_t)(((lane>>3)&1)*16);
    const uint32_t vb_row = (uint32_t)((lane&7) + (lane&8));
    const uint32_t vb_col = (uint32_t)((lane>>4)*16);

    const int rmin_w = q0 + w*16;

    for (int kt = kt0; kt <= ktend; ++kt){
        const int s = (kt - kt0) & 1;
        const uint32_t ST = ST0 + (uint32_t)s*KVSTG;
        if (kt < ktend){
            a_load_kv(ST0 + (uint32_t)(s^1)*KVSTG, (kt+1)*64, browg, tid, kvh, kh_, vh_);
            CPA_WAIT1();
        } else {
            CPA_WAIT0();
        }
        __syncthreads();

        if (kt == kt0){
            #pragma unroll
            for (int kk=0; kk<8; ++kk)
                LDSM4(qfh[kk], QH + a_row*AROWB + kk*32 + a_colb);
        }

        const int kbase = kt*64;
        if ((kbase <= rmin_w + 15) && (kbase + 63 > rmin_w - WIN)){
            float p[8][4];
            #pragma unroll
            for (int t=0;t<8;++t){p[t][0]=0;p[t][1]=0;p[t][2]=0;p[t][3]=0;}
            #pragma unroll
            for (int kk=0; kk<8; ++kk){
                #pragma unroll
                for (int np=0; np<4; ++np){
                    uint32_t kf[4];
                    LDSM4(kf, ST + (np*16 + kb_row)*AROWB + kk*32 + kb_col);
                    MMA_F16(p[2*np],   qfh[kk], kf);
                    MMA_F16(p[2*np+1], qfh[kk], kf+2);
                }
            }

            const int r0 = rmin_w + g, r1 = r0 + 8;
            const bool full = (kbase + 63 <= rmin_w) && (kbase >= rmin_w + 16 - WIN);
            if (!full){
                #pragma unroll
                for (int t=0; t<8; ++t){
                    #pragma unroll
                    for (int e=0; e<2; ++e){
                        int kj = kbase + t*8 + colc + e;
                        if (!((kj<=r0)&&(r0-kj<WIN))) p[t][e]   = -1e30f;
                        if (!((kj<=r1)&&(r1-kj<WIN))) p[t][2+e] = -1e30f;
                    }
                }
            }
            float rm0 = -1e30f, rm1 = -1e30f;
            #pragma unroll
            for (int t=0; t<8; ++t){
                rm0 = fmaxf(rm0, fmaxf(p[t][0], p[t][1]));
                rm1 = fmaxf(rm1, fmaxf(p[t][2], p[t][3]));
            }
            rm0 = fmaxf(rm0, __shfl_xor_sync(~0u, rm0, 1));
            rm0 = fmaxf(rm0, __shfl_xor_sync(~0u, rm0, 2));
            rm1 = fmaxf(rm1, __shfl_xor_sync(~0u, rm1, 1));
            rm1 = fmaxf(rm1, __shfl_xor_sync(~0u, rm1, 2));
            float mn0 = fmaxf(m0, rm0), mn1 = fmaxf(m1, rm1);
            float sc0 = exp2f(m0 - mn0), sc1 = exp2f(m1 - mn1);
            m0 = mn0; m1 = mn1;

            uint32_t eh0[8], eh1[8];
            float rs0 = 0.f, rs1 = 0.f;
            #pragma unroll
            for (int t=0; t<8; ++t){
                uint32_t d0 = h2u(__floats2half2_rn(p[t][0]-mn0, p[t][1]-mn0));
                uint32_t d1 = h2u(__floats2half2_rn(p[t][2]-mn1, p[t][3]-mn1));
                asm("ex2.approx.f16x2 %0,%1;" : "=r"(eh0[t]) : "r"(d0));
                asm("ex2.approx.f16x2 %0,%1;" : "=r"(eh1[t]) : "r"(d1));
                float2 f0 = __half22float2(*reinterpret_cast<__half2*>(&eh0[t]));
                float2 f1 = __half22float2(*reinterpret_cast<__half2*>(&eh1[t]));
                rs0 += f0.x + f0.y;
                rs1 += f1.x + f1.y;
            }
            rs0 += __shfl_xor_sync(~0u, rs0, 1); rs0 += __shfl_xor_sync(~0u, rs0, 2);
            rs1 += __shfl_xor_sync(~0u, rs1, 1); rs1 += __shfl_xor_sync(~0u, rs1, 2);
            l0 = l0*sc0 + rs0; l1 = l1*sc1 + rs1;

            if (!__all_sync(~0u, (sc0==1.0f) && (sc1==1.0f))){
                #pragma unroll
                for (int t=0; t<16; ++t){
                    O[t][0]*=sc0; O[t][1]*=sc0; O[t][2]*=sc1; O[t][3]*=sc1;
                }
            }

            const uint32_t VB = ST + KVARR;
            #pragma unroll
            for (int kk=0; kk<4; ++kk){
                uint32_t pha[4];
                pha[0] = eh0[2*kk];   pha[1] = eh1[2*kk];
                pha[2] = eh0[2*kk+1]; pha[3] = eh1[2*kk+1];
                #pragma unroll
                for (int vp=0; vp<8; ++vp){
                    uint32_t vf[4];
                    LDSM4T(vf, VB + (kk*16 + vb_row)*AROWB + vp*32 + vb_col);
                    MMA_F16(O[2*vp],   pha, vf);
                    MMA_F16(O[2*vp+1], pha, vf+2);
                }
            }
        }
        __syncthreads();
    }

    float il0 = 1.0f/l0, il1 = 1.0f/l1;
    const size_t row0 = (size_t)(browg + q0 + w*16 + g);
    #pragma unroll
    for (int nt=0; nt<16; ++nt){
        size_t o0 = row0*QDIM + hh*HD + nt*8 + colc;
        size_t o1 = o0 + 8*QDIM;
        *(uint32_t*)&aoh[o0] = h2u(__floats2half2_rn(O[nt][0]*il0, O[nt][1]*il0));
        *(uint32_t*)&aoh[o1] = h2u(__floats2half2_rn(O[nt][2]*il1, O[nt][3]*il1));
    }
}

// ---------------------------------------------------------------------------
extern "C" void kernel_launch(void* const* d_in, const int* in_sizes, int n_in,
                              void* d_out, int out_size)
{
    const float* X  = (const float*)d_in[0];
    const float* Wq = (const float*)d_in[1];
    const float* Wk = (const float*)d_in[2];
    const float* Wv = (const float*)d_in[3];
    const float* Wo = (const float*)d_in[4];
    float* out = (float*)d_out;

    hlf *xh,*wf,*woh,*qh,*kh,*vh,*aoh;
    cudaGetSymbolAddress((void**)&xh, g_xh);
    cudaGetSymbolAddress((void**)&wf, g_wf);
    cudaGetSymbolAddress((void**)&woh,g_woh);
    cudaGetSymbolAddress((void**)&qh, g_qh);
    cudaGetSymbolAddress((void**)&kh, g_kh);
    cudaGetSymbolAddress((void**)&vh, g_vh);
    cudaGetSymbolAddress((void**)&aoh,g_aoh);

    // one fused conversion launch (X + 4 weights)
    conv_all<<<28672, 256>>>(X, Wq, Wk, Wv, Wo, xh, wf, woh);

    // persistent QKV GEMM with fused rope/convert epilogue
    cudaFuncSetAttribute(gemm_qkv, cudaFuncAttributeMaxDynamicSharedMemorySize, GSMEM1);
    gemm_qkv<<<148, 512, GSMEM1>>>(xh, wf, qh, kh, vh);

    cudaFuncSetAttribute(attn_mma, cudaFuncAttributeMaxDynamicSharedMemorySize, ASMEM);
    attn_mma<<<dim3(S_LEN/128, NH, 2), 256, ASMEM>>>(qh, kh, vh, aoh);

    // persistent O projection
    cudaFuncSetAttribute(gemm_out, cudaFuncAttributeMaxDynamicSharedMemorySize, GSMEM1);
    gemm_out<<<148, 512, GSMEM1>>>(aoh, woh, out);
}

// round 13
// speedup vs baseline: 7.1732x; 1.1368x over previous
#include <cuda_runtime.h>
#include <cuda_fp16.h>
#include <math.h>
#include <stdint.h>

#define S_LEN 2048
#define HID   4096
#define NH    32
#define NKV   8
#define HD    128
#define WIN   1024
#define QDIM  4096
#define QKVN  6144
#define KVDIM 1024
#define MROWS 4096

typedef __half hlf;

__device__ hlf g_xh [(size_t)MROWS*HID];
__device__ hlf g_wf [(size_t)QKVN*HID];     // Wq|Wk|Wv
__device__ hlf g_woh[(size_t)HID*QDIM];
__device__ hlf g_qh [(size_t)MROWS*QDIM];
__device__ hlf g_kh [(size_t)MROWS*KVDIM];
__device__ hlf g_vh [(size_t)MROWS*KVDIM];
__device__ hlf g_aoh[(size_t)MROWS*QDIM];

// ---------------- PTX helpers ----------------
__device__ __forceinline__ uint32_t s2u(const void* p){
    uint32_t a;
    asm("{ .reg .u64 t; cvta.to.shared.u64 t,%1; cvt.u32.u64 %0,t; }":"=r"(a):"l"(p));
    return a;
}
#define CPA(dst,src) asm volatile( \
    "cp.async.cg.shared.global [%0],[%1],16;" :: "r"(dst),"l"(src) : "memory")
#define CPA_COMMIT() asm volatile("cp.async.commit_group;" ::: "memory")
#define CPA_WAIT0()  asm volatile("cp.async.wait_group 0;" ::: "memory")
#define CPA_WAIT1()  asm volatile("cp.async.wait_group 1;" ::: "memory")

#define LDSM4(r,addr) asm volatile( \
    "ldmatrix.sync.aligned.m8n8.x4.shared.b16 {%0,%1,%2,%3},[%4];" \
    : "=r"((r)[0]),"=r"((r)[1]),"=r"((r)[2]),"=r"((r)[3]) : "r"(addr))
#define LDSM4T(r,addr) asm volatile( \
    "ldmatrix.sync.aligned.m8n8.x4.trans.shared.b16 {%0,%1,%2,%3},[%4];" \
    : "=r"((r)[0]),"=r"((r)[1]),"=r"((r)[2]),"=r"((r)[3]) : "r"(addr))

#define MMA_F16(c,a,b) asm volatile( \
    "mma.sync.aligned.m16n8k16.row.col.f32.f16.f16.f32 " \
    "{%0,%1,%2,%3},{%4,%5,%6,%7},{%8,%9},{%0,%1,%2,%3};" \
    : "+f"((c)[0]),"+f"((c)[1]),"+f"((c)[2]),"+f"((c)[3]) \
    : "r"((a)[0]),"r"((a)[1]),"r"((a)[2]),"r"((a)[3]),"r"((b)[0]),"r"((b)[1]))

__device__ __forceinline__ uint32_t h2u(__half2 h){ return *reinterpret_cast<uint32_t*>(&h); }

// ---------------------------------------------------------------------------
// GEMM core: CTA tile 128x128, 256 thr (8 warps 4m x 2n), BK=32, 3-stage.
// smem/CTA = 61440 -> 2 CTAs/SM; regs capped 128 via launch_bounds(256,2).
// ---------------------------------------------------------------------------
#define GK      4096
#define NCHG    128
#define ROWB    80
#define STG2_B  20480      // A 10240 + B 10240
#define OFFB2   10240
#define GSMEM2  (3*STG2_B) // 61440

static __device__ __forceinline__ void load_stage2(
    uint32_t sb, int stage, int kc, int m0, int n0, int tid,
    const hlf* __restrict__ A, const hlf* __restrict__ Bh)
{
    uint32_t st = sb + stage*STG2_B;
    #pragma unroll
    for (int it=0; it<2; ++it){
        int idx = tid + it*256;
        int r = idx>>2, ch = idx&3;
        uint32_t so = (uint32_t)(r*ROWB + ch*16);
        CPA(st+so,        A  + (size_t)(m0+r)*GK + kc + ch*8);
        CPA(st+OFFB2+so,  Bh + (size_t)(n0+r)*GK + kc + ch*8);
    }
    CPA_COMMIT();
}

// main K-loop (3-stage); acc in registers
#define GEMM_MAIN2(A_, B_, m0_, n0_)                                           \
    load_stage2(sb,0,0, m0_,n0_,tid,A_,B_);                                    \
    load_stage2(sb,1,32,m0_,n0_,tid,A_,B_);                                    \
    {                                                                          \
        int stg = 0;                                                           \
        for (int c=0; c<NCHG; ++c){                                            \
            CPA_WAIT1();                                                       \
            __syncthreads();                                                   \
            if (c+2 < NCHG){                                                   \
                int ns = stg+2; if (ns>=3) ns-=3;                              \
                load_stage2(sb,ns,(c+2)*32, m0_,n0_,tid,A_,B_);                \
            } else CPA_COMMIT();                                               \
            const uint32_t st = sb + stg*STG2_B;                               \
            _Pragma("unroll")                                                  \
            for (int s=0; s<2; ++s){                                           \
                uint32_t ah[2][4];                                             \
                _Pragma("unroll")                                              \
                for (int mt=0; mt<2; ++mt)                                     \
                    LDSM4(ah[mt], st + (a_row + mt*16)*ROWB + s*32 + a_colb);  \
                uint32_t bh[8][2];                                             \
                _Pragma("unroll")                                              \
                for (int p=0; p<4; ++p){                                       \
                    uint32_t ba = st + OFFB2 + (b_row + p*16)*ROWB + s*32 + b_colb;\
                    uint32_t r[4];                                             \
                    LDSM4(r, ba);                                              \
                    bh[2*p][0]=r[0]; bh[2*p][1]=r[1];                          \
                    bh[2*p+1][0]=r[2]; bh[2*p+1][1]=r[3];                      \
                }                                                              \
                _Pragma("unroll")                                              \
                for (int mt=0; mt<2; ++mt)                                     \
                    _Pragma("unroll")                                          \
                    for (int nt=0; nt<8; ++nt)                                 \
                        MMA_F16(acc[mt][nt], ah[mt], bh[nt]);                  \
            }                                                                  \
            if (++stg >= 3) stg = 0;                                           \
        }                                                                      \
    }

// ---------------------------------------------------------------------------
// Persistent QKV GEMM with fused rope/convert epilogue -> qh/kh/vh
// tiles: 32 m x 48 n = 1536 (each n-tile = one 128-col head), m-fast
// ---------------------------------------------------------------------------
__global__ void __launch_bounds__(256,2) gemm_qkv(
    const hlf* __restrict__ A, const hlf* __restrict__ Bh,
    hlf* __restrict__ qh, hlf* __restrict__ kh, hlf* __restrict__ vh)
{
    extern __shared__ __align__(128) char sm[];
    const uint32_t sb = s2u(sm);
    float* fstage = reinterpret_cast<float*>(sm);
    const int tid = threadIdx.x, wid = tid>>5, lane = tid&31;
    const int wm = wid&3, wn = wid>>2;
    const int g = lane>>2, tg = lane&3;
    const float SCL2 = 0.08838834764831845f * 1.4426950408889634f;

    const uint32_t a_row  = (uint32_t)(wm*32 + (lane&15));
    const uint32_t a_colb = (uint32_t)((lane>>4)*16);
    const uint32_t b_row  = (uint32_t)(wn*64 + (lane&7) + ((lane>>4)<<3));
    const uint32_t b_colb = (uint32_t)(((lane>>3)&1)*16);

    for (int tile = blockIdx.x; tile < 1536; tile += gridDim.x){
        const int m0 = (tile & 31)*128, n0 = (tile >> 5)*128;

        float acc[2][8][4];
        #pragma unroll
        for (int i=0;i<2;++i)
            #pragma unroll
            for (int j=0;j<8;++j){acc[i][j][0]=0;acc[i][j][1]=0;acc[i][j][2]=0;acc[i][j][3]=0;}

        GEMM_MAIN2(A, Bh, m0, n0)

        // destination segment for this head tile
        hlf* dst; int cbase, stride; float scale; bool isv = false;
        if (n0 < 4096)      { dst = qh; cbase = n0;        stride = QDIM;  scale = SCL2; }
        else if (n0 < 5120) { dst = kh; cbase = n0 - 4096; stride = KVDIM; scale = 1.0f; }
        else                { dst = vh; cbase = n0 - 5120; stride = KVDIM; scale = 1.0f; isv = true; }

        // fused epilogue in two 64-row halves (fstage 64x132 fp32 = 33792 B)
        #pragma unroll
        for (int mh=0; mh<2; ++mh){
            __syncthreads();
            if ((wm>>1) == mh){
                int rbase = (wm&1)*32;
                #pragma unroll
                for (int mt=0; mt<2; ++mt)
                    #pragma unroll
                    for (int nt=0; nt<8; ++nt){
                        int r = rbase + mt*16 + g;
                        int cc = wn*64 + nt*8 + tg*2;
                        fstage[r*132+cc]       = acc[mt][nt][0];
                        fstage[r*132+cc+1]     = acc[mt][nt][1];
                        fstage[(r+8)*132+cc]   = acc[mt][nt][2];
                        fstage[(r+8)*132+cc+1] = acc[mt][nt][3];
                    }
            }
            __syncthreads();

            #pragma unroll
            for (int it=0; it<16; ++it){
                int idx = tid + it*256;     // 0..4095 pairs
                int r = idx >> 6, i = idx & 63;
                float x1 = fstage[r*132 + i], x2 = fstage[r*132 + i + 64];
                float y1, y2;
                if (isv){ y1 = x1; y2 = x2; }
                else {
                    int row = m0 + mh*64 + r;
                    int s = row & (S_LEN-1);
                    float inv = powf(10000.0f, -(float)i*(1.0f/64.0f));
                    float sn, cs; sincosf((float)s*inv, &sn, &cs);
                    y1 = (x1*cs - x2*sn)*scale;
                    y2 = (x2*cs + x1*sn)*scale;
                }
                size_t o = (size_t)(m0 + mh*64 + r)*stride + cbase + i;
                dst[o]      = __float2half_rn(y1);
                dst[o + 64] = __float2half_rn(y2);
            }
        }
        __syncthreads();
    }
}

// ---------------------------------------------------------------------------
// Persistent O-projection GEMM (fp32 out). tiles: 32 m x 32 n = 1024, m-fast
// ---------------------------------------------------------------------------
__global__ void __launch_bounds__(256,2) gemm_out(
    const hlf* __restrict__ A, const hlf* __restrict__ Bh,
    float* __restrict__ C)
{
    extern __shared__ __align__(128) char sm[];
    const uint32_t sb = s2u(sm);
    const int tid = threadIdx.x, wid = tid>>5, lane = tid&31;
    const int wm = wid&3, wn = wid>>2;
    const int g = lane>>2, tg = lane&3;

    const uint32_t a_row  = (uint32_t)(wm*32 + (lane&15));
    const uint32_t a_colb = (uint32_t)((lane>>4)*16);
    const uint32_t b_row  = (uint32_t)(wn*64 + (lane&7) + ((lane>>4)<<3));
    const uint32_t b_colb = (uint32_t)(((lane>>3)&1)*16);

    for (int tile = blockIdx.x; tile < 1024; tile += gridDim.x){
        const int m0 = (tile & 31)*128, n0 = (tile >> 5)*128;

        float acc[2][8][4];
        #pragma unroll
        for (int i=0;i<2;++i)
            #pragma unroll
            for (int j=0;j<8;++j){acc[i][j][0]=0;acc[i][j][1]=0;acc[i][j][2]=0;acc[i][j][3]=0;}

        GEMM_MAIN2(A, Bh, m0, n0)

        #pragma unroll
        for (int mt=0; mt<2; ++mt)
            #pragma unroll
            for (int nt=0; nt<8; ++nt){
                int row = m0 + wm*32 + mt*16 + g;
                int col = n0 + wn*64 + nt*8 + tg*2;
                float2 v0 = {acc[mt][nt][0], acc[mt][nt][1]};
                float2 v1 = {acc[mt][nt][2], acc[mt][nt][3]};
                *(float2*)&C[(size_t)row*QDIM + col]     = v0;
                *(float2*)&C[(size_t)(row+8)*QDIM + col] = v1;
            }
        __syncthreads();
    }
}

// ---------------------------------------------------------------------------
// fused fp32->fp16 conversion (one launch, 16 elems/thread)
// segments (blocks of 4096 elems): X 4096 | Wq 4096 | Wk 1024 | Wv 1024 | Wo 4096
// ---------------------------------------------------------------------------
__global__ void conv_all(const float* __restrict__ X,  const float* __restrict__ Wq,
                         const float* __restrict__ Wk, const float* __restrict__ Wv,
                         const float* __restrict__ Wo,
                         hlf* __restrict__ xh, hlf* __restrict__ wf, hlf* __restrict__ woh)
{
    const size_t QW  = (size_t)QDIM*HID;
    const size_t KVW = (size_t)1024*HID;
    int bid = blockIdx.x;
    const float* src; hlf* dst; int rel;
    if      (bid <  4096){ src = X;  dst = xh;             rel = bid; }
    else if (bid <  8192){ src = Wq; dst = wf;             rel = bid-4096; }
    else if (bid <  9216){ src = Wk; dst = wf + QW;        rel = bid-8192; }
    else if (bid < 10240){ src = Wv; dst = wf + QW + KVW;  rel = bid-9216; }
    else                 { src = Wo; dst = woh;            rel = bid-10240; }
    size_t i = ((size_t)rel*256 + threadIdx.x)*16;
    float4 v0 = *(const float4*)(src+i);
    float4 v1 = *(const float4*)(src+i+4);
    float4 v2 = *(const float4*)(src+i+8);
    float4 v3 = *(const float4*)(src+i+12);
    uint2 o0, o1;
    o0.x = h2u(__floats2half2_rn(v0.x, v0.y)); o0.y = h2u(__floats2half2_rn(v0.z, v0.w));
    o1.x = h2u(__floats2half2_rn(v1.x, v1.y)); o1.y = h2u(__floats2half2_rn(v1.z, v1.w));
    *(uint2*)&dst[i]   = o0;
    *(uint2*)&dst[i+4] = o1;
    o0.x = h2u(__floats2half2_rn(v2.x, v2.y)); o0.y = h2u(__floats2half2_rn(v2.z, v2.w));
    o1.x = h2u(__floats2half2_rn(v3.x, v3.y)); o1.y = h2u(__floats2half2_rn(v3.z, v3.w));
    *(uint2*)&dst[i+8]  = o0;
    *(uint2*)&dst[i+12] = o1;
}

// ---------------------------------------------------------------------------
// fp16 HMMA flash attention (unchanged from R11/12)
// ---------------------------------------------------------------------------
#define AROWB 272
#define QSZ   34816
#define KVARR 17408
#define KVSTG 34816
#define ASMEM (QSZ + 2*KVSTG)   // 104448

static __device__ __forceinline__ void a_load_kv(
    uint32_t st, int kbase, int brow, int tid, int kvh,
    const hlf* __restrict__ kh, const hlf* __restrict__ vh)
{
    #pragma unroll
    for (int it=0; it<4; ++it){
        int idx = tid + it*256;
        int r = idx>>4, ch = idx&15;
        uint32_t so = (uint32_t)(r*AROWB + ch*16);
        size_t gsrc = (size_t)(brow + kbase + r)*KVDIM + kvh*HD + ch*8;
        CPA(st + so,         kh + gsrc);
        CPA(st + KVARR + so, vh + gsrc);
    }
    CPA_COMMIT();
}

__global__ void __launch_bounds__(256,1) attn_mma(
    const hlf* __restrict__ qh_, const hlf* __restrict__ kh_,
    const hlf* __restrict__ vh_, hlf* __restrict__ aoh)
{
    extern __shared__ __align__(128) char sm[];
    const uint32_t sb = s2u(sm);
    const uint32_t QH = sb, ST0 = sb + QSZ;

    const int tid = threadIdx.x, w = tid>>5, lane = tid&31;
    const int qb = (int)(gridDim.x - 1 - blockIdx.x);
    const int hh = blockIdx.y, b = blockIdx.z;
    const int q0 = qb*128, kvh = hh>>2;
    const int g = lane>>2, colc = (lane&3)*2;
    const int browg = b*S_LEN;

    #pragma unroll
    for (int it=0; it<8; ++it){
        int idx = tid + it*256;
        int r = idx>>4, ch = idx&15;
        uint32_t so = (uint32_t)(r*AROWB + ch*16);
        CPA(QH + so, qh_ + (size_t)(browg + q0 + r)*QDIM + hh*HD + ch*8);
    }
    CPA_COMMIT();

    int lo = q0 - (WIN-1); if (lo < 0) lo = 0;
    const int kt0 = lo >> 6, ktend = 2*qb + 1;

    a_load_kv(ST0, kt0*64, browg, tid, kvh, kh_, vh_);

    uint32_t qfh[8][4];
    float O[16][4];
    #pragma unroll
    for (int t=0;t<16;++t){O[t][0]=0;O[t][1]=0;O[t][2]=0;O[t][3]=0;}
    float m0 = -1e30f, m1 = -1e30f, l0 = 0.f, l1 = 0.f;

    const uint32_t a_row  = (uint32_t)(w*16 + (lane&15));
    const uint32_t a_colb = (uint32_t)((lane>>4)*16);
    const uint32_t kb_row = (uint32_t)((lane&7) + ((lane>>4)<<3));
    const uint32_t kb_col = (uint32_t)(((lane>>3)&1)*16);
    const uint32_t vb_row = (uint32_t)((lane&7) + (lane&8));
    const uint32_t vb_col = (uint32_t)((lane>>4)*16);

    const int rmin_w = q0 + w*16;

    for (int kt = kt0; kt <= ktend; ++kt){
        const int s = (kt - kt0) & 1;
        const uint32_t ST = ST0 + (uint32_t)s*KVSTG;
        if (kt < ktend){
            a_load_kv(ST0 + (uint32_t)(s^1)*KVSTG, (kt+1)*64, browg, tid, kvh, kh_, vh_);
            CPA_WAIT1();
        } else {
            CPA_WAIT0();
        }
        __syncthreads();

        if (kt == kt0){
            #pragma unroll
            for (int kk=0; kk<8; ++kk)
                LDSM4(qfh[kk], QH + a_row*AROWB + kk*32 + a_colb);
        }

        const int kbase = kt*64;
        if ((kbase <= rmin_w + 15) && (kbase + 63 > rmin_w - WIN)){
            float p[8][4];
            #pragma unroll
            for (int t=0;t<8;++t){p[t][0]=0;p[t][1]=0;p[t][2]=0;p[t][3]=0;}
            #pragma unroll
            for (int kk=0; kk<8; ++kk){
                #pragma unroll
                for (int np=0; np<4; ++np){
                    uint32_t kf[4];
                    LDSM4(kf, ST + (np*16 + kb_row)*AROWB + kk*32 + kb_col);
                    MMA_F16(p[2*np],   qfh[kk], kf);
                    MMA_F16(p[2*np+1], qfh[kk], kf+2);
                }
            }

            const int r0 = rmin_w + g, r1 = r0 + 8;
            const bool full = (kbase + 63 <= rmin_w) && (kbase >= rmin_w + 16 - WIN);
            if (!full){
                #pragma unroll
                for (int t=0; t<8; ++t){
                    #pragma unroll
                    for (int e=0; e<2; ++e){
                        int kj = kbase + t*8 + colc + e;
                        if (!((kj<=r0)&&(r0-kj<WIN))) p[t][e]   = -1e30f;
                        if (!((kj<=r1)&&(r1-kj<WIN))) p[t][2+e] = -1e30f;
                    }
                }
            }
            float rm0 = -1e30f, rm1 = -1e30f;
            #pragma unroll
            for (int t=0; t<8; ++t){
                rm0 = fmaxf(rm0, fmaxf(p[t][0], p[t][1]));
                rm1 = fmaxf(rm1, fmaxf(p[t][2], p[t][3]));
            }
            rm0 = fmaxf(rm0, __shfl_xor_sync(~0u, rm0, 1));
            rm0 = fmaxf(rm0, __shfl_xor_sync(~0u, rm0, 2));
            rm1 = fmaxf(rm1, __shfl_xor_sync(~0u, rm1, 1));
            rm1 = fmaxf(rm1, __shfl_xor_sync(~0u, rm1, 2));
            float mn0 = fmaxf(m0, rm0), mn1 = fmaxf(m1, rm1);
            float sc0 = exp2f(m0 - mn0), sc1 = exp2f(m1 - mn1);
            m0 = mn0; m1 = mn1;

            uint32_t eh0[8], eh1[8];
            float rs0 = 0.f, rs1 = 0.f;
            #pragma unroll
            for (int t=0; t<8; ++t){
                uint32_t d0 = h2u(__floats2half2_rn(p[t][0]-mn0, p[t][1]-mn0));
                uint32_t d1 = h2u(__floats2half2_rn(p[t][2]-mn1, p[t][3]-mn1));
                asm("ex2.approx.f16x2 %0,%1;" : "=r"(eh0[t]) : "r"(d0));
                asm("ex2.approx.f16x2 %0,%1;" : "=r"(eh1[t]) : "r"(d1));
                float2 f0 = __half22float2(*reinterpret_cast<__half2*>(&eh0[t]));
                float2 f1 = __half22float2(*reinterpret_cast<__half2*>(&eh1[t]));
                rs0 += f0.x + f0.y;
                rs1 += f1.x + f1.y;
            }
            rs0 += __shfl_xor_sync(~0u, rs0, 1); rs0 += __shfl_xor_sync(~0u, rs0, 2);
            rs1 += __shfl_xor_sync(~0u, rs1, 1); rs1 += __shfl_xor_sync(~0u, rs1, 2);
            l0 = l0*sc0 + rs0; l1 = l1*sc1 + rs1;

            if (!__all_sync(~0u, (sc0==1.0f) && (sc1==1.0f))){
                #pragma unroll
                for (int t=0; t<16; ++t){
                    O[t][0]*=sc0; O[t][1]*=sc0; O[t][2]*=sc1; O[t][3]*=sc1;
                }
            }

            const uint32_t VB = ST + KVARR;
            #pragma unroll
            for (int kk=0; kk<4; ++kk){
                uint32_t pha[4];
                pha[0] = eh0[2*kk];   pha[1] = eh1[2*kk];
                pha[2] = eh0[2*kk+1]; pha[3] = eh1[2*kk+1];
                #pragma unroll
                for (int vp=0; vp<8; ++vp){
                    uint32_t vf[4];
                    LDSM4T(vf, VB + (kk*16 + vb_row)*AROWB + vp*32 + vb_col);
                    MMA_F16(O[2*vp],   pha, vf);
                    MMA_F16(O[2*vp+1], pha, vf+2);
                }
            }
        }
        __syncthreads();
    }

    float il0 = 1.0f/l0, il1 = 1.0f/l1;
    const size_t row0 = (size_t)(browg + q0 + w*16 + g);
    #pragma unroll
    for (int nt=0; nt<16; ++nt){
        size_t o0 = row0*QDIM + hh*HD + nt*8 + colc;
        size_t o1 = o0 + 8*QDIM;
        *(uint32_t*)&aoh[o0] = h2u(__floats2half2_rn(O[nt][0]*il0, O[nt][1]*il0));
        *(uint32_t*)&aoh[o1] = h2u(__floats2half2_rn(O[nt][2]*il1, O[nt][3]*il1));
    }
}

// ---------------------------------------------------------------------------
extern "C" void kernel_launch(void* const* d_in, const int* in_sizes, int n_in,
                              void* d_out, int out_size)
{
    const float* X  = (const float*)d_in[0];
    const float* Wq = (const float*)d_in[1];
    const float* Wk = (const float*)d_in[2];
    const float* Wv = (const float*)d_in[3];
    const float* Wo = (const float*)d_in[4];
    float* out = (float*)d_out;

    hlf *xh,*wf,*woh,*qh,*kh,*vh,*aoh;
    cudaGetSymbolAddress((void**)&xh, g_xh);
    cudaGetSymbolAddress((void**)&wf, g_wf);
    cudaGetSymbolAddress((void**)&woh,g_woh);
    cudaGetSymbolAddress((void**)&qh, g_qh);
    cudaGetSymbolAddress((void**)&kh, g_kh);
    cudaGetSymbolAddress((void**)&vh, g_vh);
    cudaGetSymbolAddress((void**)&aoh,g_aoh);

    conv_all<<<14336, 256>>>(X, Wq, Wk, Wv, Wo, xh, wf, woh);

    // persistent QKV GEMM (2 CTAs/SM) with fused rope/convert epilogue
    cudaFuncSetAttribute(gemm_qkv, cudaFuncAttributeMaxDynamicSharedMemorySize, GSMEM2);
    gemm_qkv<<<296, 256, GSMEM2>>>(xh, wf, qh, kh, vh);

    cudaFuncSetAttribute(attn_mma, cudaFuncAttributeMaxDynamicSharedMemorySize, ASMEM);
    attn_mma<<<dim3(S_LEN/128, NH, 2), 256, ASMEM>>>(qh, kh, vh, aoh);

    // persistent O projection (2 CTAs/SM)
    cudaFuncSetAttribute(gemm_out, cudaFuncAttributeMaxDynamicSharedMemorySize, GSMEM2);
    gemm_out<<<296, 256, GSMEM2>>>(aoh, woh, out);
}

// round 14
// speedup vs baseline: 7.7083x; 1.0746x over previous
#include <cuda_runtime.h>
#include <cuda_fp16.h>
#include <math.h>
#include <stdint.h>

#define S_LEN 2048
#define HID   4096
#define NH    32
#define NKV   8
#define HD    128
#define WIN   1024
#define QDIM  4096
#define QKVN  6144
#define KVDIM 1024
#define MROWS 4096

typedef __half hlf;

__device__ hlf g_xh [(size_t)MROWS*HID];
__device__ hlf g_wf [(size_t)QKVN*HID];     // Wq|Wk|Wv
__device__ hlf g_woh[(size_t)HID*QDIM];
__device__ hlf g_qh [(size_t)MROWS*QDIM];
__device__ hlf g_kh [(size_t)MROWS*KVDIM];
__device__ hlf g_vh [(size_t)MROWS*KVDIM];
__device__ hlf g_aoh[(size_t)MROWS*QDIM];
__device__ int g_ctr[2];

// ---------------- PTX helpers ----------------
__device__ __forceinline__ uint32_t s2u(const void* p){
    uint32_t a;
    asm("{ .reg .u64 t; cvta.to.shared.u64 t,%1; cvt.u32.u64 %0,t; }":"=r"(a):"l"(p));
    return a;
}
#define CPA(dst,src) asm volatile( \
    "cp.async.cg.shared.global [%0],[%1],16;" :: "r"(dst),"l"(src) : "memory")
#define CPA_COMMIT() asm volatile("cp.async.commit_group;" ::: "memory")
#define CPA_WAIT0()  asm volatile("cp.async.wait_group 0;" ::: "memory")
#define CPA_WAIT1()  asm volatile("cp.async.wait_group 1;" ::: "memory")

#define LDSM4(r,addr) asm volatile( \
    "ldmatrix.sync.aligned.m8n8.x4.shared.b16 {%0,%1,%2,%3},[%4];" \
    : "=r"((r)[0]),"=r"((r)[1]),"=r"((r)[2]),"=r"((r)[3]) : "r"(addr))
#define LDSM4T(r,addr) asm volatile( \
    "ldmatrix.sync.aligned.m8n8.x4.trans.shared.b16 {%0,%1,%2,%3},[%4];" \
    : "=r"((r)[0]),"=r"((r)[1]),"=r"((r)[2]),"=r"((r)[3]) : "r"(addr))

#define MMA_F16(c,a,b) asm volatile( \
    "mma.sync.aligned.m16n8k16.row.col.f32.f16.f16.f32 " \
    "{%0,%1,%2,%3},{%4,%5,%6,%7},{%8,%9},{%0,%1,%2,%3};" \
    : "+f"((c)[0]),"+f"((c)[1]),"+f"((c)[2]),"+f"((c)[3]) \
    : "r"((a)[0]),"r"((a)[1]),"r"((a)[2]),"r"((a)[3]),"r"((b)[0]),"r"((b)[1]))

__device__ __forceinline__ uint32_t h2u(__half2 h){ return *reinterpret_cast<uint32_t*>(&h); }

// ---------------------------------------------------------------------------
// GEMM core: CTA tile 128x128, 256 thr (8 warps 4m x 2n), BK=64, 3-stage.
// smem/CTA = 110592 -> 2 CTAs/SM; regs capped via launch_bounds(256,2).
// ---------------------------------------------------------------------------
#define GK      4096
#define NCH64   64
#define ROWB64  144
#define ARR64   18432      // 128 rows * 144
#define STG64_B 36864
#define GSMEM64 (3*STG64_B)   // 110592

static __device__ __forceinline__ void load_stage64(
    uint32_t sb, int stage, int kc, int m0, int n0, int tid,
    const hlf* __restrict__ A, const hlf* __restrict__ Bh)
{
    uint32_t st = sb + stage*STG64_B;
    #pragma unroll
    for (int it=0; it<4; ++it){
        int idx = tid + it*256;      // 0..1023
        int r = idx>>3, ch = idx&7;
        uint32_t so = (uint32_t)(r*ROWB64 + ch*16);
        CPA(st+so,        A  + (size_t)(m0+r)*GK + kc + ch*8);
        CPA(st+ARR64+so,  Bh + (size_t)(n0+r)*GK + kc + ch*8);
    }
    CPA_COMMIT();
}

// main K-loop (BK=64, 3-stage); acc in registers
#define GEMM_MAIN64(A_, B_, m0_, n0_)                                          \
    load_stage64(sb,0,0, m0_,n0_,tid,A_,B_);                                   \
    load_stage64(sb,1,64,m0_,n0_,tid,A_,B_);                                   \
    {                                                                          \
        int stg = 0;                                                           \
        for (int c=0; c<NCH64; ++c){                                           \
            CPA_WAIT1();                                                       \
            __syncthreads();                                                   \
            if (c+2 < NCH64){                                                  \
                int ns = stg+2; if (ns>=3) ns-=3;                              \
                load_stage64(sb,ns,(c+2)*64, m0_,n0_,tid,A_,B_);               \
            } else CPA_COMMIT();                                               \
            const uint32_t st = sb + stg*STG64_B;                              \
            _Pragma("unroll")                                                  \
            for (int kk=0; kk<4; ++kk){                                        \
                uint32_t ah[2][4];                                             \
                _Pragma("unroll")                                              \
                for (int mt=0; mt<2; ++mt)                                     \
                    LDSM4(ah[mt], st + (a_row + mt*16)*ROWB64 + kk*32 + a_colb);\
                uint32_t bh[8][2];                                             \
                _Pragma("unroll")                                              \
                for (int p=0; p<4; ++p){                                       \
                    uint32_t ba = st + ARR64 + (b_row + p*16)*ROWB64 + kk*32 + b_colb;\
                    uint32_t r[4];                                             \
                    LDSM4(r, ba);                                              \
                    bh[2*p][0]=r[0]; bh[2*p][1]=r[1];                          \
                    bh[2*p+1][0]=r[2]; bh[2*p+1][1]=r[3];                      \
                }                                                              \
                _Pragma("unroll")                                              \
                for (int mt=0; mt<2; ++mt)                                     \
                    _Pragma("unroll")                                          \
                    for (int nt=0; nt<8; ++nt)                                 \
                        MMA_F16(acc[mt][nt], ah[mt], bh[nt]);                  \
            }                                                                  \
            if (++stg >= 3) stg = 0;                                           \
        }                                                                      \
    }

// ---------------------------------------------------------------------------
// Persistent QKV GEMM (work-stealing) with fused rope/convert epilogue.
// tiles: 32 m x 48 n = 1536 (each n-tile = one 128-col head), m-fast
// ---------------------------------------------------------------------------
__global__ void __launch_bounds__(256,2) gemm_qkv(
    const hlf* __restrict__ A, const hlf* __restrict__ Bh,
    hlf* __restrict__ qh, hlf* __restrict__ kh, hlf* __restrict__ vh)
{
    extern __shared__ __align__(128) char sm[];
    __shared__ int s_tile;
    const uint32_t sb = s2u(sm);
    float* fstage = reinterpret_cast<float*>(sm);
    const int tid = threadIdx.x, wid = tid>>5, lane = tid&31;
    const int wm = wid&3, wn = wid>>2;
    const int g = lane>>2, tg = lane&3;
    const float SCL2 = 0.08838834764831845f * 1.4426950408889634f;

    const uint32_t a_row  = (uint32_t)(wm*32 + (lane&15));
    const uint32_t a_colb = (uint32_t)((lane>>4)*16);
    const uint32_t b_row  = (uint32_t)(wn*64 + (lane&7) + ((lane>>4)<<3));
    const uint32_t b_colb = (uint32_t)(((lane>>3)&1)*16);

    for (;;){
        if (tid == 0) s_tile = atomicAdd(&g_ctr[0], 1);
        __syncthreads();
        const int tile = s_tile;
        if (tile >= 1536) break;
        const int m0 = (tile & 31)*128, n0 = (tile >> 5)*128;

        float acc[2][8][4];
        #pragma unroll
        for (int i=0;i<2;++i)
            #pragma unroll
            for (int j=0;j<8;++j){acc[i][j][0]=0;acc[i][j][1]=0;acc[i][j][2]=0;acc[i][j][3]=0;}

        GEMM_MAIN64(A, Bh, m0, n0)

        hlf* dst; int cbase, stride; float scale; bool isv = false;
        if (n0 < 4096)      { dst = qh; cbase = n0;        stride = QDIM;  scale = SCL2; }
        else if (n0 < 5120) { dst = kh; cbase = n0 - 4096; stride = KVDIM; scale = 1.0f; }
        else                { dst = vh; cbase = n0 - 5120; stride = KVDIM; scale = 1.0f; isv = true; }

        #pragma unroll
        for (int mh=0; mh<2; ++mh){
            __syncthreads();
            if ((wm>>1) == mh){
                int rbase = (wm&1)*32;
                #pragma unroll
                for (int mt=0; mt<2; ++mt)
                    #pragma unroll
                    for (int nt=0; nt<8; ++nt){
                        int r = rbase + mt*16 + g;
                        int cc = wn*64 + nt*8 + tg*2;
                        fstage[r*132+cc]       = acc[mt][nt][0];
                        fstage[r*132+cc+1]     = acc[mt][nt][1];
                        fstage[(r+8)*132+cc]   = acc[mt][nt][2];
                        fstage[(r+8)*132+cc+1] = acc[mt][nt][3];
                    }
            }
            __syncthreads();

            #pragma unroll
            for (int it=0; it<16; ++it){
                int idx = tid + it*256;
                int r = idx >> 6, i = idx & 63;
                float x1 = fstage[r*132 + i], x2 = fstage[r*132 + i + 64];
                float y1, y2;
                if (isv){ y1 = x1; y2 = x2; }
                else {
                    int row = m0 + mh*64 + r;
                    int s = row & (S_LEN-1);
                    float inv = powf(10000.0f, -(float)i*(1.0f/64.0f));
                    float sn, cs; sincosf((float)s*inv, &sn, &cs);
                    y1 = (x1*cs - x2*sn)*scale;
                    y2 = (x2*cs + x1*sn)*scale;
                }
                size_t o = (size_t)(m0 + mh*64 + r)*stride + cbase + i;
                dst[o]      = __float2half_rn(y1);
                dst[o + 64] = __float2half_rn(y2);
            }
        }
    }
}

// ---------------------------------------------------------------------------
// Persistent O-projection GEMM (work-stealing, fp32 out). 32 m x 32 n = 1024
// ---------------------------------------------------------------------------
__global__ void __launch_bounds__(256,2) gemm_out(
    const hlf* __restrict__ A, const hlf* __restrict__ Bh,
    float* __restrict__ C)
{
    extern __shared__ __align__(128) char sm[];
    __shared__ int s_tile;
    const uint32_t sb = s2u(sm);
    const int tid = threadIdx.x, wid = tid>>5, lane = tid&31;
    const int wm = wid&3, wn = wid>>2;
    const int g = lane>>2, tg = lane&3;

    const uint32_t a_row  = (uint32_t)(wm*32 + (lane&15));
    const uint32_t a_colb = (uint32_t)((lane>>4)*16);
    const uint32_t b_row  = (uint32_t)(wn*64 + (lane&7) + ((lane>>4)<<3));
    const uint32_t b_colb = (uint32_t)(((lane>>3)&1)*16);

    for (;;){
        if (tid == 0) s_tile = atomicAdd(&g_ctr[1], 1);
        __syncthreads();
        const int tile = s_tile;
        if (tile >= 1024) break;
        const int m0 = (tile & 31)*128, n0 = (tile >> 5)*128;

        float acc[2][8][4];
        #pragma unroll
        for (int i=0;i<2;++i)
            #pragma unroll
            for (int j=0;j<8;++j){acc[i][j][0]=0;acc[i][j][1]=0;acc[i][j][2]=0;acc[i][j][3]=0;}

        GEMM_MAIN64(A, Bh, m0, n0)

        #pragma unroll
        for (int mt=0; mt<2; ++mt)
            #pragma unroll
            for (int nt=0; nt<8; ++nt){
                int row = m0 + wm*32 + mt*16 + g;
                int col = n0 + wn*64 + nt*8 + tg*2;
                float2 v0 = {acc[mt][nt][0], acc[mt][nt][1]};
                float2 v1 = {acc[mt][nt][2], acc[mt][nt][3]};
                *(float2*)&C[(size_t)row*QDIM + col]     = v0;
                *(float2*)&C[(size_t)(row+8)*QDIM + col] = v1;
            }
    }
}

// ---------------------------------------------------------------------------
// fused fp32->fp16 conversion (one launch, 16 elems/thread); resets counters
// ---------------------------------------------------------------------------
__global__ void conv_all(const float* __restrict__ X,  const float* __restrict__ Wq,
                         const float* __restrict__ Wk, const float* __restrict__ Wv,
                         const float* __restrict__ Wo,
                         hlf* __restrict__ xh, hlf* __restrict__ wf, hlf* __restrict__ woh)
{
    if (blockIdx.x == 0 && threadIdx.x == 0){ g_ctr[0] = 0; g_ctr[1] = 0; }
    const size_t QW  = (size_t)QDIM*HID;
    const size_t KVW = (size_t)1024*HID;
    int bid = blockIdx.x;
    const float* src; hlf* dst; int rel;
    if      (bid <  4096){ src = X;  dst = xh;             rel = bid; }
    else if (bid <  8192){ src = Wq; dst = wf;             rel = bid-4096; }
    else if (bid <  9216){ src = Wk; dst = wf + QW;        rel = bid-8192; }
    else if (bid < 10240){ src = Wv; dst = wf + QW + KVW;  rel = bid-9216; }
    else                 { src = Wo; dst = woh;            rel = bid-10240; }
    size_t i = ((size_t)rel*256 + threadIdx.x)*16;
    float4 v0 = *(const float4*)(src+i);
    float4 v1 = *(const float4*)(src+i+4);
    float4 v2 = *(const float4*)(src+i+8);
    float4 v3 = *(const float4*)(src+i+12);
    uint2 o0, o1;
    o0.x = h2u(__floats2half2_rn(v0.x, v0.y)); o0.y = h2u(__floats2half2_rn(v0.z, v0.w));
    o1.x = h2u(__floats2half2_rn(v1.x, v1.y)); o1.y = h2u(__floats2half2_rn(v1.z, v1.w));
    *(uint2*)&dst[i]   = o0;
    *(uint2*)&dst[i+4] = o1;
    o0.x = h2u(__floats2half2_rn(v2.x, v2.y)); o0.y = h2u(__floats2half2_rn(v2.z, v2.w));
    o1.x = h2u(__floats2half2_rn(v3.x, v3.y)); o1.y = h2u(__floats2half2_rn(v3.z, v3.w));
    *(uint2*)&dst[i+8]  = o0;
    *(uint2*)&dst[i+12] = o1;
}

// ---------------------------------------------------------------------------
// fp16 HMMA flash attention (unchanged)
// ---------------------------------------------------------------------------
#define AROWB 272
#define QSZ   34816
#define KVARR 17408
#define KVSTG 34816
#define ASMEM (QSZ + 2*KVSTG)   // 104448

static __device__ __forceinline__ void a_load_kv(
    uint32_t st, int kbase, int brow, int tid, int kvh,
    const hlf* __restrict__ kh, const hlf* __restrict__ vh)
{
    #pragma unroll
    for (int it=0; it<4; ++it){
        int idx = tid + it*256;
        int r = idx>>4, ch = idx&15;
        uint32_t so = (uint32_t)(r*AROWB + ch*16);
        size_t gsrc = (size_t)(brow + kbase + r)*KVDIM + kvh*HD + ch*8;
        CPA(st + so,         kh + gsrc);
        CPA(st + KVARR + so, vh + gsrc);
    }
    CPA_COMMIT();
}

__global__ void __launch_bounds__(256,1) attn_mma(
    const hlf* __restrict__ qh_, const hlf* __restrict__ kh_,
    const hlf* __restrict__ vh_, hlf* __restrict__ aoh)
{
    extern __shared__ __align__(128) char sm[];
    const uint32_t sb = s2u(sm);
    const uint32_t QH = sb, ST0 = sb + QSZ;

    const int tid = threadIdx.x, w = tid>>5, lane = tid&31;
    const int qb = (int)(gridDim.x - 1 - blockIdx.x);
    const int hh = blockIdx.y, b = blockIdx.z;
    const int q0 = qb*128, kvh = hh>>2;
    const int g = lane>>2, colc = (lane&3)*2;
    const int browg = b*S_LEN;

    #pragma unroll
    for (int it=0; it<8; ++it){
        int idx = tid + it*256;
        int r = idx>>4, ch = idx&15;
        uint32_t so = (uint32_t)(r*AROWB + ch*16);
        CPA(QH + so, qh_ + (size_t)(browg + q0 + r)*QDIM + hh*HD + ch*8);
    }
    CPA_COMMIT();

    int lo = q0 - (WIN-1); if (lo < 0) lo = 0;
    const int kt0 = lo >> 6, ktend = 2*qb + 1;

    a_load_kv(ST0, kt0*64, browg, tid, kvh, kh_, vh_);

    uint32_t qfh[8][4];
    float O[16][4];
    #pragma unroll
    for (int t=0;t<16;++t){O[t][0]=0;O[t][1]=0;O[t][2]=0;O[t][3]=0;}
    float m0 = -1e30f, m1 = -1e30f, l0 = 0.f, l1 = 0.f;

    const uint32_t a_row  = (uint32_t)(w*16 + (lane&15));
    const uint32_t a_colb = (uint32_t)((lane>>4)*16);
    const uint32_t kb_row = (uint32_t)((lane&7) + ((lane>>4)<<3));
    const uint32_t kb_col = (uint32_t)(((lane>>3)&1)*16);
    const uint32_t vb_row = (uint32_t)((lane&7) + (lane&8));
    const uint32_t vb_col = (uint32_t)((lane>>4)*16);

    const int rmin_w = q0 + w*16;

    for (int kt = kt0; kt <= ktend; ++kt){
        const int s = (kt - kt0) & 1;
        const uint32_t ST = ST0 + (uint32_t)s*KVSTG;
        if (kt < ktend){
            a_load_kv(ST0 + (uint32_t)(s^1)*KVSTG, (kt+1)*64, browg, tid, kvh, kh_, vh_);
            CPA_WAIT1();
        } else {
            CPA_WAIT0();
        }
        __syncthreads();

        if (kt == kt0){
            #pragma unroll
            for (int kk=0; kk<8; ++kk)
                LDSM4(qfh[kk], QH + a_row*AROWB + kk*32 + a_colb);
        }

        const int kbase = kt*64;
        if ((kbase <= rmin_w + 15) && (kbase + 63 > rmin_w - WIN)){
            float p[8][4];
            #pragma unroll
            for (int t=0;t<8;++t){p[t][0]=0;p[t][1]=0;p[t][2]=0;p[t][3]=0;}
            #pragma unroll
            for (int kk=0; kk<8; ++kk){
                #pragma unroll
                for (int np=0; np<4; ++np){
                    uint32_t kf[4];
                    LDSM4(kf, ST + (np*16 + kb_row)*AROWB + kk*32 + kb_col);
                    MMA_F16(p[2*np],   qfh[kk], kf);
                    MMA_F16(p[2*np+1], qfh[kk], kf+2);
                }
            }

            const int r0 = rmin_w + g, r1 = r0 + 8;
            const bool full = (kbase + 63 <= rmin_w) && (kbase >= rmin_w + 16 - WIN);
            if (!full){
                #pragma unroll
                for (int t=0; t<8; ++t){
                    #pragma unroll
                    for (int e=0; e<2; ++e){
                        int kj = kbase + t*8 + colc + e;
                        if (!((kj<=r0)&&(r0-kj<WIN))) p[t][e]   = -1e30f;
                        if (!((kj<=r1)&&(r1-kj<WIN))) p[t][2+e] = -1e30f;
                    }
                }
            }
            float rm0 = -1e30f, rm1 = -1e30f;
            #pragma unroll
            for (int t=0; t<8; ++t){
                rm0 = fmaxf(rm0, fmaxf(p[t][0], p[t][1]));
                rm1 = fmaxf(rm1, fmaxf(p[t][2], p[t][3]));
            }
            rm0 = fmaxf(rm0, __shfl_xor_sync(~0u, rm0, 1));
            rm0 = fmaxf(rm0, __shfl_xor_sync(~0u, rm0, 2));
            rm1 = fmaxf(rm1, __shfl_xor_sync(~0u, rm1, 1));
            rm1 = fmaxf(rm1, __shfl_xor_sync(~0u, rm1, 2));
            float mn0 = fmaxf(m0, rm0), mn1 = fmaxf(m1, rm1);
            float sc0 = exp2f(m0 - mn0), sc1 = exp2f(m1 - mn1);
            m0 = mn0; m1 = mn1;

            uint32_t eh0[8], eh1[8];
            float rs0 = 0.f, rs1 = 0.f;
            #pragma unroll
            for (int t=0; t<8; ++t){
                uint32_t d0 = h2u(__floats2half2_rn(p[t][0]-mn0, p[t][1]-mn0));
                uint32_t d1 = h2u(__floats2half2_rn(p[t][2]-mn1, p[t][3]-mn1));
                asm("ex2.approx.f16x2 %0,%1;" : "=r"(eh0[t]) : "r"(d0));
                asm("ex2.approx.f16x2 %0,%1;" : "=r"(eh1[t]) : "r"(d1));
                float2 f0 = __half22float2(*reinterpret_cast<__half2*>(&eh0[t]));
                float2 f1 = __half22float2(*reinterpret_cast<__half2*>(&eh1[t]));
                rs0 += f0.x + f0.y;
                rs1 += f1.x + f1.y;
            }
            rs0 += __shfl_xor_sync(~0u, rs0, 1); rs0 += __shfl_xor_sync(~0u, rs0, 2);
            rs1 += __shfl_xor_sync(~0u, rs1, 1); rs1 += __shfl_xor_sync(~0u, rs1, 2);
            l0 = l0*sc0 + rs0; l1 = l1*sc1 + rs1;

            if (!__all_sync(~0u, (sc0==1.0f) && (sc1==1.0f))){
                #pragma unroll
                for (int t=0; t<16; ++t){
                    O[t][0]*=sc0; O[t][1]*=sc0; O[t][2]*=sc1; O[t][3]*=sc1;
                }
            }

            const uint32_t VB = ST + KVARR;
            #pragma unroll
            for (int kk=0; kk<4; ++kk){
                uint32_t pha[4];
                pha[0] = eh0[2*kk];   pha[1] = eh1[2*kk];
                pha[2] = eh0[2*kk+1]; pha[3] = eh1[2*kk+1];
                #pragma unroll
                for (int vp=0; vp<8; ++vp){
                    uint32_t vf[4];
                    LDSM4T(vf, VB + (kk*16 + vb_row)*AROWB + vp*32 + vb_col);
                    MMA_F16(O[2*vp],   pha, vf);
                    MMA_F16(O[2*vp+1], pha, vf+2);
                }
            }
        }
        __syncthreads();
    }

    float il0 = 1.0f/l0, il1 = 1.0f/l1;
    const size_t row0 = (size_t)(browg + q0 + w*16 + g);
    #pragma unroll
    for (int nt=0; nt<16; ++nt){
        size_t o0 = row0*QDIM + hh*HD + nt*8 + colc;
        size_t o1 = o0 + 8*QDIM;
        *(uint32_t*)&aoh[o0] = h2u(__floats2half2_rn(O[nt][0]*il0, O[nt][1]*il0));
        *(uint32_t*)&aoh[o1] = h2u(__floats2half2_rn(O[nt][2]*il1, O[nt][3]*il1));
    }
}

// ---------------------------------------------------------------------------
extern "C" void kernel_launch(void* const* d_in, const int* in_sizes, int n_in,
                              void* d_out, int out_size)
{
    const float* X  = (const float*)d_in[0];
    const float* Wq = (const float*)d_in[1];
    const float* Wk = (const float*)d_in[2];
    const float* Wv = (const float*)d_in[3];
    const float* Wo = (const float*)d_in[4];
    float* out = (float*)d_out;

    hlf *xh,*wf,*woh,*qh,*kh,*vh,*aoh;
    cudaGetSymbolAddress((void**)&xh, g_xh);
    cudaGetSymbolAddress((void**)&wf, g_wf);
    cudaGetSymbolAddress((void**)&woh,g_woh);
    cudaGetSymbolAddress((void**)&qh, g_qh);
    cudaGetSymbolAddress((void**)&kh, g_kh);
    cudaGetSymbolAddress((void**)&vh, g_vh);
    cudaGetSymbolAddress((void**)&aoh,g_aoh);

    conv_all<<<14336, 256>>>(X, Wq, Wk, Wv, Wo, xh, wf, woh);

    cudaFuncSetAttribute(gemm_qkv, cudaFuncAttributeMaxDynamicSharedMemorySize, GSMEM64);
    gemm_qkv<<<296, 256, GSMEM64>>>(xh, wf, qh, kh, vh);

    cudaFuncSetAttribute(attn_mma, cudaFuncAttributeMaxDynamicSharedMemorySize, ASMEM);
    attn_mma<<<dim3(S_LEN/128, NH, 2), 256, ASMEM>>>(qh, kh, vh, aoh);

    cudaFuncSetAttribute(gemm_out, cudaFuncAttributeMaxDynamicSharedMemorySize, GSMEM64);
    gemm_out<<<296, 256, GSMEM64>>>(aoh, woh, out);
}

// round 15
// speedup vs baseline: 7.7496x; 1.0053x over previous
#include <cuda_runtime.h>
#include <cuda_fp16.h>
#include <math.h>
#include <stdint.h>

#define S_LEN 2048
#define HID   4096
#define NH    32
#define NKV   8
#define HD    128
#define WIN   1024
#define QDIM  4096
#define QKVN  6144
#define KVDIM 1024
#define MROWS 4096

typedef __half hlf;

__device__ hlf g_xh [(size_t)MROWS*HID];
__device__ hlf g_wf [(size_t)QKVN*HID];     // Wq|Wk|Wv
__device__ hlf g_woh[(size_t)HID*QDIM];
__device__ hlf g_qh [(size_t)MROWS*QDIM];
__device__ hlf g_kh [(size_t)MROWS*KVDIM];
__device__ hlf g_vh [(size_t)MROWS*KVDIM];
__device__ hlf g_aoh[(size_t)MROWS*QDIM];
__device__ int g_ctr[2];

// ---------------- PTX helpers ----------------
__device__ __forceinline__ uint32_t s2u(const void* p){
    uint32_t a;
    asm("{ .reg .u64 t; cvta.to.shared.u64 t,%1; cvt.u32.u64 %0,t; }":"=r"(a):"l"(p));
    return a;
}
#define CPA(dst,src) asm volatile( \
    "cp.async.cg.shared.global [%0],[%1],16;" :: "r"(dst),"l"(src) : "memory")
#define CPA_COMMIT() asm volatile("cp.async.commit_group;" ::: "memory")
#define CPA_WAIT0()  asm volatile("cp.async.wait_group 0;" ::: "memory")
#define CPA_WAIT1()  asm volatile("cp.async.wait_group 1;" ::: "memory")

#define LDSM4(r,addr) asm volatile( \
    "ldmatrix.sync.aligned.m8n8.x4.shared.b16 {%0,%1,%2,%3},[%4];" \
    : "=r"((r)[0]),"=r"((r)[1]),"=r"((r)[2]),"=r"((r)[3]) : "r"(addr))
#define LDSM4T(r,addr) asm volatile( \
    "ldmatrix.sync.aligned.m8n8.x4.trans.shared.b16 {%0,%1,%2,%3},[%4];" \
    : "=r"((r)[0]),"=r"((r)[1]),"=r"((r)[2]),"=r"((r)[3]) : "r"(addr))

#define MMA_F16(c,a,b) asm volatile( \
    "mma.sync.aligned.m16n8k16.row.col.f32.f16.f16.f32 " \
    "{%0,%1,%2,%3},{%4,%5,%6,%7},{%8,%9},{%0,%1,%2,%3};" \
    : "+f"((c)[0]),"+f"((c)[1]),"+f"((c)[2]),"+f"((c)[3]) \
    : "r"((a)[0]),"r"((a)[1]),"r"((a)[2]),"r"((a)[3]),"r"((b)[0]),"r"((b)[1]))

__device__ __forceinline__ uint32_t h2u(__half2 h){ return *reinterpret_cast<uint32_t*>(&h); }

// ---------------------------------------------------------------------------
// GEMM core: CTA tile 128x128, 256 thr (8 warps 4m x 2n), BK=64, 3-stage.
// ---------------------------------------------------------------------------
#define GK      4096
#define NCH64   64
#define ROWB64  144
#define ARR64   18432
#define STG64_B 36864
#define GSMEM64 (3*STG64_B)   // 110592

static __device__ __forceinline__ void load_stage64(
    uint32_t sb, int stage, int kc, int m0, int n0, int tid,
    const hlf* __restrict__ A, const hlf* __restrict__ Bh)
{
    uint32_t st = sb + stage*STG64_B;
    #pragma unroll
    for (int it=0; it<4; ++it){
        int idx = tid + it*256;
        int r = idx>>3, ch = idx&7;
        uint32_t so = (uint32_t)(r*ROWB64 + ch*16);
        CPA(st+so,        A  + (size_t)(m0+r)*GK + kc + ch*8);
        CPA(st+ARR64+so,  Bh + (size_t)(n0+r)*GK + kc + ch*8);
    }
    CPA_COMMIT();
}

#define GEMM_MAIN64(A_, B_, m0_, n0_)                                          \
    load_stage64(sb,0,0, m0_,n0_,tid,A_,B_);                                   \
    load_stage64(sb,1,64,m0_,n0_,tid,A_,B_);                                   \
    {                                                                          \
        int stg = 0;                                                           \
        for (int c=0; c<NCH64; ++c){                                           \
            CPA_WAIT1();                                                       \
            __syncthreads();                                                   \
            if (c+2 < NCH64){                                                  \
                int ns = stg+2; if (ns>=3) ns-=3;                              \
                load_stage64(sb,ns,(c+2)*64, m0_,n0_,tid,A_,B_);               \
            } else CPA_COMMIT();                                               \
            const uint32_t st = sb + stg*STG64_B;                              \
            _Pragma("unroll")                                                  \
            for (int kk=0; kk<4; ++kk){                                        \
                uint32_t ah[2][4];                                             \
                _Pragma("unroll")                                              \
                for (int mt=0; mt<2; ++mt)                                     \
                    LDSM4(ah[mt], st + (a_row + mt*16)*ROWB64 + kk*32 + a_colb);\
                uint32_t bh[8][2];                                             \
                _Pragma("unroll")                                              \
                for (int p=0; p<4; ++p){                                       \
                    uint32_t ba = st + ARR64 + (b_row + p*16)*ROWB64 + kk*32 + b_colb;\
                    uint32_t r[4];                                             \
                    LDSM4(r, ba);                                              \
                    bh[2*p][0]=r[0]; bh[2*p][1]=r[1];                          \
                    bh[2*p+1][0]=r[2]; bh[2*p+1][1]=r[3];                      \
                }                                                              \
                _Pragma("unroll")                                              \
                for (int mt=0; mt<2; ++mt)                                     \
                    _Pragma("unroll")                                          \
                    for (int nt=0; nt<8; ++nt)                                 \
                        MMA_F16(acc[mt][nt], ah[mt], bh[nt]);                  \
            }                                                                  \
            if (++stg >= 3) stg = 0;                                           \
        }                                                                      \
    }

// ---------------------------------------------------------------------------
// Persistent QKV GEMM (work-stealing) with fused rope/convert epilogue.
// ---------------------------------------------------------------------------
__global__ void __launch_bounds__(256,2) gemm_qkv(
    const hlf* __restrict__ A, const hlf* __restrict__ Bh,
    hlf* __restrict__ qh, hlf* __restrict__ kh, hlf* __restrict__ vh)
{
    extern __shared__ __align__(128) char sm[];
    __shared__ int s_tile;
    const uint32_t sb = s2u(sm);
    float* fstage = reinterpret_cast<float*>(sm);
    const int tid = threadIdx.x, wid = tid>>5, lane = tid&31;
    const int wm = wid&3, wn = wid>>2;
    const int g = lane>>2, tg = lane&3;
    const float SCL2 = 0.08838834764831845f * 1.4426950408889634f;

    const uint32_t a_row  = (uint32_t)(wm*32 + (lane&15));
    const uint32_t a_colb = (uint32_t)((lane>>4)*16);
    const uint32_t b_row  = (uint32_t)(wn*64 + (lane&7) + ((lane>>4)<<3));
    const uint32_t b_colb = (uint32_t)(((lane>>3)&1)*16);

    for (;;){
        if (tid == 0) s_tile = atomicAdd(&g_ctr[0], 1);
        __syncthreads();
        const int tile = s_tile;
        if (tile >= 1536) break;
        const int m0 = (tile & 31)*128, n0 = (tile >> 5)*128;

        float acc[2][8][4];
        #pragma unroll
        for (int i=0;i<2;++i)
            #pragma unroll
            for (int j=0;j<8;++j){acc[i][j][0]=0;acc[i][j][1]=0;acc[i][j][2]=0;acc[i][j][3]=0;}

        GEMM_MAIN64(A, Bh, m0, n0)

        hlf* dst; int cbase, stride; float scale; bool isv = false;
        if (n0 < 4096)      { dst = qh; cbase = n0;        stride = QDIM;  scale = SCL2; }
        else if (n0 < 5120) { dst = kh; cbase = n0 - 4096; stride = KVDIM; scale = 1.0f; }
        else                { dst = vh; cbase = n0 - 5120; stride = KVDIM; scale = 1.0f; isv = true; }

        #pragma unroll
        for (int mh=0; mh<2; ++mh){
            __syncthreads();
            if ((wm>>1) == mh){
                int rbase = (wm&1)*32;
                #pragma unroll
                for (int mt=0; mt<2; ++mt)
                    #pragma unroll
                    for (int nt=0; nt<8; ++nt){
                        int r = rbase + mt*16 + g;
                        int cc = wn*64 + nt*8 + tg*2;
                        fstage[r*132+cc]       = acc[mt][nt][0];
                        fstage[r*132+cc+1]     = acc[mt][nt][1];
                        fstage[(r+8)*132+cc]   = acc[mt][nt][2];
                        fstage[(r+8)*132+cc+1] = acc[mt][nt][3];
                    }
            }
            __syncthreads();

            #pragma unroll
            for (int it=0; it<16; ++it){
                int idx = tid + it*256;
                int r = idx >> 6, i = idx & 63;
                float x1 = fstage[r*132 + i], x2 = fstage[r*132 + i + 64];
                float y1, y2;
                if (isv){ y1 = x1; y2 = x2; }
                else {
                    int row = m0 + mh*64 + r;
                    int s = row & (S_LEN-1);
                    float inv = powf(10000.0f, -(float)i*(1.0f/64.0f));
                    float sn, cs; sincosf((float)s*inv, &sn, &cs);
                    y1 = (x1*cs - x2*sn)*scale;
                    y2 = (x2*cs + x1*sn)*scale;
                }
                size_t o = (size_t)(m0 + mh*64 + r)*stride + cbase + i;
                dst[o]      = __float2half_rn(y1);
                dst[o + 64] = __float2half_rn(y2);
            }
        }
    }
}

// ---------------------------------------------------------------------------
// Persistent O-projection GEMM (work-stealing, fp32 out).
// ---------------------------------------------------------------------------
__global__ void __launch_bounds__(256,2) gemm_out(
    const hlf* __restrict__ A, const hlf* __restrict__ Bh,
    float* __restrict__ C)
{
    extern __shared__ __align__(128) char sm[];
    __shared__ int s_tile;
    const uint32_t sb = s2u(sm);
    const int tid = threadIdx.x, wid = tid>>5, lane = tid&31;
    const int wm = wid&3, wn = wid>>2;
    const int g = lane>>2, tg = lane&3;

    const uint32_t a_row  = (uint32_t)(wm*32 + (lane&15));
    const uint32_t a_colb = (uint32_t)((lane>>4)*16);
    const uint32_t b_row  = (uint32_t)(wn*64 + (lane&7) + ((lane>>4)<<3));
    const uint32_t b_colb = (uint32_t)(((lane>>3)&1)*16);

    for (;;){
        if (tid == 0) s_tile = atomicAdd(&g_ctr[1], 1);
        __syncthreads();
        const int tile = s_tile;
        if (tile >= 1024) break;
        const int m0 = (tile & 31)*128, n0 = (tile >> 5)*128;

        float acc[2][8][4];
        #pragma unroll
        for (int i=0;i<2;++i)
            #pragma unroll
            for (int j=0;j<8;++j){acc[i][j][0]=0;acc[i][j][1]=0;acc[i][j][2]=0;acc[i][j][3]=0;}

        GEMM_MAIN64(A, Bh, m0, n0)

        #pragma unroll
        for (int mt=0; mt<2; ++mt)
            #pragma unroll
            for (int nt=0; nt<8; ++nt){
                int row = m0 + wm*32 + mt*16 + g;
                int col = n0 + wn*64 + nt*8 + tg*2;
                float2 v0 = {acc[mt][nt][0], acc[mt][nt][1]};
                float2 v1 = {acc[mt][nt][2], acc[mt][nt][3]};
                *(float2*)&C[(size_t)row*QDIM + col]     = v0;
                *(float2*)&C[(size_t)(row+8)*QDIM + col] = v1;
            }
    }
}

// ---------------------------------------------------------------------------
// fused fp32->fp16 conversion (one launch); resets tile counters
// ---------------------------------------------------------------------------
__global__ void conv_all(const float* __restrict__ X,  const float* __restrict__ Wq,
                         const float* __restrict__ Wk, const float* __restrict__ Wv,
                         const float* __restrict__ Wo,
                         hlf* __restrict__ xh, hlf* __restrict__ wf, hlf* __restrict__ woh)
{
    if (blockIdx.x == 0 && threadIdx.x == 0){ g_ctr[0] = 0; g_ctr[1] = 0; }
    const size_t QW  = (size_t)QDIM*HID;
    const size_t KVW = (size_t)1024*HID;
    int bid = blockIdx.x;
    const float* src; hlf* dst; int rel;
    if      (bid <  4096){ src = X;  dst = xh;             rel = bid; }
    else if (bid <  8192){ src = Wq; dst = wf;             rel = bid-4096; }
    else if (bid <  9216){ src = Wk; dst = wf + QW;        rel = bid-8192; }
    else if (bid < 10240){ src = Wv; dst = wf + QW + KVW;  rel = bid-9216; }
    else                 { src = Wo; dst = woh;            rel = bid-10240; }
    size_t i = ((size_t)rel*256 + threadIdx.x)*16;
    float4 v0 = *(const float4*)(src+i);
    float4 v1 = *(const float4*)(src+i+4);
    float4 v2 = *(const float4*)(src+i+8);
    float4 v3 = *(const float4*)(src+i+12);
    uint2 o0, o1;
    o0.x = h2u(__floats2half2_rn(v0.x, v0.y)); o0.y = h2u(__floats2half2_rn(v0.z, v0.w));
    o1.x = h2u(__floats2half2_rn(v1.x, v1.y)); o1.y = h2u(__floats2half2_rn(v1.z, v1.w));
    *(uint2*)&dst[i]   = o0;
    *(uint2*)&dst[i+4] = o1;
    o0.x = h2u(__floats2half2_rn(v2.x, v2.y)); o0.y = h2u(__floats2half2_rn(v2.z, v2.w));
    o1.x = h2u(__floats2half2_rn(v3.x, v3.y)); o1.y = h2u(__floats2half2_rn(v3.z, v3.w));
    *(uint2*)&dst[i+8]  = o0;
    *(uint2*)&dst[i+12] = o1;
}

// ---------------------------------------------------------------------------
// fp16 HMMA flash attention — register diet for 2 CTAs/SM:
// Q fragments reloaded from smem per k-tile in two 4-step passes.
// ---------------------------------------------------------------------------
#define AROWB 272
#define QSZ   34816
#define KVARR 17408
#define KVSTG 34816
#define ASMEM (QSZ + 2*KVSTG)   // 104448

static __device__ __forceinline__ void a_load_kv(
    uint32_t st, int kbase, int brow, int tid, int kvh,
    const hlf* __restrict__ kh, const hlf* __restrict__ vh)
{
    #pragma unroll
    for (int it=0; it<4; ++it){
        int idx = tid + it*256;
        int r = idx>>4, ch = idx&15;
        uint32_t so = (uint32_t)(r*AROWB + ch*16);
        size_t gsrc = (size_t)(brow + kbase + r)*KVDIM + kvh*HD + ch*8;
        CPA(st + so,         kh + gsrc);
        CPA(st + KVARR + so, vh + gsrc);
    }
    CPA_COMMIT();
}

__global__ void __launch_bounds__(256,2) attn_mma(
    const hlf* __restrict__ qh_, const hlf* __restrict__ kh_,
    const hlf* __restrict__ vh_, hlf* __restrict__ aoh)
{
    extern __shared__ __align__(128) char sm[];
    const uint32_t sb = s2u(sm);
    const uint32_t QH = sb, ST0 = sb + QSZ;

    const int tid = threadIdx.x, w = tid>>5, lane = tid&31;
    const int qb = (int)(gridDim.x - 1 - blockIdx.x);
    const int hh = blockIdx.y, b = blockIdx.z;
    const int q0 = qb*128, kvh = hh>>2;
    const int g = lane>>2, colc = (lane&3)*2;
    const int browg = b*S_LEN;

    #pragma unroll
    for (int it=0; it<8; ++it){
        int idx = tid + it*256;
        int r = idx>>4, ch = idx&15;
        uint32_t so = (uint32_t)(r*AROWB + ch*16);
        CPA(QH + so, qh_ + (size_t)(browg + q0 + r)*QDIM + hh*HD + ch*8);
    }
    CPA_COMMIT();

    int lo = q0 - (WIN-1); if (lo < 0) lo = 0;
    const int kt0 = lo >> 6, ktend = 2*qb + 1;

    a_load_kv(ST0, kt0*64, browg, tid, kvh, kh_, vh_);

    float O[16][4];
    #pragma unroll
    for (int t=0;t<16;++t){O[t][0]=0;O[t][1]=0;O[t][2]=0;O[t][3]=0;}
    float m0 = -1e30f, m1 = -1e30f, l0 = 0.f, l1 = 0.f;

    const uint32_t a_row  = (uint32_t)(w*16 + (lane&15));
    const uint32_t a_colb = (uint32_t)((lane>>4)*16);
    const uint32_t kb_row = (uint32_t)((lane&7) + ((lane>>4)<<3));
    const uint32_t kb_col = (uint32_t)(((lane>>3)&1)*16);
    const uint32_t vb_row = (uint32_t)((lane&7) + (lane&8));
    const uint32_t vb_col = (uint32_t)((lane>>4)*16);

    const int rmin_w = q0 + w*16;

    for (int kt = kt0; kt <= ktend; ++kt){
        const int s = (kt - kt0) & 1;
        const uint32_t ST = ST0 + (uint32_t)s*KVSTG;
        if (kt < ktend){
            a_load_kv(ST0 + (uint32_t)(s^1)*KVSTG, (kt+1)*64, browg, tid, kvh, kh_, vh_);
            CPA_WAIT1();
        } else {
            CPA_WAIT0();
        }
        __syncthreads();

        const int kbase = kt*64;
        if ((kbase <= rmin_w + 15) && (kbase + 63 > rmin_w - WIN)){
            // ---- S = Q K^T, two 4-step passes (Q frags reloaded from smem) ----
            float p[8][4];
            #pragma unroll
            for (int t=0;t<8;++t){p[t][0]=0;p[t][1]=0;p[t][2]=0;p[t][3]=0;}
            #pragma unroll
            for (int half=0; half<2; ++half){
                uint32_t qf[4][4];
                #pragma unroll
                for (int kk=0; kk<4; ++kk)
                    LDSM4(qf[kk], QH + a_row*AROWB + (half*4+kk)*32 + a_colb);
                #pragma unroll
                for (int kk=0; kk<4; ++kk){
                    #pragma unroll
                    for (int np=0; np<4; ++np){
                        uint32_t kf[4];
                        LDSM4(kf, ST + (np*16 + kb_row)*AROWB + (half*4+kk)*32 + kb_col);
                        MMA_F16(p[2*np],   qf[kk], kf);
                        MMA_F16(p[2*np+1], qf[kk], kf+2);
                    }
                }
            }

            const int r0 = rmin_w + g, r1 = r0 + 8;
            const bool full = (kbase + 63 <= rmin_w) && (kbase >= rmin_w + 16 - WIN);
            if (!full){
                #pragma unroll
                for (int t=0; t<8; ++t){
                    #pragma unroll
                    for (int e=0; e<2; ++e){
                        int kj = kbase + t*8 + colc + e;
                        if (!((kj<=r0)&&(r0-kj<WIN))) p[t][e]   = -1e30f;
                        if (!((kj<=r1)&&(r1-kj<WIN))) p[t][2+e] = -1e30f;
                    }
                }
            }
            float rm0 = -1e30f, rm1 = -1e30f;
            #pragma unroll
            for (int t=0; t<8; ++t){
                rm0 = fmaxf(rm0, fmaxf(p[t][0], p[t][1]));
                rm1 = fmaxf(rm1, fmaxf(p[t][2], p[t][3]));
            }
            rm0 = fmaxf(rm0, __shfl_xor_sync(~0u, rm0, 1));
            rm0 = fmaxf(rm0, __shfl_xor_sync(~0u, rm0, 2));
            rm1 = fmaxf(rm1, __shfl_xor_sync(~0u, rm1, 1));
            rm1 = fmaxf(rm1, __shfl_xor_sync(~0u, rm1, 2));
            float mn0 = fmaxf(m0, rm0), mn1 = fmaxf(m1, rm1);
            float sc0 = exp2f(m0 - mn0), sc1 = exp2f(m1 - mn1);
            m0 = mn0; m1 = mn1;

            uint32_t eh0[8], eh1[8];
            float rs0 = 0.f, rs1 = 0.f;
            #pragma unroll
            for (int t=0; t<8; ++t){
                uint32_t d0 = h2u(__floats2half2_rn(p[t][0]-mn0, p[t][1]-mn0));
                uint32_t d1 = h2u(__floats2half2_rn(p[t][2]-mn1, p[t][3]-mn1));
                asm("ex2.approx.f16x2 %0,%1;" : "=r"(eh0[t]) : "r"(d0));
                asm("ex2.approx.f16x2 %0,%1;" : "=r"(eh1[t]) : "r"(d1));
                float2 f0 = __half22float2(*reinterpret_cast<__half2*>(&eh0[t]));
                float2 f1 = __half22float2(*reinterpret_cast<__half2*>(&eh1[t]));
                rs0 += f0.x + f0.y;
                rs1 += f1.x + f1.y;
            }
            rs0 += __shfl_xor_sync(~0u, rs0, 1); rs0 += __shfl_xor_sync(~0u, rs0, 2);
            rs1 += __shfl_xor_sync(~0u, rs1, 1); rs1 += __shfl_xor_sync(~0u, rs1, 2);
            l0 = l0*sc0 + rs0; l1 = l1*sc1 + rs1;

            if (!__all_sync(~0u, (sc0==1.0f) && (sc1==1.0f))){
                #pragma unroll
                for (int t=0; t<16; ++t){
                    O[t][0]*=sc0; O[t][1]*=sc0; O[t][2]*=sc1; O[t][3]*=sc1;
                }
            }

            const uint32_t VB = ST + KVARR;
            #pragma unroll
            for (int kk=0; kk<4; ++kk){
                uint32_t pha[4];
                pha[0] = eh0[2*kk];   pha[1] = eh1[2*kk];
                pha[2] = eh0[2*kk+1]; pha[3] = eh1[2*kk+1];
                #pragma unroll
                for (int vp=0; vp<8; ++vp){
                    uint32_t vf[4];
                    LDSM4T(vf, VB + (kk*16 + vb_row)*AROWB + vp*32 + vb_col);
                    MMA_F16(O[2*vp],   pha, vf);
                    MMA_F16(O[2*vp+1], pha, vf+2);
                }
            }
        }
        __syncthreads();
    }

    float il0 = 1.0f/l0, il1 = 1.0f/l1;
    const size_t row0 = (size_t)(browg + q0 + w*16 + g);
    #pragma unroll
    for (int nt=0; nt<16; ++nt){
        size_t o0 = row0*QDIM + hh*HD + nt*8 + colc;
        size_t o1 = o0 + 8*QDIM;
        *(uint32_t*)&aoh[o0] = h2u(__floats2half2_rn(O[nt][0]*il0, O[nt][1]*il0));
        *(uint32_t*)&aoh[o1] = h2u(__floats2half2_rn(O[nt][2]*il1, O[nt][3]*il1));
    }
}

// ---------------------------------------------------------------------------
extern "C" void kernel_launch(void* const* d_in, const int* in_sizes, int n_in,
                              void* d_out, int out_size)
{
    const float* X  = (const float*)d_in[0];
    const float* Wq = (const float*)d_in[1];
    const float* Wk = (const float*)d_in[2];
    const float* Wv = (const float*)d_in[3];
    const float* Wo = (const float*)d_in[4];
    float* out = (float*)d_out;

    hlf *xh,*wf,*woh,*qh,*kh,*vh,*aoh;
    cudaGetSymbolAddress((void**)&xh, g_xh);
    cudaGetSymbolAddress((void**)&wf, g_wf);
    cudaGetSymbolAddress((void**)&woh,g_woh);
    cudaGetSymbolAddress((void**)&qh, g_qh);
    cudaGetSymbolAddress((void**)&kh, g_kh);
    cudaGetSymbolAddress((void**)&vh, g_vh);
    cudaGetSymbolAddress((void**)&aoh,g_aoh);

    conv_all<<<14336, 256>>>(X, Wq, Wk, Wv, Wo, xh, wf, woh);

    cudaFuncSetAttribute(gemm_qkv, cudaFuncAttributeMaxDynamicSharedMemorySize, GSMEM64);
    gemm_qkv<<<296, 256, GSMEM64>>>(xh, wf, qh, kh, vh);

    cudaFuncSetAttribute(attn_mma, cudaFuncAttributeMaxDynamicSharedMemorySize, ASMEM);
    attn_mma<<<dim3(S_LEN/128, NH, 2), 256, ASMEM>>>(qh, kh, vh, aoh);

    cudaFuncSetAttribute(gemm_out, cudaFuncAttributeMaxDynamicSharedMemorySize, GSMEM64);
    gemm_out<<<296, 256, GSMEM64>>>(aoh, woh, out);
}